// round 5
// baseline (speedup 1.0000x reference)
#include <cuda_runtime.h>
#include <cuda_bf16.h>
#include <cstdint>
#include <math.h>

#define HID 4096
#define KVD 1024
#define TOK 4096   /* B*S */
#define SEQ 2048

// ---------------- device scratch ----------------
__device__ __nv_bfloat16 g_xh[TOK * HID];
__device__ __nv_bfloat16 g_xl[TOK * HID];
__device__ __nv_bfloat16 g_Wqh[HID * HID];
__device__ __nv_bfloat16 g_Wql[HID * HID];
__device__ __nv_bfloat16 g_Wkh[KVD * HID];
__device__ __nv_bfloat16 g_Wkl[KVD * HID];
__device__ __nv_bfloat16 g_Wvh[KVD * HID];
__device__ __nv_bfloat16 g_Wvl[KVD * HID];
__device__ __nv_bfloat16 g_Woh[HID * HID];
__device__ __nv_bfloat16 g_Wol[HID * HID];
__device__ __nv_bfloat16 g_qh[TOK * HID];
__device__ __nv_bfloat16 g_ql[TOK * HID];
__device__ __nv_bfloat16 g_kh[TOK * KVD];
__device__ __nv_bfloat16 g_kl[TOK * KVD];
__device__ __nv_bfloat16 g_vh[TOK * KVD];
__device__ __nv_bfloat16 g_vl[TOK * KVD];
__device__ __nv_bfloat16 g_ath[TOK * HID];
__device__ __nv_bfloat16 g_atl[TOK * HID];

// ---------------- helpers ----------------
__device__ __forceinline__ uint32_t smem_u32(const void* p) {
    uint32_t a;
    asm("{ .reg .u64 t; cvta.to.shared.u64 t, %1; cvt.u32.u64 %0, t; }" : "=r"(a) : "l"(p));
    return a;
}
__device__ __forceinline__ void cp16(uint32_t dst, const void* src) {
    asm volatile("cp.async.cg.shared.global [%0], [%1], 16;\n" :: "r"(dst), "l"(src) : "memory");
}
#define CP_COMMIT() asm volatile("cp.async.commit_group;\n" ::: "memory")

#define LDSM4(r, a) \
    asm volatile("ldmatrix.sync.aligned.m8n8.x4.shared.b16 {%0,%1,%2,%3}, [%4];" \
                 : "=r"((r)[0]), "=r"((r)[1]), "=r"((r)[2]), "=r"((r)[3]) : "r"(a))
#define LDSM4T(r, a) \
    asm volatile("ldmatrix.sync.aligned.m8n8.x4.trans.shared.b16 {%0,%1,%2,%3}, [%4];" \
                 : "=r"((r)[0]), "=r"((r)[1]), "=r"((r)[2]), "=r"((r)[3]) : "r"(a))

#define MMA16816(d, a, b0, b1) \
    asm volatile("mma.sync.aligned.m16n8k16.row.col.f32.bf16.bf16.f32 " \
                 "{%0,%1,%2,%3}, {%4,%5,%6,%7}, {%8,%9}, {%0,%1,%2,%3};" \
                 : "+f"((d)[0]), "+f"((d)[1]), "+f"((d)[2]), "+f"((d)[3]) \
                 : "r"((a)[0]), "r"((a)[1]), "r"((a)[2]), "r"((a)[3]), "r"(b0), "r"(b1))

__device__ __forceinline__ uint32_t pack_bf16x2(float hi_, float lo_) {
    uint32_t r;
    asm("cvt.rn.bf16x2.f32 %0, %1, %2;" : "=r"(r) : "f"(hi_), "f"(lo_));
    return r;
}
__device__ __forceinline__ float2 unpack_bf16x2(uint32_t u) {
    float2 r;
    r.x = __uint_as_float(u << 16);
    r.y = __uint_as_float(u & 0xffff0000u);
    return r;
}
// fast exp2 on FMA pipe (no MUFU). x <= 0 expected; rel err ~2.4e-6.
__device__ __forceinline__ float exp2p(float x) {
    x = fmaxf(x, -120.f);
    int e = __float2int_rn(x);
    float f = x - (float)e;
    float p = 1.3333558e-3f;
    p = fmaf(p, f, 9.6181291e-3f);
    p = fmaf(p, f, 5.5504109e-2f);
    p = fmaf(p, f, 2.4022651e-1f);
    p = fmaf(p, f, 6.9314718e-1f);
    p = fmaf(p, f, 1.0f);
    return p * __int_as_float((uint32_t)(e + 127) << 23);
}

// ---------------- DoRA weight materialization -> bf16 hi/lo ----------------
// 8 rows per block; rank-8 A staged in 128KB smem (A L2 traffic /8).
#define DORA_SMEM (8 * HID * 4)

__global__ __launch_bounds__(256) void dora_weights(
    const float* __restrict__ W, const float* __restrict__ A,
    const float* __restrict__ Bm, const float* __restrict__ mvec,
    __nv_bfloat16* __restrict__ Whi, __nv_bfloat16* __restrict__ Wlo)
{
    extern __shared__ float sA[];   // [8][HID]
    const int tid = threadIdx.x;
    for (int i = tid; i < 8 * HID / 4; i += 256)
        ((float4*)sA)[i] = ((const float4*)A)[i];
    __syncthreads();

    __shared__ float red[8];
    __shared__ float s_scale;

    const int rowbase = blockIdx.x * 8;
#pragma unroll 1
    for (int rr = 0; rr < 8; rr++) {
        const int row = rowbase + rr;
        float b[8];
#pragma unroll
        for (int r = 0; r < 8; r++) b[r] = 2.0f * Bm[row * 8 + r];

        const float4* Wrow = (const float4*)(W + (size_t)row * HID);
        float4 w[4];
        float ss = 0.f;
#pragma unroll
        for (int c = 0; c < 4; c++) {
            int col4 = tid + 256 * c;
            float4 wv = Wrow[col4];
#pragma unroll
            for (int r = 0; r < 8; r++) {
                float4 av = ((const float4*)(sA + r * HID))[col4];
                wv.x += b[r] * av.x; wv.y += b[r] * av.y;
                wv.z += b[r] * av.z; wv.w += b[r] * av.w;
            }
            ss += wv.x * wv.x + wv.y * wv.y + wv.z * wv.z + wv.w * wv.w;
            w[c] = wv;
        }
#pragma unroll
        for (int off = 16; off; off >>= 1)
            ss += __shfl_xor_sync(0xffffffffu, ss, off);
        if ((tid & 31) == 0) red[tid >> 5] = ss;
        __syncthreads();
        if (tid == 0) {
            float t = 0.f;
#pragma unroll
            for (int i = 0; i < 8; i++) t += red[i];
            s_scale = mvec[row] / (sqrtf(t) + 1e-8f);
        }
        __syncthreads();
        const float sc = s_scale;
#pragma unroll
        for (int c = 0; c < 4; c++) {
            float vv[4] = {w[c].x * sc, w[c].y * sc, w[c].z * sc, w[c].w * sc};
            size_t base = (size_t)row * HID + (tid + 256 * c) * 4;
#pragma unroll
            for (int e = 0; e < 4; e++) {
                __nv_bfloat16 h = __float2bfloat16(vv[e]);
                Whi[base + e] = h;
                Wlo[base + e] = __float2bfloat16(vv[e] - __bfloat162float(h));
            }
        }
        __syncthreads();
    }
}

// ---------------- fp32 -> bf16 hi/lo split (x only) ----------------
__global__ __launch_bounds__(256) void split_bf16(
    const float* __restrict__ in, __nv_bfloat16* __restrict__ hi,
    __nv_bfloat16* __restrict__ lo, int n4)
{
    int i = blockIdx.x * 256 + threadIdx.x;
    if (i >= n4) return;
    float4 v = ((const float4*)in)[i];
    float vv[4] = {v.x, v.y, v.z, v.w};
    size_t base = (size_t)i * 4;
#pragma unroll
    for (int e = 0; e < 4; e++) {
        __nv_bfloat16 h = __float2bfloat16(vv[e]);
        hi[base + e] = h;
        lo[base + e] = __float2bfloat16(vv[e] - __bfloat162float(h));
    }
}

// ---------------- HMMA GEMM: C[M,N] = A[M,K]*B[N,K]^T, bf16 3-term split ----
// 128x128 CTA tile, 256 threads (4x2 warps, warp tile 32x64), K chunk 32.
// 4-stage cp.async pipeline, one barrier per chunk.
#define STRIDE_B 80
#define TILE_B   (128 * STRIDE_B)
#define STAGE_B  (4 * TILE_B)
#define GEMM_SMEM (4 * STAGE_B)          /* 163840 */

__global__ __launch_bounds__(256, 1) void gemm_hmma(
    const __nv_bfloat16* __restrict__ Ah, const __nv_bfloat16* __restrict__ Al,
    const __nv_bfloat16* __restrict__ Bh, const __nv_bfloat16* __restrict__ Bl,
    float* __restrict__ C, __nv_bfloat16* __restrict__ Chi,
    __nv_bfloat16* __restrict__ Clo, int N, int mode)
{
    extern __shared__ char dsm[];
    const uint32_t sb = smem_u32(dsm);
    const int tid = threadIdx.x, lane = tid & 31, wid = tid >> 5;
    const int wm = wid & 3, wn = wid >> 2;
    const int row0 = blockIdx.y << 7, col0 = blockIdx.x << 7;
    const int K = 4096;

    const __nv_bfloat16* g0 = Ah + (size_t)row0 * K;
    const __nv_bfloat16* g1 = Al + (size_t)row0 * K;
    const __nv_bfloat16* g2 = Bh + (size_t)col0 * K;
    const __nv_bfloat16* g3 = Bl + (size_t)col0 * K;

    const int ldr = tid >> 2;
    const int ldc = (tid & 3) * 16;

    const uint32_t a_off = (uint32_t)(wm * 32 + (lane & 15)) * STRIDE_B + ((lane >> 4) * 16);
    const uint32_t b_off = (uint32_t)(wn * 64 + (((lane >> 4) << 3) + (lane & 7))) * STRIDE_B
                           + (((lane >> 3) & 1) * 16);

    float acc[2][8][4] = {};

#define LOAD_STAGE(buf, k0) do { \
    uint32_t s0_ = sb + (buf) * STAGE_B; \
    const __nv_bfloat16* gg_[4] = {g0 + (k0), g1 + (k0), g2 + (k0), g3 + (k0)}; \
    _Pragma("unroll") \
    for (int t_ = 0; t_ < 4; t_++) { \
        uint32_t st_ = s0_ + t_ * TILE_B; \
        _Pragma("unroll") \
        for (int p_ = 0; p_ < 2; p_++) { \
            int r_ = ldr + p_ * 64; \
            cp16(st_ + (uint32_t)r_ * STRIDE_B + ldc, \
                 (const char*)(gg_[t_] + (size_t)r_ * K) + ldc); \
        } \
    } \
    CP_COMMIT(); \
} while (0)

    LOAD_STAGE(0, 0);
    LOAD_STAGE(1, 32);
    LOAD_STAGE(2, 64);

    for (int ch = 0; ch < 128; ch++) {
        if (ch + 3 < 128) {
            asm volatile("cp.async.wait_group 2;\n" ::: "memory");
        } else {
            asm volatile("cp.async.wait_group 0;\n" ::: "memory");
        }
        __syncthreads();
        if (ch + 3 < 128) LOAD_STAGE((ch + 3) & 3, (ch + 3) * 32);

        const uint32_t s0 = sb + (ch & 3) * STAGE_B;
        const uint32_t sAh = s0, sAl = s0 + TILE_B;
        const uint32_t sBh = s0 + 2 * TILE_B, sBl = s0 + 3 * TILE_B;
#pragma unroll
        for (int k16 = 0; k16 < 2; k16++) {
            const uint32_t kadd = k16 * 32;
            uint32_t ah[2][4], al[2][4], bb[4][4];
            LDSM4(ah[0], sAh + a_off + kadd);
            LDSM4(ah[1], sAh + a_off + 16 * STRIDE_B + kadd);
            LDSM4(al[0], sAl + a_off + kadd);
            LDSM4(al[1], sAl + a_off + 16 * STRIDE_B + kadd);
#pragma unroll
            for (int j = 0; j < 4; j++) LDSM4(bb[j], sBh + b_off + j * 16 * STRIDE_B + kadd);
#pragma unroll
            for (int i = 0; i < 2; i++)
#pragma unroll
                for (int f = 0; f < 8; f++)
                    MMA16816(acc[i][f], ah[i], bb[f >> 1][(f & 1) * 2], bb[f >> 1][(f & 1) * 2 + 1]);
#pragma unroll
            for (int i = 0; i < 2; i++)
#pragma unroll
                for (int f = 0; f < 8; f++)
                    MMA16816(acc[i][f], al[i], bb[f >> 1][(f & 1) * 2], bb[f >> 1][(f & 1) * 2 + 1]);
#pragma unroll
            for (int j = 0; j < 4; j++) LDSM4(bb[j], sBl + b_off + j * 16 * STRIDE_B + kadd);
#pragma unroll
            for (int i = 0; i < 2; i++)
#pragma unroll
                for (int f = 0; f < 8; f++)
                    MMA16816(acc[i][f], ah[i], bb[f >> 1][(f & 1) * 2], bb[f >> 1][(f & 1) * 2 + 1]);
        }
    }
#undef LOAD_STAGE

    if (mode == 0) {
#pragma unroll
        for (int i = 0; i < 2; i++) {
            const int mrow = row0 + wm * 32 + i * 16 + (lane >> 2);
#pragma unroll
            for (int f = 0; f < 8; f++) {
                const int col = col0 + wn * 64 + f * 8 + (lane & 3) * 2;
                float2 lo2 = {acc[i][f][0], acc[i][f][1]};
                float2 hi2 = {acc[i][f][2], acc[i][f][3]};
                *(float2*)&C[(size_t)mrow * N + col] = lo2;
                *(float2*)&C[(size_t)(mrow + 8) * N + col] = hi2;
            }
        }
    } else {
#pragma unroll
        for (int i = 0; i < 2; i++) {
            const int mrow = row0 + wm * 32 + i * 16 + (lane >> 2);
#pragma unroll
            for (int f = 0; f < 8; f++) {
                const int col = col0 + wn * 64 + f * 8 + (lane & 3) * 2;
                uint32_t h01 = pack_bf16x2(acc[i][f][1], acc[i][f][0]);
                float2 hf0 = unpack_bf16x2(h01);
                uint32_t l01 = pack_bf16x2(acc[i][f][1] - hf0.y, acc[i][f][0] - hf0.x);
                uint32_t h23 = pack_bf16x2(acc[i][f][3], acc[i][f][2]);
                float2 hf1 = unpack_bf16x2(h23);
                uint32_t l23 = pack_bf16x2(acc[i][f][3] - hf1.y, acc[i][f][2] - hf1.x);
                *(uint32_t*)&Chi[(size_t)mrow * N + col] = h01;
                *(uint32_t*)&Clo[(size_t)mrow * N + col] = l01;
                *(uint32_t*)&Chi[(size_t)(mrow + 8) * N + col] = h23;
                *(uint32_t*)&Clo[(size_t)(mrow + 8) * N + col] = l23;
            }
        }
    }
}

// ---------------- HMMA causal flash attention ----------------
// CTA: 128 q-rows (8 warps x 16 rows), key tiles of 64, D=128.
// 3-stage KV cp.async pipeline, one barrier per tile.
#define FSTR 272                 /* bytes per 128-elem bf16 row (136 elems) */
#define KV_T 17408               /* 64*FSTR */
#define KV_STAGE (4 * KV_T)      /* 69632 */
#define FLASH_SMEM (3 * KV_STAGE) /* 208896 */

__global__ __launch_bounds__(256, 1) void flash_hmma(
    const __nv_bfloat16* __restrict__ qh_g, const __nv_bfloat16* __restrict__ ql_g,
    const __nv_bfloat16* __restrict__ kh_g, const __nv_bfloat16* __restrict__ kl_g,
    const __nv_bfloat16* __restrict__ vh_g, const __nv_bfloat16* __restrict__ vl_g,
    __nv_bfloat16* __restrict__ oh_g, __nv_bfloat16* __restrict__ ol_g)
{
    extern __shared__ char dsm[];
    const uint32_t sb = smem_u32(dsm);
    const int tid = threadIdx.x, lane = tid & 31, w = tid >> 5;
    const int qt = (int)gridDim.x - 1 - (int)blockIdx.x;   // big tiles first
    const int h = blockIdx.y, b = blockIdx.z;
    const int kvh = h >> 2;
    const int gr = qt * 128;
    const int nkt = 2 * qt + 2;

    // ---- stage Q (hi/lo) into smem, build A-frags in registers
    {
        const __nv_bfloat16* srcs[2] = {qh_g, ql_g};
#pragma unroll
        for (int t = 0; t < 2; t++) {
            uint32_t sdst = sb + t * (128 * FSTR);
            const __nv_bfloat16* src = srcs[t] + ((size_t)(b * SEQ + gr)) * HID + h * 128;
#pragma unroll
            for (int i = 0; i < 8; i++) {
                int idx = tid + i * 256;
                int r = idx >> 4, c = idx & 15;
                cp16(sdst + (uint32_t)r * FSTR + c * 16,
                     (const char*)(src + (size_t)r * HID) + c * 16);
            }
        }
        CP_COMMIT();
        asm volatile("cp.async.wait_group 0;\n" ::: "memory");
        __syncthreads();
    }
    uint32_t qhf[8][4], qlf[8][4];
    {
        const uint32_t qoff = (uint32_t)(w * 16 + (lane & 15)) * FSTR + ((lane >> 4) * 16);
#pragma unroll
        for (int kf = 0; kf < 8; kf++) {
            LDSM4(qhf[kf], sb + qoff + kf * 32);
            LDSM4(qlf[kf], sb + 128 * FSTR + qoff + kf * 32);
        }
    }
    __syncthreads();

    float o[16][4];
#pragma unroll
    for (int i = 0; i < 16; i++) { o[i][0] = 0.f; o[i][1] = 0.f; o[i][2] = 0.f; o[i][3] = 0.f; }
    float m0 = -1e5f, m1 = -1e5f, l0 = 0.f, l1 = 0.f;

    const uint32_t koff = (uint32_t)(((lane >> 4) << 3) + (lane & 7)) * FSTR + (((lane >> 3) & 1) * 16);
    const uint32_t voff = (uint32_t)((((lane >> 3) & 1) << 3) + (lane & 7)) * FSTR + ((lane >> 4) * 16);

    const __nv_bfloat16* kh_p = kh_g + ((size_t)(b * SEQ)) * KVD + kvh * 128;
    const __nv_bfloat16* kl_p = kl_g + ((size_t)(b * SEQ)) * KVD + kvh * 128;
    const __nv_bfloat16* vh_p = vh_g + ((size_t)(b * SEQ)) * KVD + kvh * 128;
    const __nv_bfloat16* vl_p = vl_g + ((size_t)(b * SEQ)) * KVD + kvh * 128;

#define LOADKV(kt_, buf_) do { \
    uint32_t s0_ = sb + (buf_) * KV_STAGE; \
    const __nv_bfloat16* gs_[4] = { \
        kh_p + (size_t)(kt_) * 64 * KVD, kl_p + (size_t)(kt_) * 64 * KVD, \
        vh_p + (size_t)(kt_) * 64 * KVD, vl_p + (size_t)(kt_) * 64 * KVD}; \
    _Pragma("unroll") \
    for (int t_ = 0; t_ < 4; t_++) { \
        _Pragma("unroll") \
        for (int i_ = 0; i_ < 4; i_++) { \
            int idx_ = tid + i_ * 256; \
            int r_ = idx_ >> 4, c_ = idx_ & 15; \
            cp16(s0_ + t_ * KV_T + (uint32_t)r_ * FSTR + c_ * 16, \
                 (const char*)(gs_[t_] + (size_t)r_ * KVD) + c_ * 16); \
        } \
    } \
    CP_COMMIT(); \
} while (0)

    LOADKV(0, 0);
    LOADKV(1, 1);
    const float Cs = 0.08838834764831845f * 1.4426950408889634f;  // scale*log2e

    int st = 0;       // stage holding tile kt
    int st2 = 2;      // stage to receive tile kt+2
    for (int kt = 0; kt < nkt; kt++) {
        if (kt + 2 < nkt) {
            asm volatile("cp.async.wait_group 1;\n" ::: "memory");
        } else {
            asm volatile("cp.async.wait_group 0;\n" ::: "memory");
        }
        __syncthreads();
        if (kt + 2 < nkt) LOADKV(kt + 2, st2);

        const uint32_t sKh = sb + st * KV_STAGE;
        const uint32_t sKl = sKh + KV_T, sVh = sKh + 2 * KV_T, sVl = sKh + 3 * KV_T;

        // ---- QK^T (3-term split)
        float s[8][4];
#pragma unroll
        for (int i = 0; i < 8; i++) { s[i][0] = 0.f; s[i][1] = 0.f; s[i][2] = 0.f; s[i][3] = 0.f; }
#pragma unroll
        for (int kf = 0; kf < 8; kf++) {
#pragma unroll
            for (int nb = 0; nb < 4; nb++) {
                uint32_t bh[4], bl[4];
                LDSM4(bh, sKh + koff + nb * (16 * FSTR) + kf * 32);
                MMA16816(s[2 * nb], qhf[kf], bh[0], bh[1]);
                MMA16816(s[2 * nb + 1], qhf[kf], bh[2], bh[3]);
                MMA16816(s[2 * nb], qlf[kf], bh[0], bh[1]);
                MMA16816(s[2 * nb + 1], qlf[kf], bh[2], bh[3]);
                LDSM4(bl, sKl + koff + nb * (16 * FSTR) + kf * 32);
                MMA16816(s[2 * nb], qhf[kf], bl[0], bl[1]);
                MMA16816(s[2 * nb + 1], qhf[kf], bl[2], bl[3]);
            }
        }
#pragma unroll
        for (int nf = 0; nf < 8; nf++) {
            s[nf][0] *= Cs; s[nf][1] *= Cs; s[nf][2] *= Cs; s[nf][3] *= Cs;
        }
        // ---- causal mask (only the two diagonal tiles)
        if (kt >= nkt - 2) {
            const int r0 = gr + w * 16 + (lane >> 2);
            const int c0 = kt * 64 + 2 * (lane & 3);
#pragma unroll
            for (int nf = 0; nf < 8; nf++) {
#pragma unroll
                for (int j = 0; j < 4; j++) {
                    int col = c0 + nf * 8 + (j & 1);
                    int row = r0 + (j >> 1) * 8;
                    if (col > row) s[nf][j] = -1e5f;
                }
            }
        }
        // ---- online softmax (FMA-pipe exp2)
        float mx0 = -1e30f, mx1 = -1e30f;
#pragma unroll
        for (int nf = 0; nf < 8; nf++) {
            mx0 = fmaxf(mx0, fmaxf(s[nf][0], s[nf][1]));
            mx1 = fmaxf(mx1, fmaxf(s[nf][2], s[nf][3]));
        }
        mx0 = fmaxf(mx0, __shfl_xor_sync(0xffffffffu, mx0, 1));
        mx0 = fmaxf(mx0, __shfl_xor_sync(0xffffffffu, mx0, 2));
        mx1 = fmaxf(mx1, __shfl_xor_sync(0xffffffffu, mx1, 1));
        mx1 = fmaxf(mx1, __shfl_xor_sync(0xffffffffu, mx1, 2));
        const float mn0 = fmaxf(m0, mx0), mn1 = fmaxf(m1, mx1);
        const float cr0 = exp2p(m0 - mn0), cr1 = exp2p(m1 - mn1);
        m0 = mn0; m1 = mn1;
        float rs0 = 0.f, rs1 = 0.f;
#pragma unroll
        for (int nf = 0; nf < 8; nf++) {
            float p0 = exp2p(s[nf][0] - mn0), p1 = exp2p(s[nf][1] - mn0);
            float p2 = exp2p(s[nf][2] - mn1), p3 = exp2p(s[nf][3] - mn1);
            s[nf][0] = p0; s[nf][1] = p1; s[nf][2] = p2; s[nf][3] = p3;
            rs0 += p0 + p1; rs1 += p2 + p3;
        }
        rs0 += __shfl_xor_sync(0xffffffffu, rs0, 1);
        rs0 += __shfl_xor_sync(0xffffffffu, rs0, 2);
        rs1 += __shfl_xor_sync(0xffffffffu, rs1, 1);
        rs1 += __shfl_xor_sync(0xffffffffu, rs1, 2);
        l0 = l0 * cr0 + rs0;
        l1 = l1 * cr1 + rs1;
#pragma unroll
        for (int nf = 0; nf < 16; nf++) {
            o[nf][0] *= cr0; o[nf][1] *= cr0; o[nf][2] *= cr1; o[nf][3] *= cr1;
        }
        // ---- P @ V (3-term split); P acc-frag -> A-frag conversion
#pragma unroll
        for (int kb = 0; kb < 4; kb++) {
            uint32_t ph[4], pl[4];
#pragma unroll
            for (int q2 = 0; q2 < 2; q2++) {
                const int nf = 2 * kb + q2;
                uint32_t h01 = pack_bf16x2(s[nf][1], s[nf][0]);
                float2 f01 = unpack_bf16x2(h01);
                uint32_t l01 = pack_bf16x2(s[nf][1] - f01.y, s[nf][0] - f01.x);
                uint32_t h23 = pack_bf16x2(s[nf][3], s[nf][2]);
                float2 f23 = unpack_bf16x2(h23);
                uint32_t l23 = pack_bf16x2(s[nf][3] - f23.y, s[nf][2] - f23.x);
                ph[2 * q2] = h01; ph[2 * q2 + 1] = h23;
                pl[2 * q2] = l01; pl[2 * q2 + 1] = l23;
            }
#pragma unroll
            for (int ng = 0; ng < 8; ng++) {
                uint32_t vh[4], vl[4];
                LDSM4T(vh, sVh + voff + kb * (16 * FSTR) + ng * 32);
                MMA16816(o[2 * ng], ph, vh[0], vh[1]);
                MMA16816(o[2 * ng + 1], ph, vh[2], vh[3]);
                MMA16816(o[2 * ng], pl, vh[0], vh[1]);
                MMA16816(o[2 * ng + 1], pl, vh[2], vh[3]);
                LDSM4T(vl, sVl + voff + kb * (16 * FSTR) + ng * 32);
                MMA16816(o[2 * ng], ph, vl[0], vl[1]);
                MMA16816(o[2 * ng + 1], ph, vl[2], vl[3]);
            }
        }
        st = (st == 2) ? 0 : st + 1;
        st2 = (st2 == 2) ? 0 : st2 + 1;
    }
#undef LOADKV

    // ---- epilogue: O/l -> bf16 hi/lo, store [TOK][HID]
    const float inv0 = 1.f / l0, inv1 = 1.f / l1;
    const size_t row0_ = (size_t)(b * SEQ + gr + w * 16 + (lane >> 2));
    const int colb = h * 128 + 2 * (lane & 3);
#pragma unroll
    for (int nf = 0; nf < 16; nf++) {
        const int col = colb + nf * 8;
        float v0 = o[nf][0] * inv0, v1 = o[nf][1] * inv0;
        float v2 = o[nf][2] * inv1, v3 = o[nf][3] * inv1;
        uint32_t h01 = pack_bf16x2(v1, v0);
        float2 f01 = unpack_bf16x2(h01);
        uint32_t l01 = pack_bf16x2(v1 - f01.y, v0 - f01.x);
        uint32_t h23 = pack_bf16x2(v3, v2);
        float2 f23 = unpack_bf16x2(h23);
        uint32_t l23 = pack_bf16x2(v3 - f23.y, v2 - f23.x);
        *(uint32_t*)&oh_g[row0_ * HID + col] = h01;
        *(uint32_t*)&ol_g[row0_ * HID + col] = l01;
        *(uint32_t*)&oh_g[(row0_ + 8) * HID + col] = h23;
        *(uint32_t*)&ol_g[(row0_ + 8) * HID + col] = l23;
    }
}

// ---------------- launch ----------------
extern "C" void kernel_launch(void* const* d_in, const int* in_sizes, int n_in,
                              void* d_out, int out_size)
{
    const float* x  = (const float*)d_in[0];
    const float* Wq = (const float*)d_in[2];
    const float* Aq = (const float*)d_in[3];
    const float* Bq = (const float*)d_in[4];
    const float* mq = (const float*)d_in[5];
    const float* Wk = (const float*)d_in[6];
    const float* Ak = (const float*)d_in[7];
    const float* Bk = (const float*)d_in[8];
    const float* mk = (const float*)d_in[9];
    const float* Wv = (const float*)d_in[10];
    const float* Av = (const float*)d_in[11];
    const float* Bv = (const float*)d_in[12];
    const float* mv = (const float*)d_in[13];
    const float* Wo = (const float*)d_in[14];
    const float* Ao = (const float*)d_in[15];
    const float* Bo = (const float*)d_in[16];
    const float* mo = (const float*)d_in[17];

    __nv_bfloat16 *xh, *xl, *Wqh, *Wql, *Wkh, *Wkl, *Wvh, *Wvl, *Woh, *Wol;
    __nv_bfloat16 *qh, *ql, *kh, *kl, *vh, *vl, *ath, *atl;
    cudaGetSymbolAddress((void**)&xh, g_xh);   cudaGetSymbolAddress((void**)&xl, g_xl);
    cudaGetSymbolAddress((void**)&Wqh, g_Wqh); cudaGetSymbolAddress((void**)&Wql, g_Wql);
    cudaGetSymbolAddress((void**)&Wkh, g_Wkh); cudaGetSymbolAddress((void**)&Wkl, g_Wkl);
    cudaGetSymbolAddress((void**)&Wvh, g_Wvh); cudaGetSymbolAddress((void**)&Wvl, g_Wvl);
    cudaGetSymbolAddress((void**)&Woh, g_Woh); cudaGetSymbolAddress((void**)&Wol, g_Wol);
    cudaGetSymbolAddress((void**)&qh, g_qh);   cudaGetSymbolAddress((void**)&ql, g_ql);
    cudaGetSymbolAddress((void**)&kh, g_kh);   cudaGetSymbolAddress((void**)&kl, g_kl);
    cudaGetSymbolAddress((void**)&vh, g_vh);   cudaGetSymbolAddress((void**)&vl, g_vl);
    cudaGetSymbolAddress((void**)&ath, g_ath); cudaGetSymbolAddress((void**)&atl, g_atl);

    cudaFuncSetAttribute(dora_weights, cudaFuncAttributeMaxDynamicSharedMemorySize, DORA_SMEM);
    cudaFuncSetAttribute(gemm_hmma, cudaFuncAttributeMaxDynamicSharedMemorySize, GEMM_SMEM);
    cudaFuncSetAttribute(flash_hmma, cudaFuncAttributeMaxDynamicSharedMemorySize, FLASH_SMEM);

    // 1) DoRA effective weights (bf16 hi/lo), 8 rows per block
    dora_weights<<<HID / 8, 256, DORA_SMEM>>>(Wq, Aq, Bq, mq, Wqh, Wql);
    dora_weights<<<KVD / 8, 256, DORA_SMEM>>>(Wk, Ak, Bk, mk, Wkh, Wkl);
    dora_weights<<<KVD / 8, 256, DORA_SMEM>>>(Wv, Av, Bv, mv, Wvh, Wvl);
    dora_weights<<<HID / 8, 256, DORA_SMEM>>>(Wo, Ao, Bo, mo, Woh, Wol);

    // 2) split x
    split_bf16<<<(TOK * HID / 4 + 255) / 256, 256>>>(x, xh, xl, TOK * HID / 4);

    // 3) q/k/v projections -> bf16 hi/lo directly
    gemm_hmma<<<dim3(HID / 128, TOK / 128), 256, GEMM_SMEM>>>(xh, xl, Wqh, Wql, nullptr, qh, ql, HID, 1);
    gemm_hmma<<<dim3(KVD / 128, TOK / 128), 256, GEMM_SMEM>>>(xh, xl, Wkh, Wkl, nullptr, kh, kl, KVD, 1);
    gemm_hmma<<<dim3(KVD / 128, TOK / 128), 256, GEMM_SMEM>>>(xh, xl, Wvh, Wvl, nullptr, vh, vl, KVD, 1);

    // 4) causal attention (HMMA) -> bf16 hi/lo attention output
    flash_hmma<<<dim3(SEQ / 128, 32, 2), 256, FLASH_SMEM>>>(qh, ql, kh, kl, vh, vl, ath, atl);

    // 5) output projection -> d_out (fp32)
    gemm_hmma<<<dim3(HID / 128, TOK / 128), 256, GEMM_SMEM>>>(ath, atl, Woh, Wol, (float*)d_out, nullptr, nullptr, HID, 0);
}

// round 6
// speedup vs baseline: 1.1699x; 1.1699x over previous
#include <cuda_runtime.h>
#include <cuda_fp16.h>
#include <cstdint>
#include <math.h>

#define HID 4096
#define KVD 1024
#define TOK 4096   /* B*S */
#define SEQ 2048

// ---------------- device scratch ----------------
__device__ __half g_xh[TOK * HID];
__device__ __half g_xl[TOK * HID];
__device__ __half g_Wqh[HID * HID];
__device__ __half g_Wql[HID * HID];
__device__ __half g_Wkh[KVD * HID];
__device__ __half g_Wkl[KVD * HID];
__device__ __half g_Wvh[KVD * HID];
__device__ __half g_Wvl[KVD * HID];
__device__ __half g_Woh[HID * HID];
__device__ __half g_Wol[HID * HID];
__device__ __half g_qh[TOK * HID];
__device__ __half g_ql[TOK * HID];
__device__ __half g_kh[TOK * KVD];
__device__ __half g_kl[TOK * KVD];
__device__ __half g_vh[TOK * KVD];
__device__ __half g_ath[TOK * HID];
__device__ __half g_atl[TOK * HID];

// ---------------- helpers ----------------
__device__ __forceinline__ uint32_t smem_u32(const void* p) {
    uint32_t a;
    asm("{ .reg .u64 t; cvta.to.shared.u64 t, %1; cvt.u32.u64 %0, t; }" : "=r"(a) : "l"(p));
    return a;
}
__device__ __forceinline__ void cp16(uint32_t dst, const void* src) {
    asm volatile("cp.async.cg.shared.global [%0], [%1], 16;\n" :: "r"(dst), "l"(src) : "memory");
}
#define CP_COMMIT() asm volatile("cp.async.commit_group;\n" ::: "memory")

#define LDSM4(r, a) \
    asm volatile("ldmatrix.sync.aligned.m8n8.x4.shared.b16 {%0,%1,%2,%3}, [%4];" \
                 : "=r"((r)[0]), "=r"((r)[1]), "=r"((r)[2]), "=r"((r)[3]) : "r"(a))
#define LDSM4T(r, a) \
    asm volatile("ldmatrix.sync.aligned.m8n8.x4.trans.shared.b16 {%0,%1,%2,%3}, [%4];" \
                 : "=r"((r)[0]), "=r"((r)[1]), "=r"((r)[2]), "=r"((r)[3]) : "r"(a))

#define MMA16816(d, a, b0, b1) \
    asm volatile("mma.sync.aligned.m16n8k16.row.col.f32.f16.f16.f32 " \
                 "{%0,%1,%2,%3}, {%4,%5,%6,%7}, {%8,%9}, {%0,%1,%2,%3};" \
                 : "+f"((d)[0]), "+f"((d)[1]), "+f"((d)[2]), "+f"((d)[3]) \
                 : "r"((a)[0]), "r"((a)[1]), "r"((a)[2]), "r"((a)[3]), "r"(b0), "r"(b1))

__device__ __forceinline__ uint32_t pack_f16x2(float hi_, float lo_) {
    __half2 h = __floats2half2_rn(lo_, hi_);   // x=lo (low half), y=hi (high half)
    return *(uint32_t*)&h;
}
__device__ __forceinline__ float2 unpack_f16x2(uint32_t u) {
    __half2 h = *(__half2*)&u;
    float2 r;
    r.x = __low2float(h);
    r.y = __high2float(h);
    return r;
}
// fast exp2 on FMA pipe (no MUFU). x <= 0 expected; rel err ~2.4e-6.
__device__ __forceinline__ float exp2p(float x) {
    x = fmaxf(x, -120.f);
    int e = __float2int_rn(x);
    float f = x - (float)e;
    float p = 1.3333558e-3f;
    p = fmaf(p, f, 9.6181291e-3f);
    p = fmaf(p, f, 5.5504109e-2f);
    p = fmaf(p, f, 2.4022651e-1f);
    p = fmaf(p, f, 6.9314718e-1f);
    p = fmaf(p, f, 1.0f);
    return p * __int_as_float((uint32_t)(e + 127) << 23);
}

// ---------------- DoRA weight materialization -> fp16 hi/lo ----------------
__global__ __launch_bounds__(256) void dora_weights(
    const float* __restrict__ W, const float* __restrict__ A,
    const float* __restrict__ Bm, const float* __restrict__ mvec,
    __half* __restrict__ Whi, __half* __restrict__ Wlo)
{
    const int row = blockIdx.x;
    const int tid = threadIdx.x;
    float b[8];
#pragma unroll
    for (int r = 0; r < 8; r++) b[r] = 2.0f * Bm[row * 8 + r];

    const float4* Wrow = (const float4*)(W + (size_t)row * HID);
    float4 w[4];
    float ss = 0.f;
#pragma unroll
    for (int c = 0; c < 4; c++) {
        int col4 = tid + 256 * c;
        float4 wv = Wrow[col4];
#pragma unroll
        for (int r = 0; r < 8; r++) {
            float4 av = ((const float4*)(A + (size_t)r * HID))[col4];
            wv.x += b[r] * av.x; wv.y += b[r] * av.y;
            wv.z += b[r] * av.z; wv.w += b[r] * av.w;
        }
        ss += wv.x * wv.x + wv.y * wv.y + wv.z * wv.z + wv.w * wv.w;
        w[c] = wv;
    }
#pragma unroll
    for (int off = 16; off; off >>= 1)
        ss += __shfl_xor_sync(0xffffffffu, ss, off);

    __shared__ float red[8];
    __shared__ float s_scale;
    if ((tid & 31) == 0) red[tid >> 5] = ss;
    __syncthreads();
    if (tid == 0) {
        float t = 0.f;
#pragma unroll
        for (int i = 0; i < 8; i++) t += red[i];
        s_scale = mvec[row] / (sqrtf(t) + 1e-8f);
    }
    __syncthreads();
    const float sc = s_scale;
#pragma unroll
    for (int c = 0; c < 4; c++) {
        float vv[4] = {w[c].x * sc, w[c].y * sc, w[c].z * sc, w[c].w * sc};
        size_t base = (size_t)row * HID + (tid + 256 * c) * 4;
#pragma unroll
        for (int e = 0; e < 4; e++) {
            __half h = __float2half_rn(vv[e]);
            Whi[base + e] = h;
            Wlo[base + e] = __float2half_rn(vv[e] - __half2float(h));
        }
    }
}

// ---------------- fp32 -> fp16 hi/lo split (x only) ----------------
__global__ __launch_bounds__(256) void split_f16(
    const float* __restrict__ in, __half* __restrict__ hi,
    __half* __restrict__ lo, int n4)
{
    int i = blockIdx.x * 256 + threadIdx.x;
    if (i >= n4) return;
    float4 v = ((const float4*)in)[i];
    float vv[4] = {v.x, v.y, v.z, v.w};
    size_t base = (size_t)i * 4;
#pragma unroll
    for (int e = 0; e < 4; e++) {
        __half h = __float2half_rn(vv[e]);
        hi[base + e] = h;
        lo[base + e] = __float2half_rn(vv[e] - __half2float(h));
    }
}

// ---------------- HMMA mainloop: 128x128 tile, K=4096, 3-term fp16 split ----
#define STRIDE_B 80
#define TILE_B   (128 * STRIDE_B)
#define STAGE_B  (4 * TILE_B)
#define GEMM_SMEM (2 * STAGE_B)          /* 81920, 2 CTAs/SM */

__device__ __forceinline__ void hmma_mainloop(
    uint32_t sb, const __half* g0, const __half* g1,
    const __half* g2, const __half* g3, int tid, float acc[2][8][4])
{
    const int lane = tid & 31, wid = tid >> 5;
    const int wm = wid & 3, wn = wid >> 2;
    const int K = 4096;
    const int ldr = tid >> 2;
    const int ldc = (tid & 3) * 16;

    const uint32_t a_off = (uint32_t)(wm * 32 + (lane & 15)) * STRIDE_B + ((lane >> 4) * 16);
    const uint32_t b_off = (uint32_t)(wn * 64 + (((lane >> 4) << 3) + (lane & 7))) * STRIDE_B
                           + (((lane >> 3) & 1) * 16);

#define LOAD_STAGE(buf, k0) do { \
    uint32_t s0_ = sb + (buf) * STAGE_B; \
    const __half* gg_[4] = {g0 + (k0), g1 + (k0), g2 + (k0), g3 + (k0)}; \
    _Pragma("unroll") \
    for (int t_ = 0; t_ < 4; t_++) { \
        uint32_t st_ = s0_ + t_ * TILE_B; \
        _Pragma("unroll") \
        for (int p_ = 0; p_ < 2; p_++) { \
            int r_ = ldr + p_ * 64; \
            cp16(st_ + (uint32_t)r_ * STRIDE_B + ldc, \
                 (const char*)(gg_[t_] + (size_t)r_ * K) + ldc); \
        } \
    } \
    CP_COMMIT(); \
} while (0)

    LOAD_STAGE(0, 0);
    for (int ch = 0; ch < 128; ch++) {
        if (ch + 1 < 128) {
            LOAD_STAGE((ch + 1) & 1, (ch + 1) * 32);
            asm volatile("cp.async.wait_group 1;\n" ::: "memory");
        } else {
            asm volatile("cp.async.wait_group 0;\n" ::: "memory");
        }
        __syncthreads();
        const uint32_t s0 = sb + (ch & 1) * STAGE_B;
        const uint32_t sAh = s0, sAl = s0 + TILE_B;
        const uint32_t sBh = s0 + 2 * TILE_B, sBl = s0 + 3 * TILE_B;
#pragma unroll
        for (int k16 = 0; k16 < 2; k16++) {
            const uint32_t kadd = k16 * 32;
            uint32_t ah[2][4], al[2][4], bb[4][4];
            LDSM4(ah[0], sAh + a_off + kadd);
            LDSM4(ah[1], sAh + a_off + 16 * STRIDE_B + kadd);
            LDSM4(al[0], sAl + a_off + kadd);
            LDSM4(al[1], sAl + a_off + 16 * STRIDE_B + kadd);
#pragma unroll
            for (int j = 0; j < 4; j++) LDSM4(bb[j], sBh + b_off + j * 16 * STRIDE_B + kadd);
#pragma unroll
            for (int i = 0; i < 2; i++)
#pragma unroll
                for (int f = 0; f < 8; f++)
                    MMA16816(acc[i][f], ah[i], bb[f >> 1][(f & 1) * 2], bb[f >> 1][(f & 1) * 2 + 1]);
#pragma unroll
            for (int i = 0; i < 2; i++)
#pragma unroll
                for (int f = 0; f < 8; f++)
                    MMA16816(acc[i][f], al[i], bb[f >> 1][(f & 1) * 2], bb[f >> 1][(f & 1) * 2 + 1]);
#pragma unroll
            for (int j = 0; j < 4; j++) LDSM4(bb[j], sBl + b_off + j * 16 * STRIDE_B + kadd);
#pragma unroll
            for (int i = 0; i < 2; i++)
#pragma unroll
                for (int f = 0; f < 8; f++)
                    MMA16816(acc[i][f], ah[i], bb[f >> 1][(f & 1) * 2], bb[f >> 1][(f & 1) * 2 + 1]);
        }
        __syncthreads();
    }
#undef LOAD_STAGE
}

// ---------------- merged QKV projection ----------------
// grid.x: [0,32)->Q, [32,40)->K, [40,48)->V ; grid.y: 32 M-tiles.
__global__ __launch_bounds__(256, 1) void gemm_qkv(
    const __half* __restrict__ xh, const __half* __restrict__ xl,
    const __half* __restrict__ Wqh, const __half* __restrict__ Wql,
    const __half* __restrict__ Wkh, const __half* __restrict__ Wkl,
    const __half* __restrict__ Wvh, const __half* __restrict__ Wvl,
    __half* __restrict__ qh, __half* __restrict__ ql,
    __half* __restrict__ kh, __half* __restrict__ kl,
    __half* __restrict__ vh)
{
    extern __shared__ char dsm[];
    const uint32_t sb = smem_u32(dsm);
    const int tid = threadIdx.x, lane = tid & 31, wid = tid >> 5;
    const int wm = wid & 3, wn = wid >> 2;
    const int bx = blockIdx.x;
    const int row0 = blockIdx.y << 7;
    const int K = 4096;

    const __half *Bh_, *Bl_;
    __half *Oh, *Ol;
    int N, col0, single;
    if (bx < 32) {
        Bh_ = Wqh; Bl_ = Wql; Oh = qh; Ol = ql; N = HID; col0 = bx << 7; single = 0;
    } else if (bx < 40) {
        Bh_ = Wkh; Bl_ = Wkl; Oh = kh; Ol = kl; N = KVD; col0 = (bx - 32) << 7; single = 0;
    } else {
        Bh_ = Wvh; Bl_ = Wvl; Oh = vh; Ol = nullptr; N = KVD; col0 = (bx - 40) << 7; single = 1;
    }

    float acc[2][8][4] = {};
    hmma_mainloop(sb, xh + (size_t)row0 * K, xl + (size_t)row0 * K,
                  Bh_ + (size_t)col0 * K, Bl_ + (size_t)col0 * K, tid, acc);

#pragma unroll
    for (int i = 0; i < 2; i++) {
        const int mrow = row0 + wm * 32 + i * 16 + (lane >> 2);
#pragma unroll
        for (int f = 0; f < 8; f++) {
            const int col = col0 + wn * 64 + f * 8 + (lane & 3) * 2;
            uint32_t h01 = pack_f16x2(acc[i][f][1], acc[i][f][0]);
            uint32_t h23 = pack_f16x2(acc[i][f][3], acc[i][f][2]);
            *(uint32_t*)&Oh[(size_t)mrow * N + col] = h01;
            *(uint32_t*)&Oh[(size_t)(mrow + 8) * N + col] = h23;
            if (!single) {
                float2 hf0 = unpack_f16x2(h01);
                float2 hf1 = unpack_f16x2(h23);
                uint32_t l01 = pack_f16x2(acc[i][f][1] - hf0.y, acc[i][f][0] - hf0.x);
                uint32_t l23 = pack_f16x2(acc[i][f][3] - hf1.y, acc[i][f][2] - hf1.x);
                *(uint32_t*)&Ol[(size_t)mrow * N + col] = l01;
                *(uint32_t*)&Ol[(size_t)(mrow + 8) * N + col] = l23;
            }
        }
    }
}

// ---------------- output projection (fp32 out) ----------------
__global__ __launch_bounds__(256, 1) void gemm_o(
    const __half* __restrict__ Ah, const __half* __restrict__ Al,
    const __half* __restrict__ Bh, const __half* __restrict__ Bl,
    float* __restrict__ C)
{
    extern __shared__ char dsm[];
    const uint32_t sb = smem_u32(dsm);
    const int tid = threadIdx.x, lane = tid & 31, wid = tid >> 5;
    const int wm = wid & 3, wn = wid >> 2;
    const int row0 = blockIdx.y << 7, col0 = blockIdx.x << 7;
    const int K = 4096, N = HID;

    float acc[2][8][4] = {};
    hmma_mainloop(sb, Ah + (size_t)row0 * K, Al + (size_t)row0 * K,
                  Bh + (size_t)col0 * K, Bl + (size_t)col0 * K, tid, acc);

#pragma unroll
    for (int i = 0; i < 2; i++) {
        const int mrow = row0 + wm * 32 + i * 16 + (lane >> 2);
#pragma unroll
        for (int f = 0; f < 8; f++) {
            const int col = col0 + wn * 64 + f * 8 + (lane & 3) * 2;
            float2 lo2 = {acc[i][f][0], acc[i][f][1]};
            float2 hi2 = {acc[i][f][2], acc[i][f][3]};
            *(float2*)&C[(size_t)mrow * N + col] = lo2;
            *(float2*)&C[(size_t)(mrow + 8) * N + col] = hi2;
        }
    }
}

// ---------------- HMMA causal flash attention ----------------
// CTA: 128 q-rows (8 warps x 16 rows), key tiles of 64, D=128.
// KV stage = {kh, kl, vh}; 3-stage cp.async ring, one barrier per tile.
// QK 3-term (q,k fp16 pairs); PV 2-term (P fp16 pair x v single fp16).
#define FSTR 272                 /* bytes per 128-elem fp16 row (136 elems) */
#define KV_T 17408               /* 64*FSTR */
#define KV_STAGE (3 * KV_T)      /* 52224 */
#define FLASH_SMEM (2 * 128 * FSTR + 3 * KV_STAGE)  /* 69632 + 156672 = 226304 */

__global__ __launch_bounds__(256, 1) void flash_hmma(
    const __half* __restrict__ qh_g, const __half* __restrict__ ql_g,
    const __half* __restrict__ kh_g, const __half* __restrict__ kl_g,
    const __half* __restrict__ vh_g,
    __half* __restrict__ oh_g, __half* __restrict__ ol_g)
{
    extern __shared__ char dsm[];
    const uint32_t sq = smem_u32(dsm);            // Q region: 2 * 128*FSTR
    const uint32_t sb = sq + 2 * 128 * FSTR;      // KV ring
    const int tid = threadIdx.x, lane = tid & 31, w = tid >> 5;
    const int qt = (int)gridDim.x - 1 - (int)blockIdx.x;   // big tiles first
    const int h = blockIdx.y, b = blockIdx.z;
    const int kvh = h >> 2;
    const int gr = qt * 128;
    const int nkt = 2 * qt + 2;

    // ---- stage Q (hi/lo) into smem, build A-frags in registers
    {
        const __half* srcs[2] = {qh_g, ql_g};
#pragma unroll
        for (int t = 0; t < 2; t++) {
            uint32_t sdst = sq + t * (128 * FSTR);
            const __half* src = srcs[t] + ((size_t)(b * SEQ + gr)) * HID + h * 128;
#pragma unroll
            for (int i = 0; i < 8; i++) {
                int idx = tid + i * 256;
                int r = idx >> 4, c = idx & 15;
                cp16(sdst + (uint32_t)r * FSTR + c * 16,
                     (const char*)(src + (size_t)r * HID) + c * 16);
            }
        }
        CP_COMMIT();
        asm volatile("cp.async.wait_group 0;\n" ::: "memory");
        __syncthreads();
    }
    uint32_t qhf[8][4], qlf[8][4];
    {
        const uint32_t qoff = (uint32_t)(w * 16 + (lane & 15)) * FSTR + ((lane >> 4) * 16);
#pragma unroll
        for (int kf = 0; kf < 8; kf++) {
            LDSM4(qhf[kf], sq + qoff + kf * 32);
            LDSM4(qlf[kf], sq + 128 * FSTR + qoff + kf * 32);
        }
    }
    __syncthreads();

    float o[16][4];
#pragma unroll
    for (int i = 0; i < 16; i++) { o[i][0] = 0.f; o[i][1] = 0.f; o[i][2] = 0.f; o[i][3] = 0.f; }
    float m0 = -1e5f, m1 = -1e5f, l0 = 0.f, l1 = 0.f;

    const uint32_t koff = (uint32_t)(((lane >> 4) << 3) + (lane & 7)) * FSTR + (((lane >> 3) & 1) * 16);
    const uint32_t voff = (uint32_t)((((lane >> 3) & 1) << 3) + (lane & 7)) * FSTR + ((lane >> 4) * 16);

    const __half* kh_p = kh_g + ((size_t)(b * SEQ)) * KVD + kvh * 128;
    const __half* kl_p = kl_g + ((size_t)(b * SEQ)) * KVD + kvh * 128;
    const __half* vh_p = vh_g + ((size_t)(b * SEQ)) * KVD + kvh * 128;

#define LOADKV(kt_, buf_) do { \
    uint32_t s0_ = sb + (buf_) * KV_STAGE; \
    const __half* gs_[3] = { \
        kh_p + (size_t)(kt_) * 64 * KVD, kl_p + (size_t)(kt_) * 64 * KVD, \
        vh_p + (size_t)(kt_) * 64 * KVD}; \
    _Pragma("unroll") \
    for (int t_ = 0; t_ < 3; t_++) { \
        _Pragma("unroll") \
        for (int i_ = 0; i_ < 4; i_++) { \
            int idx_ = tid + i_ * 256; \
            int r_ = idx_ >> 4, c_ = idx_ & 15; \
            cp16(s0_ + t_ * KV_T + (uint32_t)r_ * FSTR + c_ * 16, \
                 (const char*)(gs_[t_] + (size_t)r_ * KVD) + c_ * 16); \
        } \
    } \
    CP_COMMIT(); \
} while (0)

    LOADKV(0, 0);
    LOADKV(1, 1);
    const float Cs = 0.08838834764831845f * 1.4426950408889634f;  // scale*log2e

    int st = 0;       // stage holding tile kt
    int st2 = 2;      // stage to receive tile kt+2
    for (int kt = 0; kt < nkt; kt++) {
        if (kt + 2 < nkt) {
            asm volatile("cp.async.wait_group 1;\n" ::: "memory");
        } else {
            asm volatile("cp.async.wait_group 0;\n" ::: "memory");
        }
        __syncthreads();
        if (kt + 2 < nkt) LOADKV(kt + 2, st2);

        const uint32_t sKh = sb + st * KV_STAGE;
        const uint32_t sKl = sKh + KV_T, sVh = sKh + 2 * KV_T;

        // ---- QK^T (3-term split)
        float s[8][4];
#pragma unroll
        for (int i = 0; i < 8; i++) { s[i][0] = 0.f; s[i][1] = 0.f; s[i][2] = 0.f; s[i][3] = 0.f; }
#pragma unroll
        for (int kf = 0; kf < 8; kf++) {
#pragma unroll
            for (int nb = 0; nb < 4; nb++) {
                uint32_t bh[4], bl[4];
                LDSM4(bh, sKh + koff + nb * (16 * FSTR) + kf * 32);
                MMA16816(s[2 * nb], qhf[kf], bh[0], bh[1]);
                MMA16816(s[2 * nb + 1], qhf[kf], bh[2], bh[3]);
                MMA16816(s[2 * nb], qlf[kf], bh[0], bh[1]);
                MMA16816(s[2 * nb + 1], qlf[kf], bh[2], bh[3]);
                LDSM4(bl, sKl + koff + nb * (16 * FSTR) + kf * 32);
                MMA16816(s[2 * nb], qhf[kf], bl[0], bl[1]);
                MMA16816(s[2 * nb + 1], qhf[kf], bl[2], bl[3]);
            }
        }
#pragma unroll
        for (int nf = 0; nf < 8; nf++) {
            s[nf][0] *= Cs; s[nf][1] *= Cs; s[nf][2] *= Cs; s[nf][3] *= Cs;
        }
        // ---- causal mask (only the two diagonal tiles)
        if (kt >= nkt - 2) {
            const int r0 = gr + w * 16 + (lane >> 2);
            const int c0 = kt * 64 + 2 * (lane & 3);
#pragma unroll
            for (int nf = 0; nf < 8; nf++) {
#pragma unroll
                for (int j = 0; j < 4; j++) {
                    int col = c0 + nf * 8 + (j & 1);
                    int row = r0 + (j >> 1) * 8;
                    if (col > row) s[nf][j] = -1e5f;
                }
            }
        }
        // ---- online softmax (FMA-pipe exp2)
        float mx0 = -1e30f, mx1 = -1e30f;
#pragma unroll
        for (int nf = 0; nf < 8; nf++) {
            mx0 = fmaxf(mx0, fmaxf(s[nf][0], s[nf][1]));
            mx1 = fmaxf(mx1, fmaxf(s[nf][2], s[nf][3]));
        }
        mx0 = fmaxf(mx0, __shfl_xor_sync(0xffffffffu, mx0, 1));
        mx0 = fmaxf(mx0, __shfl_xor_sync(0xffffffffu, mx0, 2));
        mx1 = fmaxf(mx1, __shfl_xor_sync(0xffffffffu, mx1, 1));
        mx1 = fmaxf(mx1, __shfl_xor_sync(0xffffffffu, mx1, 2));
        const float mn0 = fmaxf(m0, mx0), mn1 = fmaxf(m1, mx1);
        const float cr0 = exp2p(m0 - mn0), cr1 = exp2p(m1 - mn1);
        m0 = mn0; m1 = mn1;
        float rs0 = 0.f, rs1 = 0.f;
#pragma unroll
        for (int nf = 0; nf < 8; nf++) {
            float p0 = exp2p(s[nf][0] - mn0), p1 = exp2p(s[nf][1] - mn0);
            float p2 = exp2p(s[nf][2] - mn1), p3 = exp2p(s[nf][3] - mn1);
            s[nf][0] = p0; s[nf][1] = p1; s[nf][2] = p2; s[nf][3] = p3;
            rs0 += p0 + p1; rs1 += p2 + p3;
        }
        rs0 += __shfl_xor_sync(0xffffffffu, rs0, 1);
        rs0 += __shfl_xor_sync(0xffffffffu, rs0, 2);
        rs1 += __shfl_xor_sync(0xffffffffu, rs1, 1);
        rs1 += __shfl_xor_sync(0xffffffffu, rs1, 2);
        l0 = l0 * cr0 + rs0;
        l1 = l1 * cr1 + rs1;
#pragma unroll
        for (int nf = 0; nf < 16; nf++) {
            o[nf][0] *= cr0; o[nf][1] *= cr0; o[nf][2] *= cr1; o[nf][3] *= cr1;
        }
        // ---- P @ V: P fp16 pair (exact) x v single fp16 -> 2 MMA terms
#pragma unroll
        for (int kb = 0; kb < 4; kb++) {
            uint32_t ph[4], pl[4];
#pragma unroll
            for (int q2 = 0; q2 < 2; q2++) {
                const int nf = 2 * kb + q2;
                uint32_t h01 = pack_f16x2(s[nf][1], s[nf][0]);
                float2 f01 = unpack_f16x2(h01);
                uint32_t l01 = pack_f16x2(s[nf][1] - f01.y, s[nf][0] - f01.x);
                uint32_t h23 = pack_f16x2(s[nf][3], s[nf][2]);
                float2 f23 = unpack_f16x2(h23);
                uint32_t l23 = pack_f16x2(s[nf][3] - f23.y, s[nf][2] - f23.x);
                ph[2 * q2] = h01; ph[2 * q2 + 1] = h23;
                pl[2 * q2] = l01; pl[2 * q2 + 1] = l23;
            }
#pragma unroll
            for (int ng = 0; ng < 8; ng++) {
                uint32_t vv[4];
                LDSM4T(vv, sVh + voff + kb * (16 * FSTR) + ng * 32);
                MMA16816(o[2 * ng], ph, vv[0], vv[1]);
                MMA16816(o[2 * ng + 1], ph, vv[2], vv[3]);
                MMA16816(o[2 * ng], pl, vv[0], vv[1]);
                MMA16816(o[2 * ng + 1], pl, vv[2], vv[3]);
            }
        }
        st = (st == 2) ? 0 : st + 1;
        st2 = (st2 == 2) ? 0 : st2 + 1;
    }
#undef LOADKV

    // ---- epilogue: O/l -> fp16 hi/lo, store [TOK][HID]
    const float inv0 = 1.f / l0, inv1 = 1.f / l1;
    const size_t row0_ = (size_t)(b * SEQ + gr + w * 16 + (lane >> 2));
    const int colb = h * 128 + 2 * (lane & 3);
#pragma unroll
    for (int nf = 0; nf < 16; nf++) {
        const int col = colb + nf * 8;
        float v0 = o[nf][0] * inv0, v1 = o[nf][1] * inv0;
        float v2 = o[nf][2] * inv1, v3 = o[nf][3] * inv1;
        uint32_t h01 = pack_f16x2(v1, v0);
        float2 f01 = unpack_f16x2(h01);
        uint32_t l01 = pack_f16x2(v1 - f01.y, v0 - f01.x);
        uint32_t h23 = pack_f16x2(v3, v2);
        float2 f23 = unpack_f16x2(h23);
        uint32_t l23 = pack_f16x2(v3 - f23.y, v2 - f23.x);
        *(uint32_t*)&oh_g[row0_ * HID + col] = h01;
        *(uint32_t*)&ol_g[row0_ * HID + col] = l01;
        *(uint32_t*)&oh_g[(row0_ + 8) * HID + col] = h23;
        *(uint32_t*)&ol_g[(row0_ + 8) * HID + col] = l23;
    }
}

// ---------------- launch ----------------
extern "C" void kernel_launch(void* const* d_in, const int* in_sizes, int n_in,
                              void* d_out, int out_size)
{
    const float* x  = (const float*)d_in[0];
    const float* Wq = (const float*)d_in[2];
    const float* Aq = (const float*)d_in[3];
    const float* Bq = (const float*)d_in[4];
    const float* mq = (const float*)d_in[5];
    const float* Wk = (const float*)d_in[6];
    const float* Ak = (const float*)d_in[7];
    const float* Bk = (const float*)d_in[8];
    const float* mk = (const float*)d_in[9];
    const float* Wv = (const float*)d_in[10];
    const float* Av = (const float*)d_in[11];
    const float* Bv = (const float*)d_in[12];
    const float* mv = (const float*)d_in[13];
    const float* Wo = (const float*)d_in[14];
    const float* Ao = (const float*)d_in[15];
    const float* Bo = (const float*)d_in[16];
    const float* mo = (const float*)d_in[17];

    __half *xh, *xl, *Wqh, *Wql, *Wkh, *Wkl, *Wvh, *Wvl, *Woh, *Wol;
    __half *qh, *ql, *kh, *kl, *vh, *ath, *atl;
    cudaGetSymbolAddress((void**)&xh, g_xh);   cudaGetSymbolAddress((void**)&xl, g_xl);
    cudaGetSymbolAddress((void**)&Wqh, g_Wqh); cudaGetSymbolAddress((void**)&Wql, g_Wql);
    cudaGetSymbolAddress((void**)&Wkh, g_Wkh); cudaGetSymbolAddress((void**)&Wkl, g_Wkl);
    cudaGetSymbolAddress((void**)&Wvh, g_Wvh); cudaGetSymbolAddress((void**)&Wvl, g_Wvl);
    cudaGetSymbolAddress((void**)&Woh, g_Woh); cudaGetSymbolAddress((void**)&Wol, g_Wol);
    cudaGetSymbolAddress((void**)&qh, g_qh);   cudaGetSymbolAddress((void**)&ql, g_ql);
    cudaGetSymbolAddress((void**)&kh, g_kh);   cudaGetSymbolAddress((void**)&kl, g_kl);
    cudaGetSymbolAddress((void**)&vh, g_vh);
    cudaGetSymbolAddress((void**)&ath, g_ath); cudaGetSymbolAddress((void**)&atl, g_atl);

    cudaFuncSetAttribute(gemm_qkv, cudaFuncAttributeMaxDynamicSharedMemorySize, GEMM_SMEM);
    cudaFuncSetAttribute(gemm_o, cudaFuncAttributeMaxDynamicSharedMemorySize, GEMM_SMEM);
    cudaFuncSetAttribute(flash_hmma, cudaFuncAttributeMaxDynamicSharedMemorySize, FLASH_SMEM);

    // 1) DoRA effective weights (fp16 hi/lo)
    dora_weights<<<HID, 256>>>(Wq, Aq, Bq, mq, Wqh, Wql);
    dora_weights<<<KVD, 256>>>(Wk, Ak, Bk, mk, Wkh, Wkl);
    dora_weights<<<KVD, 256>>>(Wv, Av, Bv, mv, Wvh, Wvl);
    dora_weights<<<HID, 256>>>(Wo, Ao, Bo, mo, Woh, Wol);

    // 2) split x
    split_f16<<<(TOK * HID / 4 + 255) / 256, 256>>>(x, xh, xl, TOK * HID / 4);

    // 3) merged q/k/v projections (one packed launch)
    gemm_qkv<<<dim3(48, TOK / 128), 256, GEMM_SMEM>>>(
        xh, xl, Wqh, Wql, Wkh, Wkl, Wvh, Wvl, qh, ql, kh, kl, vh);

    // 4) causal attention (HMMA) -> fp16 hi/lo attention output
    flash_hmma<<<dim3(SEQ / 128, 32, 2), 256, FLASH_SMEM>>>(qh, ql, kh, kl, vh, ath, atl);

    // 5) output projection -> d_out (fp32)
    gemm_o<<<dim3(HID / 128, TOK / 128), 256, GEMM_SMEM>>>(ath, atl, Woh, Wol, (float*)d_out);
}

// round 7
// speedup vs baseline: 1.3468x; 1.1512x over previous
#include <cuda_runtime.h>
#include <cuda_fp16.h>
#include <cstdint>
#include <math.h>

#define HID 4096
#define KVD 1024
#define TOK 4096   /* B*S */
#define SEQ 2048

// ---------------- device scratch ----------------
__device__ __half g_xh[TOK * HID];
__device__ __half g_xl[TOK * HID];
__device__ __half g_Wqh[HID * HID];
__device__ __half g_Wql[HID * HID];
__device__ __half g_Wkh[KVD * HID];
__device__ __half g_Wkl[KVD * HID];
__device__ __half g_Wvh[KVD * HID];
__device__ __half g_Woh[HID * HID];
__device__ __half g_qh[TOK * HID];
__device__ __half g_ql[TOK * HID];
__device__ __half g_kh[TOK * KVD];
__device__ __half g_kl[TOK * KVD];
__device__ __half g_vh[TOK * KVD];
__device__ __half g_ath[TOK * HID];
__device__ __half g_atl[TOK * HID];

// ---------------- helpers ----------------
__device__ __forceinline__ uint32_t smem_u32(const void* p) {
    uint32_t a;
    asm("{ .reg .u64 t; cvta.to.shared.u64 t, %1; cvt.u32.u64 %0, t; }" : "=r"(a) : "l"(p));
    return a;
}
__device__ __forceinline__ void cp16(uint32_t dst, const void* src) {
    asm volatile("cp.async.cg.shared.global [%0], [%1], 16;\n" :: "r"(dst), "l"(src) : "memory");
}
#define CP_COMMIT() asm volatile("cp.async.commit_group;\n" ::: "memory")

#define LDSM4(r, a) \
    asm volatile("ldmatrix.sync.aligned.m8n8.x4.shared.b16 {%0,%1,%2,%3}, [%4];" \
                 : "=r"((r)[0]), "=r"((r)[1]), "=r"((r)[2]), "=r"((r)[3]) : "r"(a))
#define LDSM4T(r, a) \
    asm volatile("ldmatrix.sync.aligned.m8n8.x4.trans.shared.b16 {%0,%1,%2,%3}, [%4];" \
                 : "=r"((r)[0]), "=r"((r)[1]), "=r"((r)[2]), "=r"((r)[3]) : "r"(a))

#define MMA16816(d, a, b0, b1) \
    asm volatile("mma.sync.aligned.m16n8k16.row.col.f32.f16.f16.f32 " \
                 "{%0,%1,%2,%3}, {%4,%5,%6,%7}, {%8,%9}, {%0,%1,%2,%3};" \
                 : "+f"((d)[0]), "+f"((d)[1]), "+f"((d)[2]), "+f"((d)[3]) \
                 : "r"((a)[0]), "r"((a)[1]), "r"((a)[2]), "r"((a)[3]), "r"(b0), "r"(b1))

__device__ __forceinline__ uint32_t pack_f16x2(float hi_, float lo_) {
    __half2 h = __floats2half2_rn(lo_, hi_);
    return *(uint32_t*)&h;
}
__device__ __forceinline__ float2 unpack_f16x2(uint32_t u) {
    __half2 h = *(__half2*)&u;
    float2 r;
    r.x = __low2float(h);
    r.y = __high2float(h);
    return r;
}
// fast exp2 on FMA pipe (no MUFU). x <= 0 expected; rel err ~2.4e-6.
__device__ __forceinline__ float exp2p(float x) {
    x = fmaxf(x, -120.f);
    int e = __float2int_rn(x);
    float f = x - (float)e;
    float p = 1.3333558e-3f;
    p = fmaf(p, f, 9.6181291e-3f);
    p = fmaf(p, f, 5.5504109e-2f);
    p = fmaf(p, f, 2.4022651e-1f);
    p = fmaf(p, f, 6.9314718e-1f);
    p = fmaf(p, f, 1.0f);
    return p * __int_as_float((uint32_t)(e + 127) << 23);
}

// ---------------- DoRA weight materialization (all 4 weights, one launch) ----
__global__ __launch_bounds__(256) void dora_all(
    const float* __restrict__ Wq, const float* __restrict__ Aq,
    const float* __restrict__ Bq, const float* __restrict__ mq,
    const float* __restrict__ Wk, const float* __restrict__ Ak,
    const float* __restrict__ Bk, const float* __restrict__ mk,
    const float* __restrict__ Wv, const float* __restrict__ Av,
    const float* __restrict__ Bv, const float* __restrict__ mv,
    const float* __restrict__ Wo, const float* __restrict__ Ao,
    const float* __restrict__ Bo, const float* __restrict__ mo,
    __half* __restrict__ Wqh, __half* __restrict__ Wql,
    __half* __restrict__ Wkh, __half* __restrict__ Wkl,
    __half* __restrict__ Wvh, __half* __restrict__ Woh)
{
    const int bx = blockIdx.x;
    const float *W, *A, *Bm, *mvec;
    __half *Whi, *Wlo;
    int row;
    if (bx < 4096)      { W = Wq; A = Aq; Bm = Bq; mvec = mq; Whi = Wqh; Wlo = Wql; row = bx; }
    else if (bx < 5120) { W = Wk; A = Ak; Bm = Bk; mvec = mk; Whi = Wkh; Wlo = Wkl; row = bx - 4096; }
    else if (bx < 6144) { W = Wv; A = Av; Bm = Bv; mvec = mv; Whi = Wvh; Wlo = nullptr; row = bx - 5120; }
    else                { W = Wo; A = Ao; Bm = Bo; mvec = mo; Whi = Woh; Wlo = nullptr; row = bx - 6144; }

    const int tid = threadIdx.x;
    float b[8];
#pragma unroll
    for (int r = 0; r < 8; r++) b[r] = 2.0f * Bm[row * 8 + r];

    const float4* Wrow = (const float4*)(W + (size_t)row * HID);
    float4 w[4];
    float ss = 0.f;
#pragma unroll
    for (int c = 0; c < 4; c++) {
        int col4 = tid + 256 * c;
        float4 wv = Wrow[col4];
#pragma unroll
        for (int r = 0; r < 8; r++) {
            float4 av = ((const float4*)(A + (size_t)r * HID))[col4];
            wv.x += b[r] * av.x; wv.y += b[r] * av.y;
            wv.z += b[r] * av.z; wv.w += b[r] * av.w;
        }
        ss += wv.x * wv.x + wv.y * wv.y + wv.z * wv.z + wv.w * wv.w;
        w[c] = wv;
    }
#pragma unroll
    for (int off = 16; off; off >>= 1)
        ss += __shfl_xor_sync(0xffffffffu, ss, off);

    __shared__ float red[8];
    __shared__ float s_scale;
    if ((tid & 31) == 0) red[tid >> 5] = ss;
    __syncthreads();
    if (tid == 0) {
        float t = 0.f;
#pragma unroll
        for (int i = 0; i < 8; i++) t += red[i];
        s_scale = mvec[row] / (sqrtf(t) + 1e-8f);
    }
    __syncthreads();
    const float sc = s_scale;
#pragma unroll
    for (int c = 0; c < 4; c++) {
        float vv[4] = {w[c].x * sc, w[c].y * sc, w[c].z * sc, w[c].w * sc};
        size_t base = (size_t)row * HID + (tid + 256 * c) * 4;
#pragma unroll
        for (int e = 0; e < 4; e++) {
            __half h = __float2half_rn(vv[e]);
            Whi[base + e] = h;
            if (Wlo) Wlo[base + e] = __float2half_rn(vv[e] - __half2float(h));
        }
    }
}

// ---------------- fp32 -> fp16 hi/lo split (x only) ----------------
__global__ __launch_bounds__(256) void split_f16(
    const float* __restrict__ in, __half* __restrict__ hi,
    __half* __restrict__ lo, int n4)
{
    int i = blockIdx.x * 256 + threadIdx.x;
    if (i >= n4) return;
    float4 v = ((const float4*)in)[i];
    float vv[4] = {v.x, v.y, v.z, v.w};
    size_t base = (size_t)i * 4;
#pragma unroll
    for (int e = 0; e < 4; e++) {
        __half h = __float2half_rn(vv[e]);
        hi[base + e] = h;
        lo[base + e] = __float2half_rn(vv[e] - __half2float(h));
    }
}

// ---------------- HMMA mainloop: 128x128 tile, K=4096 ----------------
// terms: 3 -> ah*bh + al*bh + ah*bl ; 2 -> ah*bh + al*bh (B single fp16, Bl not loaded)
#define STRIDE_B 80
#define TILE_B   (128 * STRIDE_B)
#define STAGE_B  (4 * TILE_B)
#define GEMM_SMEM (2 * STAGE_B)          /* 81920, 2 CTAs/SM */

__device__ __forceinline__ void hmma_mainloop(
    uint32_t sb, const __half* g0, const __half* g1,
    const __half* g2, const __half* g3, int tid, float acc[2][8][4], int three)
{
    const int lane = tid & 31, wid = tid >> 5;
    const int wm = wid & 3, wn = wid >> 2;
    const int K = 4096;
    const int ldr = tid >> 2;
    const int ldc = (tid & 3) * 16;
    const int ntile = three ? 4 : 3;

    const uint32_t a_off = (uint32_t)(wm * 32 + (lane & 15)) * STRIDE_B + ((lane >> 4) * 16);
    const uint32_t b_off = (uint32_t)(wn * 64 + (((lane >> 4) << 3) + (lane & 7))) * STRIDE_B
                           + (((lane >> 3) & 1) * 16);

#define LOAD_STAGE(buf, k0) do { \
    uint32_t s0_ = sb + (buf) * STAGE_B; \
    const __half* gg_[4] = {g0 + (k0), g1 + (k0), g2 + (k0), g3 + (k0)}; \
    for (int t_ = 0; t_ < ntile; t_++) { \
        uint32_t st_ = s0_ + t_ * TILE_B; \
        _Pragma("unroll") \
        for (int p_ = 0; p_ < 2; p_++) { \
            int r_ = ldr + p_ * 64; \
            cp16(st_ + (uint32_t)r_ * STRIDE_B + ldc, \
                 (const char*)(gg_[t_] + (size_t)r_ * K) + ldc); \
        } \
    } \
    CP_COMMIT(); \
} while (0)

    LOAD_STAGE(0, 0);
    for (int ch = 0; ch < 128; ch++) {
        if (ch + 1 < 128) {
            LOAD_STAGE((ch + 1) & 1, (ch + 1) * 32);
            asm volatile("cp.async.wait_group 1;\n" ::: "memory");
        } else {
            asm volatile("cp.async.wait_group 0;\n" ::: "memory");
        }
        __syncthreads();
        const uint32_t s0 = sb + (ch & 1) * STAGE_B;
        const uint32_t sAh = s0, sAl = s0 + TILE_B;
        const uint32_t sBh = s0 + 2 * TILE_B, sBl = s0 + 3 * TILE_B;
#pragma unroll
        for (int k16 = 0; k16 < 2; k16++) {
            const uint32_t kadd = k16 * 32;
            uint32_t ah[2][4], al[2][4], bb[4][4];
            LDSM4(ah[0], sAh + a_off + kadd);
            LDSM4(ah[1], sAh + a_off + 16 * STRIDE_B + kadd);
            LDSM4(al[0], sAl + a_off + kadd);
            LDSM4(al[1], sAl + a_off + 16 * STRIDE_B + kadd);
#pragma unroll
            for (int j = 0; j < 4; j++) LDSM4(bb[j], sBh + b_off + j * 16 * STRIDE_B + kadd);
#pragma unroll
            for (int i = 0; i < 2; i++)
#pragma unroll
                for (int f = 0; f < 8; f++)
                    MMA16816(acc[i][f], ah[i], bb[f >> 1][(f & 1) * 2], bb[f >> 1][(f & 1) * 2 + 1]);
#pragma unroll
            for (int i = 0; i < 2; i++)
#pragma unroll
                for (int f = 0; f < 8; f++)
                    MMA16816(acc[i][f], al[i], bb[f >> 1][(f & 1) * 2], bb[f >> 1][(f & 1) * 2 + 1]);
            if (three) {
#pragma unroll
                for (int j = 0; j < 4; j++) LDSM4(bb[j], sBl + b_off + j * 16 * STRIDE_B + kadd);
#pragma unroll
                for (int i = 0; i < 2; i++)
#pragma unroll
                    for (int f = 0; f < 8; f++)
                        MMA16816(acc[i][f], ah[i], bb[f >> 1][(f & 1) * 2], bb[f >> 1][(f & 1) * 2 + 1]);
            }
        }
        __syncthreads();
    }
#undef LOAD_STAGE
}

// ---------------- merged QKV projection ----------------
// grid.x: [0,32)->Q (3-term), [32,40)->K (3-term), [40,48)->V (2-term)
__global__ __launch_bounds__(256, 1) void gemm_qkv(
    const __half* __restrict__ xh, const __half* __restrict__ xl,
    const __half* __restrict__ Wqh, const __half* __restrict__ Wql,
    const __half* __restrict__ Wkh, const __half* __restrict__ Wkl,
    const __half* __restrict__ Wvh,
    __half* __restrict__ qh, __half* __restrict__ ql,
    __half* __restrict__ kh, __half* __restrict__ kl,
    __half* __restrict__ vh)
{
    extern __shared__ char dsm[];
    const uint32_t sb = smem_u32(dsm);
    const int tid = threadIdx.x, lane = tid & 31, wid = tid >> 5;
    const int wm = wid & 3, wn = wid >> 2;
    const int bx = blockIdx.x;
    const int row0 = blockIdx.y << 7;
    const int K = 4096;

    const __half *Bh_, *Bl_;
    __half *Oh, *Ol;
    int N, col0, three;
    if (bx < 32) {
        Bh_ = Wqh; Bl_ = Wql; Oh = qh; Ol = ql; N = HID; col0 = bx << 7; three = 1;
    } else if (bx < 40) {
        Bh_ = Wkh; Bl_ = Wkl; Oh = kh; Ol = kl; N = KVD; col0 = (bx - 32) << 7; three = 1;
    } else {
        Bh_ = Wvh; Bl_ = Wvh; Oh = vh; Ol = nullptr; N = KVD; col0 = (bx - 40) << 7; three = 0;
    }

    float acc[2][8][4] = {};
    hmma_mainloop(sb, xh + (size_t)row0 * K, xl + (size_t)row0 * K,
                  Bh_ + (size_t)col0 * K, Bl_ + (size_t)col0 * K, tid, acc, three);

#pragma unroll
    for (int i = 0; i < 2; i++) {
        const int mrow = row0 + wm * 32 + i * 16 + (lane >> 2);
#pragma unroll
        for (int f = 0; f < 8; f++) {
            const int col = col0 + wn * 64 + f * 8 + (lane & 3) * 2;
            uint32_t h01 = pack_f16x2(acc[i][f][1], acc[i][f][0]);
            uint32_t h23 = pack_f16x2(acc[i][f][3], acc[i][f][2]);
            *(uint32_t*)&Oh[(size_t)mrow * N + col] = h01;
            *(uint32_t*)&Oh[(size_t)(mrow + 8) * N + col] = h23;
            if (Ol) {
                float2 hf0 = unpack_f16x2(h01);
                float2 hf1 = unpack_f16x2(h23);
                uint32_t l01 = pack_f16x2(acc[i][f][1] - hf0.y, acc[i][f][0] - hf0.x);
                uint32_t l23 = pack_f16x2(acc[i][f][3] - hf1.y, acc[i][f][2] - hf1.x);
                *(uint32_t*)&Ol[(size_t)mrow * N + col] = l01;
                *(uint32_t*)&Ol[(size_t)(mrow + 8) * N + col] = l23;
            }
        }
    }
}

// ---------------- output projection (2-term, fp32 out) ----------------
__global__ __launch_bounds__(256, 1) void gemm_o(
    const __half* __restrict__ Ah, const __half* __restrict__ Al,
    const __half* __restrict__ Bh,
    float* __restrict__ C)
{
    extern __shared__ char dsm[];
    const uint32_t sb = smem_u32(dsm);
    const int tid = threadIdx.x, lane = tid & 31, wid = tid >> 5;
    const int wm = wid & 3, wn = wid >> 2;
    const int row0 = blockIdx.y << 7, col0 = blockIdx.x << 7;
    const int K = 4096, N = HID;

    float acc[2][8][4] = {};
    hmma_mainloop(sb, Ah + (size_t)row0 * K, Al + (size_t)row0 * K,
                  Bh + (size_t)col0 * K, Bh + (size_t)col0 * K, tid, acc, 0);

#pragma unroll
    for (int i = 0; i < 2; i++) {
        const int mrow = row0 + wm * 32 + i * 16 + (lane >> 2);
#pragma unroll
        for (int f = 0; f < 8; f++) {
            const int col = col0 + wn * 64 + f * 8 + (lane & 3) * 2;
            float2 lo2 = {acc[i][f][0], acc[i][f][1]};
            float2 hi2 = {acc[i][f][2], acc[i][f][3]};
            *(float2*)&C[(size_t)mrow * N + col] = lo2;
            *(float2*)&C[(size_t)(mrow + 8) * N + col] = hi2;
        }
    }
}

// ---------------- HMMA causal flash attention ----------------
#define FSTR 272                 /* bytes per 128-elem fp16 row (136 elems) */
#define KV_T 17408               /* 64*FSTR */
#define KV_STAGE (3 * KV_T)      /* 52224 */
#define FLASH_SMEM (2 * 128 * FSTR + 3 * KV_STAGE)  /* 226304 */

__global__ __launch_bounds__(256, 1) void flash_hmma(
    const __half* __restrict__ qh_g, const __half* __restrict__ ql_g,
    const __half* __restrict__ kh_g, const __half* __restrict__ kl_g,
    const __half* __restrict__ vh_g,
    __half* __restrict__ oh_g, __half* __restrict__ ol_g)
{
    extern __shared__ char dsm[];
    const uint32_t sq = smem_u32(dsm);
    const uint32_t sb = sq + 2 * 128 * FSTR;
    const int tid = threadIdx.x, lane = tid & 31, w = tid >> 5;
    const int qt = (int)gridDim.x - 1 - (int)blockIdx.x;
    const int h = blockIdx.y, b = blockIdx.z;
    const int kvh = h >> 2;
    const int gr = qt * 128;
    const int nkt = 2 * qt + 2;

    {
        const __half* srcs[2] = {qh_g, ql_g};
#pragma unroll
        for (int t = 0; t < 2; t++) {
            uint32_t sdst = sq + t * (128 * FSTR);
            const __half* src = srcs[t] + ((size_t)(b * SEQ + gr)) * HID + h * 128;
#pragma unroll
            for (int i = 0; i < 8; i++) {
                int idx = tid + i * 256;
                int r = idx >> 4, c = idx & 15;
                cp16(sdst + (uint32_t)r * FSTR + c * 16,
                     (const char*)(src + (size_t)r * HID) + c * 16);
            }
        }
        CP_COMMIT();
        asm volatile("cp.async.wait_group 0;\n" ::: "memory");
        __syncthreads();
    }
    uint32_t qhf[8][4], qlf[8][4];
    {
        const uint32_t qoff = (uint32_t)(w * 16 + (lane & 15)) * FSTR + ((lane >> 4) * 16);
#pragma unroll
        for (int kf = 0; kf < 8; kf++) {
            LDSM4(qhf[kf], sq + qoff + kf * 32);
            LDSM4(qlf[kf], sq + 128 * FSTR + qoff + kf * 32);
        }
    }
    __syncthreads();

    float o[16][4];
#pragma unroll
    for (int i = 0; i < 16; i++) { o[i][0] = 0.f; o[i][1] = 0.f; o[i][2] = 0.f; o[i][3] = 0.f; }
    float m0 = -1e5f, m1 = -1e5f, l0 = 0.f, l1 = 0.f;

    const uint32_t koff = (uint32_t)(((lane >> 4) << 3) + (lane & 7)) * FSTR + (((lane >> 3) & 1) * 16);
    const uint32_t voff = (uint32_t)((((lane >> 3) & 1) << 3) + (lane & 7)) * FSTR + ((lane >> 4) * 16);

    const __half* kh_p = kh_g + ((size_t)(b * SEQ)) * KVD + kvh * 128;
    const __half* kl_p = kl_g + ((size_t)(b * SEQ)) * KVD + kvh * 128;
    const __half* vh_p = vh_g + ((size_t)(b * SEQ)) * KVD + kvh * 128;

#define LOADKV(kt_, buf_) do { \
    uint32_t s0_ = sb + (buf_) * KV_STAGE; \
    const __half* gs_[3] = { \
        kh_p + (size_t)(kt_) * 64 * KVD, kl_p + (size_t)(kt_) * 64 * KVD, \
        vh_p + (size_t)(kt_) * 64 * KVD}; \
    _Pragma("unroll") \
    for (int t_ = 0; t_ < 3; t_++) { \
        _Pragma("unroll") \
        for (int i_ = 0; i_ < 4; i_++) { \
            int idx_ = tid + i_ * 256; \
            int r_ = idx_ >> 4, c_ = idx_ & 15; \
            cp16(s0_ + t_ * KV_T + (uint32_t)r_ * FSTR + c_ * 16, \
                 (const char*)(gs_[t_] + (size_t)r_ * KVD) + c_ * 16); \
        } \
    } \
    CP_COMMIT(); \
} while (0)

    LOADKV(0, 0);
    LOADKV(1, 1);
    const float Cs = 0.08838834764831845f * 1.4426950408889634f;

    int st = 0;
    int st2 = 2;
    for (int kt = 0; kt < nkt; kt++) {
        if (kt + 2 < nkt) {
            asm volatile("cp.async.wait_group 1;\n" ::: "memory");
        } else {
            asm volatile("cp.async.wait_group 0;\n" ::: "memory");
        }
        __syncthreads();
        if (kt + 2 < nkt) LOADKV(kt + 2, st2);

        const uint32_t sKh = sb + st * KV_STAGE;
        const uint32_t sKl = sKh + KV_T, sVh = sKh + 2 * KV_T;

        float s[8][4];
#pragma unroll
        for (int i = 0; i < 8; i++) { s[i][0] = 0.f; s[i][1] = 0.f; s[i][2] = 0.f; s[i][3] = 0.f; }
#pragma unroll
        for (int kf = 0; kf < 8; kf++) {
#pragma unroll
            for (int nb = 0; nb < 4; nb++) {
                uint32_t bh[4], bl[4];
                LDSM4(bh, sKh + koff + nb * (16 * FSTR) + kf * 32);
                MMA16816(s[2 * nb], qhf[kf], bh[0], bh[1]);
                MMA16816(s[2 * nb + 1], qhf[kf], bh[2], bh[3]);
                MMA16816(s[2 * nb], qlf[kf], bh[0], bh[1]);
                MMA16816(s[2 * nb + 1], qlf[kf], bh[2], bh[3]);
                LDSM4(bl, sKl + koff + nb * (16 * FSTR) + kf * 32);
                MMA16816(s[2 * nb], qhf[kf], bl[0], bl[1]);
                MMA16816(s[2 * nb + 1], qhf[kf], bl[2], bl[3]);
            }
        }
#pragma unroll
        for (int nf = 0; nf < 8; nf++) {
            s[nf][0] *= Cs; s[nf][1] *= Cs; s[nf][2] *= Cs; s[nf][3] *= Cs;
        }
        if (kt >= nkt - 2) {
            const int r0 = gr + w * 16 + (lane >> 2);
            const int c0 = kt * 64 + 2 * (lane & 3);
#pragma unroll
            for (int nf = 0; nf < 8; nf++) {
#pragma unroll
                for (int j = 0; j < 4; j++) {
                    int col = c0 + nf * 8 + (j & 1);
                    int row = r0 + (j >> 1) * 8;
                    if (col > row) s[nf][j] = -1e5f;
                }
            }
        }
        float mx0 = -1e30f, mx1 = -1e30f;
#pragma unroll
        for (int nf = 0; nf < 8; nf++) {
            mx0 = fmaxf(mx0, fmaxf(s[nf][0], s[nf][1]));
            mx1 = fmaxf(mx1, fmaxf(s[nf][2], s[nf][3]));
        }
        mx0 = fmaxf(mx0, __shfl_xor_sync(0xffffffffu, mx0, 1));
        mx0 = fmaxf(mx0, __shfl_xor_sync(0xffffffffu, mx0, 2));
        mx1 = fmaxf(mx1, __shfl_xor_sync(0xffffffffu, mx1, 1));
        mx1 = fmaxf(mx1, __shfl_xor_sync(0xffffffffu, mx1, 2));
        const float mn0 = fmaxf(m0, mx0), mn1 = fmaxf(m1, mx1);
        const float cr0 = exp2p(m0 - mn0), cr1 = exp2p(m1 - mn1);
        m0 = mn0; m1 = mn1;
        float rs0 = 0.f, rs1 = 0.f;
#pragma unroll
        for (int nf = 0; nf < 8; nf++) {
            float p0 = exp2p(s[nf][0] - mn0), p1 = exp2p(s[nf][1] - mn0);
            float p2 = exp2p(s[nf][2] - mn1), p3 = exp2p(s[nf][3] - mn1);
            s[nf][0] = p0; s[nf][1] = p1; s[nf][2] = p2; s[nf][3] = p3;
            rs0 += p0 + p1; rs1 += p2 + p3;
        }
        rs0 += __shfl_xor_sync(0xffffffffu, rs0, 1);
        rs0 += __shfl_xor_sync(0xffffffffu, rs0, 2);
        rs1 += __shfl_xor_sync(0xffffffffu, rs1, 1);
        rs1 += __shfl_xor_sync(0xffffffffu, rs1, 2);
        l0 = l0 * cr0 + rs0;
        l1 = l1 * cr1 + rs1;
#pragma unroll
        for (int nf = 0; nf < 16; nf++) {
            o[nf][0] *= cr0; o[nf][1] *= cr0; o[nf][2] *= cr1; o[nf][3] *= cr1;
        }
#pragma unroll
        for (int kb = 0; kb < 4; kb++) {
            uint32_t ph[4], pl[4];
#pragma unroll
            for (int q2 = 0; q2 < 2; q2++) {
                const int nf = 2 * kb + q2;
                uint32_t h01 = pack_f16x2(s[nf][1], s[nf][0]);
                float2 f01 = unpack_f16x2(h01);
                uint32_t l01 = pack_f16x2(s[nf][1] - f01.y, s[nf][0] - f01.x);
                uint32_t h23 = pack_f16x2(s[nf][3], s[nf][2]);
                float2 f23 = unpack_f16x2(h23);
                uint32_t l23 = pack_f16x2(s[nf][3] - f23.y, s[nf][2] - f23.x);
                ph[2 * q2] = h01; ph[2 * q2 + 1] = h23;
                pl[2 * q2] = l01; pl[2 * q2 + 1] = l23;
            }
#pragma unroll
            for (int ng = 0; ng < 8; ng++) {
                uint32_t vv[4];
                LDSM4T(vv, sVh + voff + kb * (16 * FSTR) + ng * 32);
                MMA16816(o[2 * ng], ph, vv[0], vv[1]);
                MMA16816(o[2 * ng + 1], ph, vv[2], vv[3]);
                MMA16816(o[2 * ng], pl, vv[0], vv[1]);
                MMA16816(o[2 * ng + 1], pl, vv[2], vv[3]);
            }
        }
        st = (st == 2) ? 0 : st + 1;
        st2 = (st2 == 2) ? 0 : st2 + 1;
    }
#undef LOADKV

    const float inv0 = 1.f / l0, inv1 = 1.f / l1;
    const size_t row0_ = (size_t)(b * SEQ + gr + w * 16 + (lane >> 2));
    const int colb = h * 128 + 2 * (lane & 3);
#pragma unroll
    for (int nf = 0; nf < 16; nf++) {
        const int col = colb + nf * 8;
        float v0 = o[nf][0] * inv0, v1 = o[nf][1] * inv0;
        float v2 = o[nf][2] * inv1, v3 = o[nf][3] * inv1;
        uint32_t h01 = pack_f16x2(v1, v0);
        float2 f01 = unpack_f16x2(h01);
        uint32_t l01 = pack_f16x2(v1 - f01.y, v0 - f01.x);
        uint32_t h23 = pack_f16x2(v3, v2);
        float2 f23 = unpack_f16x2(h23);
        uint32_t l23 = pack_f16x2(v3 - f23.y, v2 - f23.x);
        *(uint32_t*)&oh_g[row0_ * HID + col] = h01;
        *(uint32_t*)&ol_g[row0_ * HID + col] = l01;
        *(uint32_t*)&oh_g[(row0_ + 8) * HID + col] = h23;
        *(uint32_t*)&ol_g[(row0_ + 8) * HID + col] = l23;
    }
}

// ---------------- launch ----------------
extern "C" void kernel_launch(void* const* d_in, const int* in_sizes, int n_in,
                              void* d_out, int out_size)
{
    const float* x  = (const float*)d_in[0];
    const float* Wq = (const float*)d_in[2];
    const float* Aq = (const float*)d_in[3];
    const float* Bq = (const float*)d_in[4];
    const float* mq = (const float*)d_in[5];
    const float* Wk = (const float*)d_in[6];
    const float* Ak = (const float*)d_in[7];
    const float* Bk = (const float*)d_in[8];
    const float* mk = (const float*)d_in[9];
    const float* Wv = (const float*)d_in[10];
    const float* Av = (const float*)d_in[11];
    const float* Bv = (const float*)d_in[12];
    const float* mv = (const float*)d_in[13];
    const float* Wo = (const float*)d_in[14];
    const float* Ao = (const float*)d_in[15];
    const float* Bo = (const float*)d_in[16];
    const float* mo = (const float*)d_in[17];

    __half *xh, *xl, *Wqh, *Wql, *Wkh, *Wkl, *Wvh, *Woh;
    __half *qh, *ql, *kh, *kl, *vh, *ath, *atl;
    cudaGetSymbolAddress((void**)&xh, g_xh);   cudaGetSymbolAddress((void**)&xl, g_xl);
    cudaGetSymbolAddress((void**)&Wqh, g_Wqh); cudaGetSymbolAddress((void**)&Wql, g_Wql);
    cudaGetSymbolAddress((void**)&Wkh, g_Wkh); cudaGetSymbolAddress((void**)&Wkl, g_Wkl);
    cudaGetSymbolAddress((void**)&Wvh, g_Wvh); cudaGetSymbolAddress((void**)&Woh, g_Woh);
    cudaGetSymbolAddress((void**)&qh, g_qh);   cudaGetSymbolAddress((void**)&ql, g_ql);
    cudaGetSymbolAddress((void**)&kh, g_kh);   cudaGetSymbolAddress((void**)&kl, g_kl);
    cudaGetSymbolAddress((void**)&vh, g_vh);
    cudaGetSymbolAddress((void**)&ath, g_ath); cudaGetSymbolAddress((void**)&atl, g_atl);

    cudaFuncSetAttribute(gemm_qkv, cudaFuncAttributeMaxDynamicSharedMemorySize, GEMM_SMEM);
    cudaFuncSetAttribute(gemm_o, cudaFuncAttributeMaxDynamicSharedMemorySize, GEMM_SMEM);
    cudaFuncSetAttribute(flash_hmma, cudaFuncAttributeMaxDynamicSharedMemorySize, FLASH_SMEM);

    // 1) DoRA effective weights (one launch, fp16 hi/lo; Wv/Wo hi only)
    dora_all<<<10240, 256>>>(Wq, Aq, Bq, mq, Wk, Ak, Bk, mk,
                             Wv, Av, Bv, mv, Wo, Ao, Bo, mo,
                             Wqh, Wql, Wkh, Wkl, Wvh, Woh);

    // 2) split x
    split_f16<<<(TOK * HID / 4 + 255) / 256, 256>>>(x, xh, xl, TOK * HID / 4);

    // 3) merged q/k/v projections
    gemm_qkv<<<dim3(48, TOK / 128), 256, GEMM_SMEM>>>(
        xh, xl, Wqh, Wql, Wkh, Wkl, Wvh, qh, ql, kh, kl, vh);

    // 4) causal attention (HMMA) -> fp16 hi/lo attention output
    flash_hmma<<<dim3(SEQ / 128, 32, 2), 256, FLASH_SMEM>>>(qh, ql, kh, kl, vh, ath, atl);

    // 5) output projection (2-term) -> d_out (fp32)
    gemm_o<<<dim3(HID / 128, TOK / 128), 256, GEMM_SMEM>>>(ath, atl, Woh, (float*)d_out);
}

// round 8
// speedup vs baseline: 1.4283x; 1.0605x over previous
#include <cuda_runtime.h>
#include <cuda_fp16.h>
#include <cstdint>
#include <math.h>

#define HID 4096
#define KVD 1024
#define TOK 4096   /* B*S */
#define SEQ 2048

// ---------------- device scratch ----------------
__device__ __half g_xh[TOK * HID];
__device__ __half g_xl[TOK * HID];
__device__ __half g_Wqh[HID * HID];
__device__ __half g_Wql[HID * HID];
__device__ __half g_Wkh[KVD * HID];
__device__ __half g_Wvh[KVD * HID];
__device__ __half g_Woh[HID * HID];
__device__ __half g_qh[TOK * HID];
__device__ __half g_ql[TOK * HID];
__device__ __half g_kh[TOK * KVD];
__device__ __half g_vh[TOK * KVD];
__device__ __half g_ath[TOK * HID];
__device__ __half g_atl[TOK * HID];

// ---------------- helpers ----------------
__device__ __forceinline__ uint32_t smem_u32(const void* p) {
    uint32_t a;
    asm("{ .reg .u64 t; cvta.to.shared.u64 t, %1; cvt.u32.u64 %0, t; }" : "=r"(a) : "l"(p));
    return a;
}
__device__ __forceinline__ void cp16(uint32_t dst, const void* src) {
    asm volatile("cp.async.cg.shared.global [%0], [%1], 16;\n" :: "r"(dst), "l"(src) : "memory");
}
#define CP_COMMIT() asm volatile("cp.async.commit_group;\n" ::: "memory")

#define LDSM4(r, a) \
    asm volatile("ldmatrix.sync.aligned.m8n8.x4.shared.b16 {%0,%1,%2,%3}, [%4];" \
                 : "=r"((r)[0]), "=r"((r)[1]), "=r"((r)[2]), "=r"((r)[3]) : "r"(a))
#define LDSM4T(r, a) \
    asm volatile("ldmatrix.sync.aligned.m8n8.x4.trans.shared.b16 {%0,%1,%2,%3}, [%4];" \
                 : "=r"((r)[0]), "=r"((r)[1]), "=r"((r)[2]), "=r"((r)[3]) : "r"(a))

#define MMA16816(d, a, b0, b1) \
    asm volatile("mma.sync.aligned.m16n8k16.row.col.f32.f16.f16.f32 " \
                 "{%0,%1,%2,%3}, {%4,%5,%6,%7}, {%8,%9}, {%0,%1,%2,%3};" \
                 : "+f"((d)[0]), "+f"((d)[1]), "+f"((d)[2]), "+f"((d)[3]) \
                 : "r"((a)[0]), "r"((a)[1]), "r"((a)[2]), "r"((a)[3]), "r"(b0), "r"(b1))

__device__ __forceinline__ uint32_t pack_f16x2(float hi_, float lo_) {
    __half2 h = __floats2half2_rn(lo_, hi_);
    return *(uint32_t*)&h;
}
__device__ __forceinline__ float2 unpack_f16x2(uint32_t u) {
    __half2 h = *(__half2*)&u;
    float2 r;
    r.x = __low2float(h);
    r.y = __high2float(h);
    return r;
}
// fast exp2 on FMA pipe (no MUFU). x <= 0 expected; rel err ~2.4e-6.
__device__ __forceinline__ float exp2p(float x) {
    x = fmaxf(x, -120.f);
    int e = __float2int_rn(x);
    float f = x - (float)e;
    float p = 1.3333558e-3f;
    p = fmaf(p, f, 9.6181291e-3f);
    p = fmaf(p, f, 5.5504109e-2f);
    p = fmaf(p, f, 2.4022651e-1f);
    p = fmaf(p, f, 6.9314718e-1f);
    p = fmaf(p, f, 1.0f);
    return p * __int_as_float((uint32_t)(e + 127) << 23);
}

// ---------------- DoRA weight materialization (all 4 weights, one launch) ----
__global__ __launch_bounds__(256) void dora_all(
    const float* __restrict__ Wq, const float* __restrict__ Aq,
    const float* __restrict__ Bq, const float* __restrict__ mq,
    const float* __restrict__ Wk, const float* __restrict__ Ak,
    const float* __restrict__ Bk, const float* __restrict__ mk,
    const float* __restrict__ Wv, const float* __restrict__ Av,
    const float* __restrict__ Bv, const float* __restrict__ mv,
    const float* __restrict__ Wo, const float* __restrict__ Ao,
    const float* __restrict__ Bo, const float* __restrict__ mo,
    __half* __restrict__ Wqh, __half* __restrict__ Wql,
    __half* __restrict__ Wkh, __half* __restrict__ Wvh,
    __half* __restrict__ Woh)
{
    const int bx = blockIdx.x;
    const float *W, *A, *Bm, *mvec;
    __half *Whi, *Wlo;
    int row;
    if (bx < 4096)      { W = Wq; A = Aq; Bm = Bq; mvec = mq; Whi = Wqh; Wlo = Wql; row = bx; }
    else if (bx < 5120) { W = Wk; A = Ak; Bm = Bk; mvec = mk; Whi = Wkh; Wlo = nullptr; row = bx - 4096; }
    else if (bx < 6144) { W = Wv; A = Av; Bm = Bv; mvec = mv; Whi = Wvh; Wlo = nullptr; row = bx - 5120; }
    else                { W = Wo; A = Ao; Bm = Bo; mvec = mo; Whi = Woh; Wlo = nullptr; row = bx - 6144; }

    const int tid = threadIdx.x;
    float b[8];
#pragma unroll
    for (int r = 0; r < 8; r++) b[r] = 2.0f * Bm[row * 8 + r];

    const float4* Wrow = (const float4*)(W + (size_t)row * HID);
    float4 w[4];
    float ss = 0.f;
#pragma unroll
    for (int c = 0; c < 4; c++) {
        int col4 = tid + 256 * c;
        float4 wv = Wrow[col4];
#pragma unroll
        for (int r = 0; r < 8; r++) {
            float4 av = ((const float4*)(A + (size_t)r * HID))[col4];
            wv.x += b[r] * av.x; wv.y += b[r] * av.y;
            wv.z += b[r] * av.z; wv.w += b[r] * av.w;
        }
        ss += wv.x * wv.x + wv.y * wv.y + wv.z * wv.z + wv.w * wv.w;
        w[c] = wv;
    }
#pragma unroll
    for (int off = 16; off; off >>= 1)
        ss += __shfl_xor_sync(0xffffffffu, ss, off);

    __shared__ float red[8];
    __shared__ float s_scale;
    if ((tid & 31) == 0) red[tid >> 5] = ss;
    __syncthreads();
    if (tid == 0) {
        float t = 0.f;
#pragma unroll
        for (int i = 0; i < 8; i++) t += red[i];
        s_scale = mvec[row] / (sqrtf(t) + 1e-8f);
    }
    __syncthreads();
    const float sc = s_scale;
#pragma unroll
    for (int c = 0; c < 4; c++) {
        float vv[4] = {w[c].x * sc, w[c].y * sc, w[c].z * sc, w[c].w * sc};
        size_t base = (size_t)row * HID + (tid + 256 * c) * 4;
#pragma unroll
        for (int e = 0; e < 4; e++) {
            __half h = __float2half_rn(vv[e]);
            Whi[base + e] = h;
            if (Wlo) Wlo[base + e] = __float2half_rn(vv[e] - __half2float(h));
        }
    }
}

// ---------------- fp32 -> fp16 hi/lo split (x only) ----------------
__global__ __launch_bounds__(256) void split_f16(
    const float* __restrict__ in, __half* __restrict__ hi,
    __half* __restrict__ lo, int n4)
{
    int i = blockIdx.x * 256 + threadIdx.x;
    if (i >= n4) return;
    float4 v = ((const float4*)in)[i];
    float vv[4] = {v.x, v.y, v.z, v.w};
    size_t base = (size_t)i * 4;
#pragma unroll
    for (int e = 0; e < 4; e++) {
        __half h = __float2half_rn(vv[e]);
        hi[base + e] = h;
        lo[base + e] = __float2half_rn(vv[e] - __half2float(h));
    }
}

// ---------------- HMMA mainloop: 128x128 tile, K=4096 ----------------
// terms: 3 -> ah*bh + al*bh + ah*bl ; 2 -> ah*bh + al*bh (B single fp16)
#define STRIDE_B 80
#define TILE_B   (128 * STRIDE_B)
#define STAGE_B  (4 * TILE_B)
#define GEMM_SMEM (2 * STAGE_B)          /* 81920, 2 CTAs/SM */

__device__ __forceinline__ void hmma_mainloop(
    uint32_t sb, const __half* g0, const __half* g1,
    const __half* g2, const __half* g3, int tid, float acc[2][8][4], int three)
{
    const int lane = tid & 31, wid = tid >> 5;
    const int wm = wid & 3, wn = wid >> 2;
    const int K = 4096;
    const int ldr = tid >> 2;
    const int ldc = (tid & 3) * 16;
    const int ntile = three ? 4 : 3;

    const uint32_t a_off = (uint32_t)(wm * 32 + (lane & 15)) * STRIDE_B + ((lane >> 4) * 16);
    const uint32_t b_off = (uint32_t)(wn * 64 + (((lane >> 4) << 3) + (lane & 7))) * STRIDE_B
                           + (((lane >> 3) & 1) * 16);

#define LOAD_STAGE(buf, k0) do { \
    uint32_t s0_ = sb + (buf) * STAGE_B; \
    const __half* gg_[4] = {g0 + (k0), g1 + (k0), g2 + (k0), g3 + (k0)}; \
    for (int t_ = 0; t_ < ntile; t_++) { \
        uint32_t st_ = s0_ + t_ * TILE_B; \
        _Pragma("unroll") \
        for (int p_ = 0; p_ < 2; p_++) { \
            int r_ = ldr + p_ * 64; \
            cp16(st_ + (uint32_t)r_ * STRIDE_B + ldc, \
                 (const char*)(gg_[t_] + (size_t)r_ * K) + ldc); \
        } \
    } \
    CP_COMMIT(); \
} while (0)

    LOAD_STAGE(0, 0);
    for (int ch = 0; ch < 128; ch++) {
        if (ch + 1 < 128) {
            LOAD_STAGE((ch + 1) & 1, (ch + 1) * 32);
            asm volatile("cp.async.wait_group 1;\n" ::: "memory");
        } else {
            asm volatile("cp.async.wait_group 0;\n" ::: "memory");
        }
        __syncthreads();
        const uint32_t s0 = sb + (ch & 1) * STAGE_B;
        const uint32_t sAh = s0, sAl = s0 + TILE_B;
        const uint32_t sBh = s0 + 2 * TILE_B, sBl = s0 + 3 * TILE_B;
#pragma unroll
        for (int k16 = 0; k16 < 2; k16++) {
            const uint32_t kadd = k16 * 32;
            uint32_t ah[2][4], al[2][4], bb[4][4];
            LDSM4(ah[0], sAh + a_off + kadd);
            LDSM4(ah[1], sAh + a_off + 16 * STRIDE_B + kadd);
            LDSM4(al[0], sAl + a_off + kadd);
            LDSM4(al[1], sAl + a_off + 16 * STRIDE_B + kadd);
#pragma unroll
            for (int j = 0; j < 4; j++) LDSM4(bb[j], sBh + b_off + j * 16 * STRIDE_B + kadd);
#pragma unroll
            for (int i = 0; i < 2; i++)
#pragma unroll
                for (int f = 0; f < 8; f++)
                    MMA16816(acc[i][f], ah[i], bb[f >> 1][(f & 1) * 2], bb[f >> 1][(f & 1) * 2 + 1]);
#pragma unroll
            for (int i = 0; i < 2; i++)
#pragma unroll
                for (int f = 0; f < 8; f++)
                    MMA16816(acc[i][f], al[i], bb[f >> 1][(f & 1) * 2], bb[f >> 1][(f & 1) * 2 + 1]);
            if (three) {
#pragma unroll
                for (int j = 0; j < 4; j++) LDSM4(bb[j], sBl + b_off + j * 16 * STRIDE_B + kadd);
#pragma unroll
                for (int i = 0; i < 2; i++)
#pragma unroll
                    for (int f = 0; f < 8; f++)
                        MMA16816(acc[i][f], ah[i], bb[f >> 1][(f & 1) * 2], bb[f >> 1][(f & 1) * 2 + 1]);
            }
        }
        __syncthreads();
    }
#undef LOAD_STAGE
}

// ---------------- merged QKV projection ----------------
// grid.x: [0,32)->Q (3-term, hi/lo out), [32,40)->K (2-term, hi out),
//         [40,48)->V (2-term, hi out)
__global__ __launch_bounds__(256, 1) void gemm_qkv(
    const __half* __restrict__ xh, const __half* __restrict__ xl,
    const __half* __restrict__ Wqh, const __half* __restrict__ Wql,
    const __half* __restrict__ Wkh, const __half* __restrict__ Wvh,
    __half* __restrict__ qh, __half* __restrict__ ql,
    __half* __restrict__ kh, __half* __restrict__ vh)
{
    extern __shared__ char dsm[];
    const uint32_t sb = smem_u32(dsm);
    const int tid = threadIdx.x, lane = tid & 31, wid = tid >> 5;
    const int wm = wid & 3, wn = wid >> 2;
    const int bx = blockIdx.x;
    const int row0 = blockIdx.y << 7;
    const int K = 4096;

    const __half *Bh_, *Bl_;
    __half *Oh, *Ol;
    int N, col0, three;
    if (bx < 32) {
        Bh_ = Wqh; Bl_ = Wql; Oh = qh; Ol = ql; N = HID; col0 = bx << 7; three = 1;
    } else if (bx < 40) {
        Bh_ = Wkh; Bl_ = Wkh; Oh = kh; Ol = nullptr; N = KVD; col0 = (bx - 32) << 7; three = 0;
    } else {
        Bh_ = Wvh; Bl_ = Wvh; Oh = vh; Ol = nullptr; N = KVD; col0 = (bx - 40) << 7; three = 0;
    }

    float acc[2][8][4] = {};
    hmma_mainloop(sb, xh + (size_t)row0 * K, xl + (size_t)row0 * K,
                  Bh_ + (size_t)col0 * K, Bl_ + (size_t)col0 * K, tid, acc, three);

#pragma unroll
    for (int i = 0; i < 2; i++) {
        const int mrow = row0 + wm * 32 + i * 16 + (lane >> 2);
#pragma unroll
        for (int f = 0; f < 8; f++) {
            const int col = col0 + wn * 64 + f * 8 + (lane & 3) * 2;
            uint32_t h01 = pack_f16x2(acc[i][f][1], acc[i][f][0]);
            uint32_t h23 = pack_f16x2(acc[i][f][3], acc[i][f][2]);
            *(uint32_t*)&Oh[(size_t)mrow * N + col] = h01;
            *(uint32_t*)&Oh[(size_t)(mrow + 8) * N + col] = h23;
            if (Ol) {
                float2 hf0 = unpack_f16x2(h01);
                float2 hf1 = unpack_f16x2(h23);
                uint32_t l01 = pack_f16x2(acc[i][f][1] - hf0.y, acc[i][f][0] - hf0.x);
                uint32_t l23 = pack_f16x2(acc[i][f][3] - hf1.y, acc[i][f][2] - hf1.x);
                *(uint32_t*)&Ol[(size_t)mrow * N + col] = l01;
                *(uint32_t*)&Ol[(size_t)(mrow + 8) * N + col] = l23;
            }
        }
    }
}

// ---------------- output projection (2-term, fp32 out) ----------------
__global__ __launch_bounds__(256, 1) void gemm_o(
    const __half* __restrict__ Ah, const __half* __restrict__ Al,
    const __half* __restrict__ Bh,
    float* __restrict__ C)
{
    extern __shared__ char dsm[];
    const uint32_t sb = smem_u32(dsm);
    const int tid = threadIdx.x, lane = tid & 31, wid = tid >> 5;
    const int wm = wid & 3, wn = wid >> 2;
    const int row0 = blockIdx.y << 7, col0 = blockIdx.x << 7;
    const int K = 4096, N = HID;

    float acc[2][8][4] = {};
    hmma_mainloop(sb, Ah + (size_t)row0 * K, Al + (size_t)row0 * K,
                  Bh + (size_t)col0 * K, Bh + (size_t)col0 * K, tid, acc, 0);

#pragma unroll
    for (int i = 0; i < 2; i++) {
        const int mrow = row0 + wm * 32 + i * 16 + (lane >> 2);
#pragma unroll
        for (int f = 0; f < 8; f++) {
            const int col = col0 + wn * 64 + f * 8 + (lane & 3) * 2;
            float2 lo2 = {acc[i][f][0], acc[i][f][1]};
            float2 hi2 = {acc[i][f][2], acc[i][f][3]};
            *(float2*)&C[(size_t)mrow * N + col] = lo2;
            *(float2*)&C[(size_t)(mrow + 8) * N + col] = hi2;
        }
    }
}

// ---------------- HMMA causal flash attention ----------------
// CTA: 128 q-rows (8 warps x 16 rows), key tiles of 64, D=128.
// QK 2-term (q hi/lo x k single); PV 2-term (P hi/lo x v single).
// KV ring (3 stages of {kh, vh}) REUSES the Q staging region — Q is
// register-resident before the first KV load.
#define FSTR 272                 /* bytes per 128-elem fp16 row (136 elems) */
#define KV_T 17408               /* 64*FSTR */
#define KV_STAGE (2 * KV_T)      /* 34816 */
#define FLASH_SMEM (3 * KV_STAGE) /* 104448 >= Q staging 69632 */

__global__ __launch_bounds__(256, 1) void flash_hmma(
    const __half* __restrict__ qh_g, const __half* __restrict__ ql_g,
    const __half* __restrict__ kh_g, const __half* __restrict__ vh_g,
    __half* __restrict__ oh_g, __half* __restrict__ ol_g)
{
    extern __shared__ char dsm[];
    const uint32_t sq = smem_u32(dsm);
    const uint32_t sb = sq;                    // KV ring reuses Q region
    const int tid = threadIdx.x, lane = tid & 31, w = tid >> 5;
    const int qt = (int)gridDim.x - 1 - (int)blockIdx.x;
    const int h = blockIdx.y, b = blockIdx.z;
    const int kvh = h >> 2;
    const int gr = qt * 128;
    const int nkt = 2 * qt + 2;

    // ---- stage Q (hi/lo) into smem, build A-frags in registers
    {
        const __half* srcs[2] = {qh_g, ql_g};
#pragma unroll
        for (int t = 0; t < 2; t++) {
            uint32_t sdst = sq + t * (128 * FSTR);
            const __half* src = srcs[t] + ((size_t)(b * SEQ + gr)) * HID + h * 128;
#pragma unroll
            for (int i = 0; i < 8; i++) {
                int idx = tid + i * 256;
                int r = idx >> 4, c = idx & 15;
                cp16(sdst + (uint32_t)r * FSTR + c * 16,
                     (const char*)(src + (size_t)r * HID) + c * 16);
            }
        }
        CP_COMMIT();
        asm volatile("cp.async.wait_group 0;\n" ::: "memory");
        __syncthreads();
    }
    uint32_t qhf[8][4], qlf[8][4];
    {
        const uint32_t qoff = (uint32_t)(w * 16 + (lane & 15)) * FSTR + ((lane >> 4) * 16);
#pragma unroll
        for (int kf = 0; kf < 8; kf++) {
            LDSM4(qhf[kf], sq + qoff + kf * 32);
            LDSM4(qlf[kf], sq + 128 * FSTR + qoff + kf * 32);
        }
    }
    __syncthreads();   // Q smem free; ring may overwrite

    float o[16][4];
#pragma unroll
    for (int i = 0; i < 16; i++) { o[i][0] = 0.f; o[i][1] = 0.f; o[i][2] = 0.f; o[i][3] = 0.f; }
    float m0 = -1e5f, m1 = -1e5f, l0 = 0.f, l1 = 0.f;

    const uint32_t koff = (uint32_t)(((lane >> 4) << 3) + (lane & 7)) * FSTR + (((lane >> 3) & 1) * 16);
    const uint32_t voff = (uint32_t)((((lane >> 3) & 1) << 3) + (lane & 7)) * FSTR + ((lane >> 4) * 16);

    const __half* kh_p = kh_g + ((size_t)(b * SEQ)) * KVD + kvh * 128;
    const __half* vh_p = vh_g + ((size_t)(b * SEQ)) * KVD + kvh * 128;

#define LOADKV(kt_, buf_) do { \
    uint32_t s0_ = sb + (buf_) * KV_STAGE; \
    const __half* gs_[2] = { \
        kh_p + (size_t)(kt_) * 64 * KVD, vh_p + (size_t)(kt_) * 64 * KVD}; \
    _Pragma("unroll") \
    for (int t_ = 0; t_ < 2; t_++) { \
        _Pragma("unroll") \
        for (int i_ = 0; i_ < 4; i_++) { \
            int idx_ = tid + i_ * 256; \
            int r_ = idx_ >> 4, c_ = idx_ & 15; \
            cp16(s0_ + t_ * KV_T + (uint32_t)r_ * FSTR + c_ * 16, \
                 (const char*)(gs_[t_] + (size_t)r_ * KVD) + c_ * 16); \
        } \
    } \
    CP_COMMIT(); \
} while (0)

    LOADKV(0, 0);
    LOADKV(1, 1);
    const float Cs = 0.08838834764831845f * 1.4426950408889634f;

    int st = 0;
    int st2 = 2;
    for (int kt = 0; kt < nkt; kt++) {
        if (kt + 2 < nkt) {
            asm volatile("cp.async.wait_group 1;\n" ::: "memory");
        } else {
            asm volatile("cp.async.wait_group 0;\n" ::: "memory");
        }
        __syncthreads();
        if (kt + 2 < nkt) LOADKV(kt + 2, st2);

        const uint32_t sKh = sb + st * KV_STAGE;
        const uint32_t sVh = sKh + KV_T;

        // ---- QK^T (2-term: qh,ql x kh)
        float s[8][4];
#pragma unroll
        for (int i = 0; i < 8; i++) { s[i][0] = 0.f; s[i][1] = 0.f; s[i][2] = 0.f; s[i][3] = 0.f; }
#pragma unroll
        for (int kf = 0; kf < 8; kf++) {
#pragma unroll
            for (int nb = 0; nb < 4; nb++) {
                uint32_t bh[4];
                LDSM4(bh, sKh + koff + nb * (16 * FSTR) + kf * 32);
                MMA16816(s[2 * nb], qhf[kf], bh[0], bh[1]);
                MMA16816(s[2 * nb + 1], qhf[kf], bh[2], bh[3]);
                MMA16816(s[2 * nb], qlf[kf], bh[0], bh[1]);
                MMA16816(s[2 * nb + 1], qlf[kf], bh[2], bh[3]);
            }
        }
#pragma unroll
        for (int nf = 0; nf < 8; nf++) {
            s[nf][0] *= Cs; s[nf][1] *= Cs; s[nf][2] *= Cs; s[nf][3] *= Cs;
        }
        if (kt >= nkt - 2) {
            const int r0 = gr + w * 16 + (lane >> 2);
            const int c0 = kt * 64 + 2 * (lane & 3);
#pragma unroll
            for (int nf = 0; nf < 8; nf++) {
#pragma unroll
                for (int j = 0; j < 4; j++) {
                    int col = c0 + nf * 8 + (j & 1);
                    int row = r0 + (j >> 1) * 8;
                    if (col > row) s[nf][j] = -1e5f;
                }
            }
        }
        float mx0 = -1e30f, mx1 = -1e30f;
#pragma unroll
        for (int nf = 0; nf < 8; nf++) {
            mx0 = fmaxf(mx0, fmaxf(s[nf][0], s[nf][1]));
            mx1 = fmaxf(mx1, fmaxf(s[nf][2], s[nf][3]));
        }
        mx0 = fmaxf(mx0, __shfl_xor_sync(0xffffffffu, mx0, 1));
        mx0 = fmaxf(mx0, __shfl_xor_sync(0xffffffffu, mx0, 2));
        mx1 = fmaxf(mx1, __shfl_xor_sync(0xffffffffu, mx1, 1));
        mx1 = fmaxf(mx1, __shfl_xor_sync(0xffffffffu, mx1, 2));
        const float mn0 = fmaxf(m0, mx0), mn1 = fmaxf(m1, mx1);
        const float cr0 = exp2p(m0 - mn0), cr1 = exp2p(m1 - mn1);
        m0 = mn0; m1 = mn1;
        float rs0 = 0.f, rs1 = 0.f;
#pragma unroll
        for (int nf = 0; nf < 8; nf++) {
            float p0 = exp2p(s[nf][0] - mn0), p1 = exp2p(s[nf][1] - mn0);
            float p2 = exp2p(s[nf][2] - mn1), p3 = exp2p(s[nf][3] - mn1);
            s[nf][0] = p0; s[nf][1] = p1; s[nf][2] = p2; s[nf][3] = p3;
            rs0 += p0 + p1; rs1 += p2 + p3;
        }
        rs0 += __shfl_xor_sync(0xffffffffu, rs0, 1);
        rs0 += __shfl_xor_sync(0xffffffffu, rs0, 2);
        rs1 += __shfl_xor_sync(0xffffffffu, rs1, 1);
        rs1 += __shfl_xor_sync(0xffffffffu, rs1, 2);
        l0 = l0 * cr0 + rs0;
        l1 = l1 * cr1 + rs1;
#pragma unroll
        for (int nf = 0; nf < 16; nf++) {
            o[nf][0] *= cr0; o[nf][1] *= cr0; o[nf][2] *= cr1; o[nf][3] *= cr1;
        }
        // ---- P @ V (P hi/lo pair x v single)
#pragma unroll
        for (int kb = 0; kb < 4; kb++) {
            uint32_t ph[4], pl[4];
#pragma unroll
            for (int q2 = 0; q2 < 2; q2++) {
                const int nf = 2 * kb + q2;
                uint32_t h01 = pack_f16x2(s[nf][1], s[nf][0]);
                float2 f01 = unpack_f16x2(h01);
                uint32_t l01 = pack_f16x2(s[nf][1] - f01.y, s[nf][0] - f01.x);
                uint32_t h23 = pack_f16x2(s[nf][3], s[nf][2]);
                float2 f23 = unpack_f16x2(h23);
                uint32_t l23 = pack_f16x2(s[nf][3] - f23.y, s[nf][2] - f23.x);
                ph[2 * q2] = h01; ph[2 * q2 + 1] = h23;
                pl[2 * q2] = l01; pl[2 * q2 + 1] = l23;
            }
#pragma unroll
            for (int ng = 0; ng < 8; ng++) {
                uint32_t vv[4];
                LDSM4T(vv, sVh + voff + kb * (16 * FSTR) + ng * 32);
                MMA16816(o[2 * ng], ph, vv[0], vv[1]);
                MMA16816(o[2 * ng + 1], ph, vv[2], vv[3]);
                MMA16816(o[2 * ng], pl, vv[0], vv[1]);
                MMA16816(o[2 * ng + 1], pl, vv[2], vv[3]);
            }
        }
        st = (st == 2) ? 0 : st + 1;
        st2 = (st2 == 2) ? 0 : st2 + 1;
    }
#undef LOADKV

    const float inv0 = 1.f / l0, inv1 = 1.f / l1;
    const size_t row0_ = (size_t)(b * SEQ + gr + w * 16 + (lane >> 2));
    const int colb = h * 128 + 2 * (lane & 3);
#pragma unroll
    for (int nf = 0; nf < 16; nf++) {
        const int col = colb + nf * 8;
        float v0 = o[nf][0] * inv0, v1 = o[nf][1] * inv0;
        float v2 = o[nf][2] * inv1, v3 = o[nf][3] * inv1;
        uint32_t h01 = pack_f16x2(v1, v0);
        float2 f01 = unpack_f16x2(h01);
        uint32_t l01 = pack_f16x2(v1 - f01.y, v0 - f01.x);
        uint32_t h23 = pack_f16x2(v3, v2);
        float2 f23 = unpack_f16x2(h23);
        uint32_t l23 = pack_f16x2(v3 - f23.y, v2 - f23.x);
        *(uint32_t*)&oh_g[row0_ * HID + col] = h01;
        *(uint32_t*)&ol_g[row0_ * HID + col] = l01;
        *(uint32_t*)&oh_g[(row0_ + 8) * HID + col] = h23;
        *(uint32_t*)&ol_g[(row0_ + 8) * HID + col] = l23;
    }
}

// ---------------- launch ----------------
extern "C" void kernel_launch(void* const* d_in, const int* in_sizes, int n_in,
                              void* d_out, int out_size)
{
    const float* x  = (const float*)d_in[0];
    const float* Wq = (const float*)d_in[2];
    const float* Aq = (const float*)d_in[3];
    const float* Bq = (const float*)d_in[4];
    const float* mq = (const float*)d_in[5];
    const float* Wk = (const float*)d_in[6];
    const float* Ak = (const float*)d_in[7];
    const float* Bk = (const float*)d_in[8];
    const float* mk = (const float*)d_in[9];
    const float* Wv = (const float*)d_in[10];
    const float* Av = (const float*)d_in[11];
    const float* Bv = (const float*)d_in[12];
    const float* mv = (const float*)d_in[13];
    const float* Wo = (const float*)d_in[14];
    const float* Ao = (const float*)d_in[15];
    const float* Bo = (const float*)d_in[16];
    const float* mo = (const float*)d_in[17];

    __half *xh, *xl, *Wqh, *Wql, *Wkh, *Wvh, *Woh;
    __half *qh, *ql, *kh, *vh, *ath, *atl;
    cudaGetSymbolAddress((void**)&xh, g_xh);   cudaGetSymbolAddress((void**)&xl, g_xl);
    cudaGetSymbolAddress((void**)&Wqh, g_Wqh); cudaGetSymbolAddress((void**)&Wql, g_Wql);
    cudaGetSymbolAddress((void**)&Wkh, g_Wkh);
    cudaGetSymbolAddress((void**)&Wvh, g_Wvh); cudaGetSymbolAddress((void**)&Woh, g_Woh);
    cudaGetSymbolAddress((void**)&qh, g_qh);   cudaGetSymbolAddress((void**)&ql, g_ql);
    cudaGetSymbolAddress((void**)&kh, g_kh);
    cudaGetSymbolAddress((void**)&vh, g_vh);
    cudaGetSymbolAddress((void**)&ath, g_ath); cudaGetSymbolAddress((void**)&atl, g_atl);

    cudaFuncSetAttribute(gemm_qkv, cudaFuncAttributeMaxDynamicSharedMemorySize, GEMM_SMEM);
    cudaFuncSetAttribute(gemm_o, cudaFuncAttributeMaxDynamicSharedMemorySize, GEMM_SMEM);
    cudaFuncSetAttribute(flash_hmma, cudaFuncAttributeMaxDynamicSharedMemorySize, FLASH_SMEM);

    // 1) DoRA effective weights (one launch; Wq hi/lo, others hi only)
    dora_all<<<10240, 256>>>(Wq, Aq, Bq, mq, Wk, Ak, Bk, mk,
                             Wv, Av, Bv, mv, Wo, Ao, Bo, mo,
                             Wqh, Wql, Wkh, Wvh, Woh);

    // 2) split x
    split_f16<<<(TOK * HID / 4 + 255) / 256, 256>>>(x, xh, xl, TOK * HID / 4);

    // 3) merged q/k/v projections
    gemm_qkv<<<dim3(48, TOK / 128), 256, GEMM_SMEM>>>(
        xh, xl, Wqh, Wql, Wkh, Wvh, qh, ql, kh, vh);

    // 4) causal attention (HMMA) -> fp16 hi/lo attention output
    flash_hmma<<<dim3(SEQ / 128, 32, 2), 256, FLASH_SMEM>>>(qh, ql, kh, vh, ath, atl);

    // 5) output projection (2-term) -> d_out (fp32)
    gemm_o<<<dim3(HID / 128, TOK / 128), 256, GEMM_SMEM>>>(ath, atl, Woh, (float*)d_out);
}

// round 9
// speedup vs baseline: 1.4650x; 1.0256x over previous
#include <cuda_runtime.h>
#include <cuda_fp16.h>
#include <cstdint>
#include <math.h>

#define HID 4096
#define KVD 1024
#define TOK 4096   /* B*S */
#define SEQ 2048

// ---------------- device scratch ----------------
__device__ __half g_xh[TOK * HID];
__device__ __half g_xl[TOK * HID];
__device__ __half g_Wqh[HID * HID];
__device__ __half g_Wkh[KVD * HID];
__device__ __half g_Wvh[KVD * HID];
__device__ __half g_Woh[HID * HID];
__device__ __half g_qh[TOK * HID];
__device__ __half g_kh[TOK * KVD];
__device__ __half g_vh[TOK * KVD];
__device__ __half g_ath[TOK * HID];
__device__ __half g_atl[TOK * HID];

// ---------------- helpers ----------------
__device__ __forceinline__ uint32_t smem_u32(const void* p) {
    uint32_t a;
    asm("{ .reg .u64 t; cvta.to.shared.u64 t, %1; cvt.u32.u64 %0, t; }" : "=r"(a) : "l"(p));
    return a;
}
__device__ __forceinline__ void cp16(uint32_t dst, const void* src) {
    asm volatile("cp.async.cg.shared.global [%0], [%1], 16;\n" :: "r"(dst), "l"(src) : "memory");
}
#define CP_COMMIT() asm volatile("cp.async.commit_group;\n" ::: "memory")

#define LDSM4(r, a) \
    asm volatile("ldmatrix.sync.aligned.m8n8.x4.shared.b16 {%0,%1,%2,%3}, [%4];" \
                 : "=r"((r)[0]), "=r"((r)[1]), "=r"((r)[2]), "=r"((r)[3]) : "r"(a))
#define LDSM4T(r, a) \
    asm volatile("ldmatrix.sync.aligned.m8n8.x4.trans.shared.b16 {%0,%1,%2,%3}, [%4];" \
                 : "=r"((r)[0]), "=r"((r)[1]), "=r"((r)[2]), "=r"((r)[3]) : "r"(a))

#define MMA16816(d, a, b0, b1) \
    asm volatile("mma.sync.aligned.m16n8k16.row.col.f32.f16.f16.f32 " \
                 "{%0,%1,%2,%3}, {%4,%5,%6,%7}, {%8,%9}, {%0,%1,%2,%3};" \
                 : "+f"((d)[0]), "+f"((d)[1]), "+f"((d)[2]), "+f"((d)[3]) \
                 : "r"((a)[0]), "r"((a)[1]), "r"((a)[2]), "r"((a)[3]), "r"(b0), "r"(b1))

__device__ __forceinline__ uint32_t pack_f16x2(float hi_, float lo_) {
    __half2 h = __floats2half2_rn(lo_, hi_);
    return *(uint32_t*)&h;
}
__device__ __forceinline__ float2 unpack_f16x2(uint32_t u) {
    __half2 h = *(__half2*)&u;
    float2 r;
    r.x = __low2float(h);
    r.y = __high2float(h);
    return r;
}
// fast exp2 on FMA pipe (no MUFU). x <= 0 expected; rel err ~2.4e-6.
__device__ __forceinline__ float exp2p(float x) {
    x = fmaxf(x, -120.f);
    int e = __float2int_rn(x);
    float f = x - (float)e;
    float p = 1.3333558e-3f;
    p = fmaf(p, f, 9.6181291e-3f);
    p = fmaf(p, f, 5.5504109e-2f);
    p = fmaf(p, f, 2.4022651e-1f);
    p = fmaf(p, f, 6.9314718e-1f);
    p = fmaf(p, f, 1.0f);
    return p * __int_as_float((uint32_t)(e + 127) << 23);
}

// ---------------- DoRA weight materialization (all 4 weights, one launch) ----
__global__ __launch_bounds__(256) void dora_all(
    const float* __restrict__ Wq, const float* __restrict__ Aq,
    const float* __restrict__ Bq, const float* __restrict__ mq,
    const float* __restrict__ Wk, const float* __restrict__ Ak,
    const float* __restrict__ Bk, const float* __restrict__ mk,
    const float* __restrict__ Wv, const float* __restrict__ Av,
    const float* __restrict__ Bv, const float* __restrict__ mv,
    const float* __restrict__ Wo, const float* __restrict__ Ao,
    const float* __restrict__ Bo, const float* __restrict__ mo,
    __half* __restrict__ Wqh, __half* __restrict__ Wkh,
    __half* __restrict__ Wvh, __half* __restrict__ Woh)
{
    const int bx = blockIdx.x;
    const float *W, *A, *Bm, *mvec;
    __half *Whi;
    int row;
    if (bx < 4096)      { W = Wq; A = Aq; Bm = Bq; mvec = mq; Whi = Wqh; row = bx; }
    else if (bx < 5120) { W = Wk; A = Ak; Bm = Bk; mvec = mk; Whi = Wkh; row = bx - 4096; }
    else if (bx < 6144) { W = Wv; A = Av; Bm = Bv; mvec = mv; Whi = Wvh; row = bx - 5120; }
    else                { W = Wo; A = Ao; Bm = Bo; mvec = mo; Whi = Woh; row = bx - 6144; }

    const int tid = threadIdx.x;
    float b[8];
#pragma unroll
    for (int r = 0; r < 8; r++) b[r] = 2.0f * Bm[row * 8 + r];

    const float4* Wrow = (const float4*)(W + (size_t)row * HID);
    float4 w[4];
    float ss = 0.f;
#pragma unroll
    for (int c = 0; c < 4; c++) {
        int col4 = tid + 256 * c;
        float4 wv = Wrow[col4];
#pragma unroll
        for (int r = 0; r < 8; r++) {
            float4 av = ((const float4*)(A + (size_t)r * HID))[col4];
            wv.x += b[r] * av.x; wv.y += b[r] * av.y;
            wv.z += b[r] * av.z; wv.w += b[r] * av.w;
        }
        ss += wv.x * wv.x + wv.y * wv.y + wv.z * wv.z + wv.w * wv.w;
        w[c] = wv;
    }
#pragma unroll
    for (int off = 16; off; off >>= 1)
        ss += __shfl_xor_sync(0xffffffffu, ss, off);

    __shared__ float red[8];
    __shared__ float s_scale;
    if ((tid & 31) == 0) red[tid >> 5] = ss;
    __syncthreads();
    if (tid == 0) {
        float t = 0.f;
#pragma unroll
        for (int i = 0; i < 8; i++) t += red[i];
        s_scale = mvec[row] / (sqrtf(t) + 1e-8f);
    }
    __syncthreads();
    const float sc = s_scale;
#pragma unroll
    for (int c = 0; c < 4; c++) {
        float vv[4] = {w[c].x * sc, w[c].y * sc, w[c].z * sc, w[c].w * sc};
        size_t base = (size_t)row * HID + (tid + 256 * c) * 4;
        __half2 p0 = __floats2half2_rn(vv[0], vv[1]);
        __half2 p1 = __floats2half2_rn(vv[2], vv[3]);
        *(__half2*)&Whi[base] = p0;
        *(__half2*)&Whi[base + 2] = p1;
    }
}

// ---------------- fp32 -> fp16 hi/lo split (x only) ----------------
__global__ __launch_bounds__(256) void split_f16(
    const float* __restrict__ in, __half* __restrict__ hi,
    __half* __restrict__ lo, int n4)
{
    int i = blockIdx.x * 256 + threadIdx.x;
    if (i >= n4) return;
    float4 v = ((const float4*)in)[i];
    float vv[4] = {v.x, v.y, v.z, v.w};
    size_t base = (size_t)i * 4;
#pragma unroll
    for (int e = 0; e < 4; e++) {
        __half h = __float2half_rn(vv[e]);
        hi[base + e] = h;
        lo[base + e] = __float2half_rn(vv[e] - __half2float(h));
    }
}

// ---------------- HMMA mainloop: 128x128 tile, K=4096, 2-term ----------------
// acc += ah*bh + al*bh  (A hi/lo split, B single fp16)
#define STRIDE_B 80
#define TILE_B   (128 * STRIDE_B)
#define STAGE_B  (3 * TILE_B)            /* {Ah, Al, Bh} */
#define GEMM_SMEM (2 * STAGE_B)          /* 61440, 2+ CTAs/SM */

__device__ __forceinline__ void hmma_mainloop(
    uint32_t sb, const __half* g0, const __half* g1,
    const __half* g2, int tid, float acc[2][8][4])
{
    const int lane = tid & 31, wid = tid >> 5;
    const int wm = wid & 3, wn = wid >> 2;
    const int K = 4096;
    const int ldr = tid >> 2;
    const int ldc = (tid & 3) * 16;

    const uint32_t a_off = (uint32_t)(wm * 32 + (lane & 15)) * STRIDE_B + ((lane >> 4) * 16);
    const uint32_t b_off = (uint32_t)(wn * 64 + (((lane >> 4) << 3) + (lane & 7))) * STRIDE_B
                           + (((lane >> 3) & 1) * 16);

#define LOAD_STAGE(buf, k0) do { \
    uint32_t s0_ = sb + (buf) * STAGE_B; \
    const __half* gg_[3] = {g0 + (k0), g1 + (k0), g2 + (k0)}; \
    _Pragma("unroll") \
    for (int t_ = 0; t_ < 3; t_++) { \
        uint32_t st_ = s0_ + t_ * TILE_B; \
        _Pragma("unroll") \
        for (int p_ = 0; p_ < 2; p_++) { \
            int r_ = ldr + p_ * 64; \
            cp16(st_ + (uint32_t)r_ * STRIDE_B + ldc, \
                 (const char*)(gg_[t_] + (size_t)r_ * K) + ldc); \
        } \
    } \
    CP_COMMIT(); \
} while (0)

    LOAD_STAGE(0, 0);
    for (int ch = 0; ch < 128; ch++) {
        if (ch + 1 < 128) {
            LOAD_STAGE((ch + 1) & 1, (ch + 1) * 32);
            asm volatile("cp.async.wait_group 1;\n" ::: "memory");
        } else {
            asm volatile("cp.async.wait_group 0;\n" ::: "memory");
        }
        __syncthreads();
        const uint32_t s0 = sb + (ch & 1) * STAGE_B;
        const uint32_t sAh = s0, sAl = s0 + TILE_B, sBh = s0 + 2 * TILE_B;
#pragma unroll
        for (int k16 = 0; k16 < 2; k16++) {
            const uint32_t kadd = k16 * 32;
            uint32_t ah[2][4], al[2][4], bb[4][4];
            LDSM4(ah[0], sAh + a_off + kadd);
            LDSM4(ah[1], sAh + a_off + 16 * STRIDE_B + kadd);
            LDSM4(al[0], sAl + a_off + kadd);
            LDSM4(al[1], sAl + a_off + 16 * STRIDE_B + kadd);
#pragma unroll
            for (int j = 0; j < 4; j++) LDSM4(bb[j], sBh + b_off + j * 16 * STRIDE_B + kadd);
#pragma unroll
            for (int i = 0; i < 2; i++)
#pragma unroll
                for (int f = 0; f < 8; f++)
                    MMA16816(acc[i][f], ah[i], bb[f >> 1][(f & 1) * 2], bb[f >> 1][(f & 1) * 2 + 1]);
#pragma unroll
            for (int i = 0; i < 2; i++)
#pragma unroll
                for (int f = 0; f < 8; f++)
                    MMA16816(acc[i][f], al[i], bb[f >> 1][(f & 1) * 2], bb[f >> 1][(f & 1) * 2 + 1]);
        }
        __syncthreads();
    }
#undef LOAD_STAGE
}

// ---------------- merged QKV projection (all 2-term, single fp16 out) -------
// grid.x: [0,32)->Q, [32,40)->K, [40,48)->V
__global__ __launch_bounds__(256, 1) void gemm_qkv(
    const __half* __restrict__ xh, const __half* __restrict__ xl,
    const __half* __restrict__ Wqh, const __half* __restrict__ Wkh,
    const __half* __restrict__ Wvh,
    __half* __restrict__ qh, __half* __restrict__ kh, __half* __restrict__ vh)
{
    extern __shared__ char dsm[];
    const uint32_t sb = smem_u32(dsm);
    const int tid = threadIdx.x, lane = tid & 31, wid = tid >> 5;
    const int wm = wid & 3, wn = wid >> 2;
    const int bx = blockIdx.x;
    const int row0 = blockIdx.y << 7;
    const int K = 4096;

    const __half* Bh_;
    __half* Oh;
    int N, col0;
    if (bx < 32)      { Bh_ = Wqh; Oh = qh; N = HID; col0 = bx << 7; }
    else if (bx < 40) { Bh_ = Wkh; Oh = kh; N = KVD; col0 = (bx - 32) << 7; }
    else              { Bh_ = Wvh; Oh = vh; N = KVD; col0 = (bx - 40) << 7; }

    float acc[2][8][4] = {};
    hmma_mainloop(sb, xh + (size_t)row0 * K, xl + (size_t)row0 * K,
                  Bh_ + (size_t)col0 * K, tid, acc);

#pragma unroll
    for (int i = 0; i < 2; i++) {
        const int mrow = row0 + wm * 32 + i * 16 + (lane >> 2);
#pragma unroll
        for (int f = 0; f < 8; f++) {
            const int col = col0 + wn * 64 + f * 8 + (lane & 3) * 2;
            uint32_t h01 = pack_f16x2(acc[i][f][1], acc[i][f][0]);
            uint32_t h23 = pack_f16x2(acc[i][f][3], acc[i][f][2]);
            *(uint32_t*)&Oh[(size_t)mrow * N + col] = h01;
            *(uint32_t*)&Oh[(size_t)(mrow + 8) * N + col] = h23;
        }
    }
}

// ---------------- output projection (2-term, fp32 out) ----------------
__global__ __launch_bounds__(256, 1) void gemm_o(
    const __half* __restrict__ Ah, const __half* __restrict__ Al,
    const __half* __restrict__ Bh,
    float* __restrict__ C)
{
    extern __shared__ char dsm[];
    const uint32_t sb = smem_u32(dsm);
    const int tid = threadIdx.x, lane = tid & 31, wid = tid >> 5;
    const int wm = wid & 3, wn = wid >> 2;
    const int row0 = blockIdx.y << 7, col0 = blockIdx.x << 7;
    const int K = 4096, N = HID;

    float acc[2][8][4] = {};
    hmma_mainloop(sb, Ah + (size_t)row0 * K, Al + (size_t)row0 * K,
                  Bh + (size_t)col0 * K, tid, acc);

#pragma unroll
    for (int i = 0; i < 2; i++) {
        const int mrow = row0 + wm * 32 + i * 16 + (lane >> 2);
#pragma unroll
        for (int f = 0; f < 8; f++) {
            const int col = col0 + wn * 64 + f * 8 + (lane & 3) * 2;
            float2 lo2 = {acc[i][f][0], acc[i][f][1]};
            float2 hi2 = {acc[i][f][2], acc[i][f][3]};
            *(float2*)&C[(size_t)mrow * N + col] = lo2;
            *(float2*)&C[(size_t)(mrow + 8) * N + col] = hi2;
        }
    }
}

// ---------------- HMMA causal flash attention ----------------
// CTA: 128 q-rows (8 warps x 16 rows), key tiles of 64, D=128.
// QK 1-term (q single x k single); PV 2-term (P hi/lo x v single).
// KV ring (3 stages of {kh, vh}) reuses the Q staging region.
#define FSTR 272                 /* bytes per 128-elem fp16 row (136 elems) */
#define KV_T 17408               /* 64*FSTR */
#define KV_STAGE (2 * KV_T)      /* 34816 */
#define FLASH_SMEM (3 * KV_STAGE) /* 104448 >= Q staging 34816 */

__global__ __launch_bounds__(256, 1) void flash_hmma(
    const __half* __restrict__ qh_g, const __half* __restrict__ kh_g,
    const __half* __restrict__ vh_g,
    __half* __restrict__ oh_g, __half* __restrict__ ol_g)
{
    extern __shared__ char dsm[];
    const uint32_t sq = smem_u32(dsm);
    const uint32_t sb = sq;                    // KV ring reuses Q region
    const int tid = threadIdx.x, lane = tid & 31, w = tid >> 5;
    const int qt = (int)gridDim.x - 1 - (int)blockIdx.x;
    const int h = blockIdx.y, b = blockIdx.z;
    const int kvh = h >> 2;
    const int gr = qt * 128;
    const int nkt = 2 * qt + 2;

    // ---- stage Q into smem, build A-frags in registers
    {
        const __half* src = qh_g + ((size_t)(b * SEQ + gr)) * HID + h * 128;
#pragma unroll
        for (int i = 0; i < 8; i++) {
            int idx = tid + i * 256;
            int r = idx >> 4, c = idx & 15;
            cp16(sq + (uint32_t)r * FSTR + c * 16,
                 (const char*)(src + (size_t)r * HID) + c * 16);
        }
        CP_COMMIT();
        asm volatile("cp.async.wait_group 0;\n" ::: "memory");
        __syncthreads();
    }
    uint32_t qhf[8][4];
    {
        const uint32_t qoff = (uint32_t)(w * 16 + (lane & 15)) * FSTR + ((lane >> 4) * 16);
#pragma unroll
        for (int kf = 0; kf < 8; kf++)
            LDSM4(qhf[kf], sq + qoff + kf * 32);
    }
    __syncthreads();   // Q smem free; ring may overwrite

    float o[16][4];
#pragma unroll
    for (int i = 0; i < 16; i++) { o[i][0] = 0.f; o[i][1] = 0.f; o[i][2] = 0.f; o[i][3] = 0.f; }
    float m0 = -1e5f, m1 = -1e5f, l0 = 0.f, l1 = 0.f;

    const uint32_t koff = (uint32_t)(((lane >> 4) << 3) + (lane & 7)) * FSTR + (((lane >> 3) & 1) * 16);
    const uint32_t voff = (uint32_t)((((lane >> 3) & 1) << 3) + (lane & 7)) * FSTR + ((lane >> 4) * 16);

    const __half* kh_p = kh_g + ((size_t)(b * SEQ)) * KVD + kvh * 128;
    const __half* vh_p = vh_g + ((size_t)(b * SEQ)) * KVD + kvh * 128;

#define LOADKV(kt_, buf_) do { \
    uint32_t s0_ = sb + (buf_) * KV_STAGE; \
    const __half* gs_[2] = { \
        kh_p + (size_t)(kt_) * 64 * KVD, vh_p + (size_t)(kt_) * 64 * KVD}; \
    _Pragma("unroll") \
    for (int t_ = 0; t_ < 2; t_++) { \
        _Pragma("unroll") \
        for (int i_ = 0; i_ < 4; i_++) { \
            int idx_ = tid + i_ * 256; \
            int r_ = idx_ >> 4, c_ = idx_ & 15; \
            cp16(s0_ + t_ * KV_T + (uint32_t)r_ * FSTR + c_ * 16, \
                 (const char*)(gs_[t_] + (size_t)r_ * KVD) + c_ * 16); \
        } \
    } \
    CP_COMMIT(); \
} while (0)

    LOADKV(0, 0);
    LOADKV(1, 1);
    const float Cs = 0.08838834764831845f * 1.4426950408889634f;

    int st = 0;
    int st2 = 2;
    for (int kt = 0; kt < nkt; kt++) {
        if (kt + 2 < nkt) {
            asm volatile("cp.async.wait_group 1;\n" ::: "memory");
        } else {
            asm volatile("cp.async.wait_group 0;\n" ::: "memory");
        }
        __syncthreads();
        if (kt + 2 < nkt) LOADKV(kt + 2, st2);

        const uint32_t sKh = sb + st * KV_STAGE;
        const uint32_t sVh = sKh + KV_T;

        // ---- QK^T (1-term)
        float s[8][4];
#pragma unroll
        for (int i = 0; i < 8; i++) { s[i][0] = 0.f; s[i][1] = 0.f; s[i][2] = 0.f; s[i][3] = 0.f; }
#pragma unroll
        for (int kf = 0; kf < 8; kf++) {
#pragma unroll
            for (int nb = 0; nb < 4; nb++) {
                uint32_t bh[4];
                LDSM4(bh, sKh + koff + nb * (16 * FSTR) + kf * 32);
                MMA16816(s[2 * nb], qhf[kf], bh[0], bh[1]);
                MMA16816(s[2 * nb + 1], qhf[kf], bh[2], bh[3]);
            }
        }
#pragma unroll
        for (int nf = 0; nf < 8; nf++) {
            s[nf][0] *= Cs; s[nf][1] *= Cs; s[nf][2] *= Cs; s[nf][3] *= Cs;
        }
        if (kt >= nkt - 2) {
            const int r0 = gr + w * 16 + (lane >> 2);
            const int c0 = kt * 64 + 2 * (lane & 3);
#pragma unroll
            for (int nf = 0; nf < 8; nf++) {
#pragma unroll
                for (int j = 0; j < 4; j++) {
                    int col = c0 + nf * 8 + (j & 1);
                    int row = r0 + (j >> 1) * 8;
                    if (col > row) s[nf][j] = -1e5f;
                }
            }
        }
        float mx0 = -1e30f, mx1 = -1e30f;
#pragma unroll
        for (int nf = 0; nf < 8; nf++) {
            mx0 = fmaxf(mx0, fmaxf(s[nf][0], s[nf][1]));
            mx1 = fmaxf(mx1, fmaxf(s[nf][2], s[nf][3]));
        }
        mx0 = fmaxf(mx0, __shfl_xor_sync(0xffffffffu, mx0, 1));
        mx0 = fmaxf(mx0, __shfl_xor_sync(0xffffffffu, mx0, 2));
        mx1 = fmaxf(mx1, __shfl_xor_sync(0xffffffffu, mx1, 1));
        mx1 = fmaxf(mx1, __shfl_xor_sync(0xffffffffu, mx1, 2));
        const float mn0 = fmaxf(m0, mx0), mn1 = fmaxf(m1, mx1);
        const float cr0 = exp2p(m0 - mn0), cr1 = exp2p(m1 - mn1);
        m0 = mn0; m1 = mn1;
        float rs0 = 0.f, rs1 = 0.f;
#pragma unroll
        for (int nf = 0; nf < 8; nf++) {
            float p0 = exp2p(s[nf][0] - mn0), p1 = exp2p(s[nf][1] - mn0);
            float p2 = exp2p(s[nf][2] - mn1), p3 = exp2p(s[nf][3] - mn1);
            s[nf][0] = p0; s[nf][1] = p1; s[nf][2] = p2; s[nf][3] = p3;
            rs0 += p0 + p1; rs1 += p2 + p3;
        }
        rs0 += __shfl_xor_sync(0xffffffffu, rs0, 1);
        rs0 += __shfl_xor_sync(0xffffffffu, rs0, 2);
        rs1 += __shfl_xor_sync(0xffffffffu, rs1, 1);
        rs1 += __shfl_xor_sync(0xffffffffu, rs1, 2);
        l0 = l0 * cr0 + rs0;
        l1 = l1 * cr1 + rs1;
#pragma unroll
        for (int nf = 0; nf < 16; nf++) {
            o[nf][0] *= cr0; o[nf][1] *= cr0; o[nf][2] *= cr1; o[nf][3] *= cr1;
        }
        // ---- P @ V (P hi/lo pair x v single)
#pragma unroll
        for (int kb = 0; kb < 4; kb++) {
            uint32_t ph[4], pl[4];
#pragma unroll
            for (int q2 = 0; q2 < 2; q2++) {
                const int nf = 2 * kb + q2;
                uint32_t h01 = pack_f16x2(s[nf][1], s[nf][0]);
                float2 f01 = unpack_f16x2(h01);
                uint32_t l01 = pack_f16x2(s[nf][1] - f01.y, s[nf][0] - f01.x);
                uint32_t h23 = pack_f16x2(s[nf][3], s[nf][2]);
                float2 f23 = unpack_f16x2(h23);
                uint32_t l23 = pack_f16x2(s[nf][3] - f23.y, s[nf][2] - f23.x);
                ph[2 * q2] = h01; ph[2 * q2 + 1] = h23;
                pl[2 * q2] = l01; pl[2 * q2 + 1] = l23;
            }
#pragma unroll
            for (int ng = 0; ng < 8; ng++) {
                uint32_t vv[4];
                LDSM4T(vv, sVh + voff + kb * (16 * FSTR) + ng * 32);
                MMA16816(o[2 * ng], ph, vv[0], vv[1]);
                MMA16816(o[2 * ng + 1], ph, vv[2], vv[3]);
                MMA16816(o[2 * ng], pl, vv[0], vv[1]);
                MMA16816(o[2 * ng + 1], pl, vv[2], vv[3]);
            }
        }
        st = (st == 2) ? 0 : st + 1;
        st2 = (st2 == 2) ? 0 : st2 + 1;
    }
#undef LOADKV

    const float inv0 = 1.f / l0, inv1 = 1.f / l1;
    const size_t row0_ = (size_t)(b * SEQ + gr + w * 16 + (lane >> 2));
    const int colb = h * 128 + 2 * (lane & 3);
#pragma unroll
    for (int nf = 0; nf < 16; nf++) {
        const int col = colb + nf * 8;
        float v0 = o[nf][0] * inv0, v1 = o[nf][1] * inv0;
        float v2 = o[nf][2] * inv1, v3 = o[nf][3] * inv1;
        uint32_t h01 = pack_f16x2(v1, v0);
        float2 f01 = unpack_f16x2(h01);
        uint32_t l01 = pack_f16x2(v1 - f01.y, v0 - f01.x);
        uint32_t h23 = pack_f16x2(v3, v2);
        float2 f23 = unpack_f16x2(h23);
        uint32_t l23 = pack_f16x2(v3 - f23.y, v2 - f23.x);
        *(uint32_t*)&oh_g[row0_ * HID + col] = h01;
        *(uint32_t*)&ol_g[row0_ * HID + col] = l01;
        *(uint32_t*)&oh_g[(row0_ + 8) * HID + col] = h23;
        *(uint32_t*)&ol_g[(row0_ + 8) * HID + col] = l23;
    }
}

// ---------------- launch ----------------
extern "C" void kernel_launch(void* const* d_in, const int* in_sizes, int n_in,
                              void* d_out, int out_size)
{
    const float* x  = (const float*)d_in[0];
    const float* Wq = (const float*)d_in[2];
    const float* Aq = (const float*)d_in[3];
    const float* Bq = (const float*)d_in[4];
    const float* mq = (const float*)d_in[5];
    const float* Wk = (const float*)d_in[6];
    const float* Ak = (const float*)d_in[7];
    const float* Bk = (const float*)d_in[8];
    const float* mk = (const float*)d_in[9];
    const float* Wv = (const float*)d_in[10];
    const float* Av = (const float*)d_in[11];
    const float* Bv = (const float*)d_in[12];
    const float* mv = (const float*)d_in[13];
    const float* Wo = (const float*)d_in[14];
    const float* Ao = (const float*)d_in[15];
    const float* Bo = (const float*)d_in[16];
    const float* mo = (const float*)d_in[17];

    __half *xh, *xl, *Wqh, *Wkh, *Wvh, *Woh;
    __half *qh, *kh, *vh, *ath, *atl;
    cudaGetSymbolAddress((void**)&xh, g_xh);   cudaGetSymbolAddress((void**)&xl, g_xl);
    cudaGetSymbolAddress((void**)&Wqh, g_Wqh); cudaGetSymbolAddress((void**)&Wkh, g_Wkh);
    cudaGetSymbolAddress((void**)&Wvh, g_Wvh); cudaGetSymbolAddress((void**)&Woh, g_Woh);
    cudaGetSymbolAddress((void**)&qh, g_qh);   cudaGetSymbolAddress((void**)&kh, g_kh);
    cudaGetSymbolAddress((void**)&vh, g_vh);
    cudaGetSymbolAddress((void**)&ath, g_ath); cudaGetSymbolAddress((void**)&atl, g_atl);

    cudaFuncSetAttribute(gemm_qkv, cudaFuncAttributeMaxDynamicSharedMemorySize, GEMM_SMEM);
    cudaFuncSetAttribute(gemm_o, cudaFuncAttributeMaxDynamicSharedMemorySize, GEMM_SMEM);
    cudaFuncSetAttribute(flash_hmma, cudaFuncAttributeMaxDynamicSharedMemorySize, FLASH_SMEM);

    // 1) DoRA effective weights (one launch, single fp16 out)
    dora_all<<<10240, 256>>>(Wq, Aq, Bq, mq, Wk, Ak, Bk, mk,
                             Wv, Av, Bv, mv, Wo, Ao, Bo, mo,
                             Wqh, Wkh, Wvh, Woh);

    // 2) split x
    split_f16<<<(TOK * HID / 4 + 255) / 256, 256>>>(x, xh, xl, TOK * HID / 4);

    // 3) merged q/k/v projections (all 2-term, single fp16 out)
    gemm_qkv<<<dim3(48, TOK / 128), 256, GEMM_SMEM>>>(
        xh, xl, Wqh, Wkh, Wvh, qh, kh, vh);

    // 4) causal attention (HMMA) -> fp16 hi/lo attention output
    flash_hmma<<<dim3(SEQ / 128, 32, 2), 256, FLASH_SMEM>>>(qh, kh, vh, ath, atl);

    // 5) output projection (2-term) -> d_out (fp32)
    gemm_o<<<dim3(HID / 128, TOK / 128), 256, GEMM_SMEM>>>(ath, atl, Woh, (float*)d_out);
}

// round 10
// speedup vs baseline: 1.7085x; 1.1662x over previous
#include <cuda_runtime.h>
#include <cuda_fp16.h>
#include <cstdint>
#include <math.h>

#define HID 4096
#define KVD 1024
#define TOK 4096   /* B*S */
#define SEQ 2048

// ---------------- device scratch ----------------
__device__ __half g_xh[TOK * HID];
__device__ __half g_xl[TOK * HID];
__device__ __half g_Wqh[HID * HID];
__device__ __half g_Wkh[KVD * HID];
__device__ __half g_Wvh[KVD * HID];
__device__ __half g_Woh[HID * HID];
__device__ __half g_qh[TOK * HID];
__device__ __half g_kh[TOK * KVD];
__device__ __half g_vh[TOK * KVD];
__device__ __half g_ath[TOK * HID];
__device__ __half g_atl[TOK * HID];

// ---------------- helpers ----------------
__device__ __forceinline__ uint32_t smem_u32(const void* p) {
    uint32_t a;
    asm("{ .reg .u64 t; cvta.to.shared.u64 t, %1; cvt.u32.u64 %0, t; }" : "=r"(a) : "l"(p));
    return a;
}
__device__ __forceinline__ void cp16(uint32_t dst, const void* src) {
    asm volatile("cp.async.cg.shared.global [%0], [%1], 16;\n" :: "r"(dst), "l"(src) : "memory");
}
#define CP_COMMIT() asm volatile("cp.async.commit_group;\n" ::: "memory")

#define LDSM4(r, a) \
    asm volatile("ldmatrix.sync.aligned.m8n8.x4.shared.b16 {%0,%1,%2,%3}, [%4];" \
                 : "=r"((r)[0]), "=r"((r)[1]), "=r"((r)[2]), "=r"((r)[3]) : "r"(a))
#define LDSM4T(r, a) \
    asm volatile("ldmatrix.sync.aligned.m8n8.x4.trans.shared.b16 {%0,%1,%2,%3}, [%4];" \
                 : "=r"((r)[0]), "=r"((r)[1]), "=r"((r)[2]), "=r"((r)[3]) : "r"(a))

#define MMA16816(d, a, b0, b1) \
    asm volatile("mma.sync.aligned.m16n8k16.row.col.f32.f16.f16.f32 " \
                 "{%0,%1,%2,%3}, {%4,%5,%6,%7}, {%8,%9}, {%0,%1,%2,%3};" \
                 : "+f"((d)[0]), "+f"((d)[1]), "+f"((d)[2]), "+f"((d)[3]) \
                 : "r"((a)[0]), "r"((a)[1]), "r"((a)[2]), "r"((a)[3]), "r"(b0), "r"(b1))

__device__ __forceinline__ uint32_t pack_f16x2(float hi_, float lo_) {
    __half2 h = __floats2half2_rn(lo_, hi_);
    return *(uint32_t*)&h;
}
__device__ __forceinline__ float2 unpack_f16x2(uint32_t u) {
    __half2 h = *(__half2*)&u;
    float2 r;
    r.x = __low2float(h);
    r.y = __high2float(h);
    return r;
}
// fast exp2 on FMA pipe (no MUFU). x <= 0 expected; rel err ~2.4e-6.
__device__ __forceinline__ float exp2p(float x) {
    x = fmaxf(x, -120.f);
    int e = __float2int_rn(x);
    float f = x - (float)e;
    float p = 1.3333558e-3f;
    p = fmaf(p, f, 9.6181291e-3f);
    p = fmaf(p, f, 5.5504109e-2f);
    p = fmaf(p, f, 2.4022651e-1f);
    p = fmaf(p, f, 6.9314718e-1f);
    p = fmaf(p, f, 1.0f);
    return p * __int_as_float((uint32_t)(e + 127) << 23);
}

// ---------------- DoRA weight materialization (all 4 weights, one launch) ----
__global__ __launch_bounds__(256) void dora_all(
    const float* __restrict__ Wq, const float* __restrict__ Aq,
    const float* __restrict__ Bq, const float* __restrict__ mq,
    const float* __restrict__ Wk, const float* __restrict__ Ak,
    const float* __restrict__ Bk, const float* __restrict__ mk,
    const float* __restrict__ Wv, const float* __restrict__ Av,
    const float* __restrict__ Bv, const float* __restrict__ mv,
    const float* __restrict__ Wo, const float* __restrict__ Ao,
    const float* __restrict__ Bo, const float* __restrict__ mo,
    __half* __restrict__ Wqh, __half* __restrict__ Wkh,
    __half* __restrict__ Wvh, __half* __restrict__ Woh)
{
    const int bx = blockIdx.x;
    const float *W, *A, *Bm, *mvec;
    __half *Whi;
    int row;
    if (bx < 4096)      { W = Wq; A = Aq; Bm = Bq; mvec = mq; Whi = Wqh; row = bx; }
    else if (bx < 5120) { W = Wk; A = Ak; Bm = Bk; mvec = mk; Whi = Wkh; row = bx - 4096; }
    else if (bx < 6144) { W = Wv; A = Av; Bm = Bv; mvec = mv; Whi = Wvh; row = bx - 5120; }
    else                { W = Wo; A = Ao; Bm = Bo; mvec = mo; Whi = Woh; row = bx - 6144; }

    const int tid = threadIdx.x;
    float b[8];
#pragma unroll
    for (int r = 0; r < 8; r++) b[r] = 2.0f * Bm[row * 8 + r];

    const float4* Wrow = (const float4*)(W + (size_t)row * HID);
    float4 w[4];
    float ss = 0.f;
#pragma unroll
    for (int c = 0; c < 4; c++) {
        int col4 = tid + 256 * c;
        float4 wv = Wrow[col4];
#pragma unroll
        for (int r = 0; r < 8; r++) {
            float4 av = ((const float4*)(A + (size_t)r * HID))[col4];
            wv.x += b[r] * av.x; wv.y += b[r] * av.y;
            wv.z += b[r] * av.z; wv.w += b[r] * av.w;
        }
        ss += wv.x * wv.x + wv.y * wv.y + wv.z * wv.z + wv.w * wv.w;
        w[c] = wv;
    }
#pragma unroll
    for (int off = 16; off; off >>= 1)
        ss += __shfl_xor_sync(0xffffffffu, ss, off);

    __shared__ float red[8];
    __shared__ float s_scale;
    if ((tid & 31) == 0) red[tid >> 5] = ss;
    __syncthreads();
    if (tid == 0) {
        float t = 0.f;
#pragma unroll
        for (int i = 0; i < 8; i++) t += red[i];
        s_scale = mvec[row] / (sqrtf(t) + 1e-8f);
    }
    __syncthreads();
    const float sc = s_scale;
#pragma unroll
    for (int c = 0; c < 4; c++) {
        float vv[4] = {w[c].x * sc, w[c].y * sc, w[c].z * sc, w[c].w * sc};
        size_t base = (size_t)row * HID + (tid + 256 * c) * 4;
        __half2 p0 = __floats2half2_rn(vv[0], vv[1]);
        __half2 p1 = __floats2half2_rn(vv[2], vv[3]);
        *(__half2*)&Whi[base] = p0;
        *(__half2*)&Whi[base + 2] = p1;
    }
}

// ---------------- fp32 -> fp16 hi/lo split (x only) ----------------
__global__ __launch_bounds__(256) void split_f16(
    const float* __restrict__ in, __half* __restrict__ hi,
    __half* __restrict__ lo, int n4)
{
    int i = blockIdx.x * 256 + threadIdx.x;
    if (i >= n4) return;
    float4 v = ((const float4*)in)[i];
    float vv[4] = {v.x, v.y, v.z, v.w};
    size_t base = (size_t)i * 4;
#pragma unroll
    for (int e = 0; e < 4; e++) {
        __half h = __float2half_rn(vv[e]);
        hi[base + e] = h;
        lo[base + e] = __float2half_rn(vv[e] - __half2float(h));
    }
}

// ---------------- HMMA mainloop: 128x128 tile, K=4096, 2-term ----------------
// acc += ah*bh + al*bh  (A hi/lo split, B single fp16)
// 3-stage cp.async ring (loads 2 chunks ahead), ONE barrier per chunk.
#define STRIDE_B 80
#define TILE_B   (128 * STRIDE_B)
#define KSTAGE_B (3 * TILE_B)            /* one stage: {Ah, Al, Bh} = 30720 */
#define GEMM_SMEM (3 * KSTAGE_B)         /* 92160/CTA -> 2 CTAs/SM (184320) */

__device__ __forceinline__ void hmma_mainloop(
    uint32_t sb, const __half* g0, const __half* g1,
    const __half* g2, int tid, float acc[2][8][4])
{
    const int lane = tid & 31, wid = tid >> 5;
    const int wm = wid & 3, wn = wid >> 2;
    const int K = 4096;
    const int ldr = tid >> 2;
    const int ldc = (tid & 3) * 16;

    const uint32_t a_off = (uint32_t)(wm * 32 + (lane & 15)) * STRIDE_B + ((lane >> 4) * 16);
    const uint32_t b_off = (uint32_t)(wn * 64 + (((lane >> 4) << 3) + (lane & 7))) * STRIDE_B
                           + (((lane >> 3) & 1) * 16);

#define LOAD_STAGE(buf, k0) do { \
    uint32_t s0_ = sb + (buf) * KSTAGE_B; \
    const __half* gg_[3] = {g0 + (k0), g1 + (k0), g2 + (k0)}; \
    _Pragma("unroll") \
    for (int t_ = 0; t_ < 3; t_++) { \
        uint32_t st_ = s0_ + t_ * TILE_B; \
        _Pragma("unroll") \
        for (int p_ = 0; p_ < 2; p_++) { \
            int r_ = ldr + p_ * 64; \
            cp16(st_ + (uint32_t)r_ * STRIDE_B + ldc, \
                 (const char*)(gg_[t_] + (size_t)r_ * K) + ldc); \
        } \
    } \
    CP_COMMIT(); \
} while (0)

    LOAD_STAGE(0, 0);
    LOAD_STAGE(1, 32);

    int cst = 0;   // stage holding chunk ch
    for (int ch = 0; ch < 128; ch++) {
        if (ch + 1 < 128) {
            asm volatile("cp.async.wait_group 1;\n" ::: "memory");
        } else {
            asm volatile("cp.async.wait_group 0;\n" ::: "memory");
        }
        __syncthreads();
        if (ch + 2 < 128) {
            int lst = cst - 1; if (lst < 0) lst += 3;   // (cst+2)%3
            LOAD_STAGE(lst, (ch + 2) * 32);
        }
        const uint32_t s0 = sb + cst * KSTAGE_B;
        const uint32_t sAh = s0, sAl = s0 + TILE_B, sBh = s0 + 2 * TILE_B;
#pragma unroll
        for (int k16 = 0; k16 < 2; k16++) {
            const uint32_t kadd = k16 * 32;
            uint32_t ah[2][4], al[2][4], bb[4][4];
            LDSM4(ah[0], sAh + a_off + kadd);
            LDSM4(ah[1], sAh + a_off + 16 * STRIDE_B + kadd);
            LDSM4(al[0], sAl + a_off + kadd);
            LDSM4(al[1], sAl + a_off + 16 * STRIDE_B + kadd);
#pragma unroll
            for (int j = 0; j < 4; j++) LDSM4(bb[j], sBh + b_off + j * 16 * STRIDE_B + kadd);
#pragma unroll
            for (int i = 0; i < 2; i++)
#pragma unroll
                for (int f = 0; f < 8; f++)
                    MMA16816(acc[i][f], ah[i], bb[f >> 1][(f & 1) * 2], bb[f >> 1][(f & 1) * 2 + 1]);
#pragma unroll
            for (int i = 0; i < 2; i++)
#pragma unroll
                for (int f = 0; f < 8; f++)
                    MMA16816(acc[i][f], al[i], bb[f >> 1][(f & 1) * 2], bb[f >> 1][(f & 1) * 2 + 1]);
        }
        cst = (cst == 2) ? 0 : cst + 1;
    }
#undef LOAD_STAGE
}

// ---------------- merged QKV projection (all 2-term, single fp16 out) -------
// grid.x: [0,32)->Q, [32,40)->K, [40,48)->V
__global__ __launch_bounds__(256, 2) void gemm_qkv(
    const __half* __restrict__ xh, const __half* __restrict__ xl,
    const __half* __restrict__ Wqh, const __half* __restrict__ Wkh,
    const __half* __restrict__ Wvh,
    __half* __restrict__ qh, __half* __restrict__ kh, __half* __restrict__ vh)
{
    extern __shared__ char dsm[];
    const uint32_t sb = smem_u32(dsm);
    const int tid = threadIdx.x, lane = tid & 31, wid = tid >> 5;
    const int wm = wid & 3, wn = wid >> 2;
    const int bx = blockIdx.x;
    const int row0 = blockIdx.y << 7;
    const int K = 4096;

    const __half* Bh_;
    __half* Oh;
    int N, col0;
    if (bx < 32)      { Bh_ = Wqh; Oh = qh; N = HID; col0 = bx << 7; }
    else if (bx < 40) { Bh_ = Wkh; Oh = kh; N = KVD; col0 = (bx - 32) << 7; }
    else              { Bh_ = Wvh; Oh = vh; N = KVD; col0 = (bx - 40) << 7; }

    float acc[2][8][4] = {};
    hmma_mainloop(sb, xh + (size_t)row0 * K, xl + (size_t)row0 * K,
                  Bh_ + (size_t)col0 * K, tid, acc);

#pragma unroll
    for (int i = 0; i < 2; i++) {
        const int mrow = row0 + wm * 32 + i * 16 + (lane >> 2);
#pragma unroll
        for (int f = 0; f < 8; f++) {
            const int col = col0 + wn * 64 + f * 8 + (lane & 3) * 2;
            uint32_t h01 = pack_f16x2(acc[i][f][1], acc[i][f][0]);
            uint32_t h23 = pack_f16x2(acc[i][f][3], acc[i][f][2]);
            *(uint32_t*)&Oh[(size_t)mrow * N + col] = h01;
            *(uint32_t*)&Oh[(size_t)(mrow + 8) * N + col] = h23;
        }
    }
}

// ---------------- output projection (2-term, fp32 out) ----------------
__global__ __launch_bounds__(256, 2) void gemm_o(
    const __half* __restrict__ Ah, const __half* __restrict__ Al,
    const __half* __restrict__ Bh,
    float* __restrict__ C)
{
    extern __shared__ char dsm[];
    const uint32_t sb = smem_u32(dsm);
    const int tid = threadIdx.x, lane = tid & 31, wid = tid >> 5;
    const int wm = wid & 3, wn = wid >> 2;
    const int row0 = blockIdx.y << 7, col0 = blockIdx.x << 7;
    const int K = 4096, N = HID;

    float acc[2][8][4] = {};
    hmma_mainloop(sb, Ah + (size_t)row0 * K, Al + (size_t)row0 * K,
                  Bh + (size_t)col0 * K, tid, acc);

#pragma unroll
    for (int i = 0; i < 2; i++) {
        const int mrow = row0 + wm * 32 + i * 16 + (lane >> 2);
#pragma unroll
        for (int f = 0; f < 8; f++) {
            const int col = col0 + wn * 64 + f * 8 + (lane & 3) * 2;
            float2 lo2 = {acc[i][f][0], acc[i][f][1]};
            float2 hi2 = {acc[i][f][2], acc[i][f][3]};
            *(float2*)&C[(size_t)mrow * N + col] = lo2;
            *(float2*)&C[(size_t)(mrow + 8) * N + col] = hi2;
        }
    }
}

// ---------------- HMMA causal flash attention ----------------
// CTA: 128 q-rows (8 warps x 16 rows), key tiles of 64, D=128.
// QK 1-term (q single x k single); PV 2-term (P hi/lo x v single).
// KV ring (3 stages of {kh, vh}) reuses the Q staging region.
#define FSTR 272                 /* bytes per 128-elem fp16 row (136 elems) */
#define KV_T 17408               /* 64*FSTR */
#define KV_STAGE (2 * KV_T)      /* 34816 */
#define FLASH_SMEM (3 * KV_STAGE) /* 104448 >= Q staging 34816 */

__global__ __launch_bounds__(256, 1) void flash_hmma(
    const __half* __restrict__ qh_g, const __half* __restrict__ kh_g,
    const __half* __restrict__ vh_g,
    __half* __restrict__ oh_g, __half* __restrict__ ol_g)
{
    extern __shared__ char dsm[];
    const uint32_t sq = smem_u32(dsm);
    const uint32_t sb = sq;                    // KV ring reuses Q region
    const int tid = threadIdx.x, lane = tid & 31, w = tid >> 5;
    const int qt = (int)gridDim.x - 1 - (int)blockIdx.x;
    const int h = blockIdx.y, b = blockIdx.z;
    const int kvh = h >> 2;
    const int gr = qt * 128;
    const int nkt = 2 * qt + 2;

    // ---- stage Q into smem, build A-frags in registers
    {
        const __half* src = qh_g + ((size_t)(b * SEQ + gr)) * HID + h * 128;
#pragma unroll
        for (int i = 0; i < 8; i++) {
            int idx = tid + i * 256;
            int r = idx >> 4, c = idx & 15;
            cp16(sq + (uint32_t)r * FSTR + c * 16,
                 (const char*)(src + (size_t)r * HID) + c * 16);
        }
        CP_COMMIT();
        asm volatile("cp.async.wait_group 0;\n" ::: "memory");
        __syncthreads();
    }
    uint32_t qhf[8][4];
    {
        const uint32_t qoff = (uint32_t)(w * 16 + (lane & 15)) * FSTR + ((lane >> 4) * 16);
#pragma unroll
        for (int kf = 0; kf < 8; kf++)
            LDSM4(qhf[kf], sq + qoff + kf * 32);
    }
    __syncthreads();   // Q smem free; ring may overwrite

    float o[16][4];
#pragma unroll
    for (int i = 0; i < 16; i++) { o[i][0] = 0.f; o[i][1] = 0.f; o[i][2] = 0.f; o[i][3] = 0.f; }
    float m0 = -1e5f, m1 = -1e5f, l0 = 0.f, l1 = 0.f;

    const uint32_t koff = (uint32_t)(((lane >> 4) << 3) + (lane & 7)) * FSTR + (((lane >> 3) & 1) * 16);
    const uint32_t voff = (uint32_t)((((lane >> 3) & 1) << 3) + (lane & 7)) * FSTR + ((lane >> 4) * 16);

    const __half* kh_p = kh_g + ((size_t)(b * SEQ)) * KVD + kvh * 128;
    const __half* vh_p = vh_g + ((size_t)(b * SEQ)) * KVD + kvh * 128;

#define LOADKV(kt_, buf_) do { \
    uint32_t s0_ = sb + (buf_) * KV_STAGE; \
    const __half* gs_[2] = { \
        kh_p + (size_t)(kt_) * 64 * KVD, vh_p + (size_t)(kt_) * 64 * KVD}; \
    _Pragma("unroll") \
    for (int t_ = 0; t_ < 2; t_++) { \
        _Pragma("unroll") \
        for (int i_ = 0; i_ < 4; i_++) { \
            int idx_ = tid + i_ * 256; \
            int r_ = idx_ >> 4, c_ = idx_ & 15; \
            cp16(s0_ + t_ * KV_T + (uint32_t)r_ * FSTR + c_ * 16, \
                 (const char*)(gs_[t_] + (size_t)r_ * KVD) + c_ * 16); \
        } \
    } \
    CP_COMMIT(); \
} while (0)

    LOADKV(0, 0);
    LOADKV(1, 1);
    const float Cs = 0.08838834764831845f * 1.4426950408889634f;

    int st = 0;
    int st2 = 2;
    for (int kt = 0; kt < nkt; kt++) {
        if (kt + 2 < nkt) {
            asm volatile("cp.async.wait_group 1;\n" ::: "memory");
        } else {
            asm volatile("cp.async.wait_group 0;\n" ::: "memory");
        }
        __syncthreads();
        if (kt + 2 < nkt) LOADKV(kt + 2, st2);

        const uint32_t sKh = sb + st * KV_STAGE;
        const uint32_t sVh = sKh + KV_T;

        // ---- QK^T (1-term)
        float s[8][4];
#pragma unroll
        for (int i = 0; i < 8; i++) { s[i][0] = 0.f; s[i][1] = 0.f; s[i][2] = 0.f; s[i][3] = 0.f; }
#pragma unroll
        for (int kf = 0; kf < 8; kf++) {
#pragma unroll
            for (int nb = 0; nb < 4; nb++) {
                uint32_t bh[4];
                LDSM4(bh, sKh + koff + nb * (16 * FSTR) + kf * 32);
                MMA16816(s[2 * nb], qhf[kf], bh[0], bh[1]);
                MMA16816(s[2 * nb + 1], qhf[kf], bh[2], bh[3]);
            }
        }
#pragma unroll
        for (int nf = 0; nf < 8; nf++) {
            s[nf][0] *= Cs; s[nf][1] *= Cs; s[nf][2] *= Cs; s[nf][3] *= Cs;
        }
        if (kt >= nkt - 2) {
            const int r0 = gr + w * 16 + (lane >> 2);
            const int c0 = kt * 64 + 2 * (lane & 3);
#pragma unroll
            for (int nf = 0; nf < 8; nf++) {
#pragma unroll
                for (int j = 0; j < 4; j++) {
                    int col = c0 + nf * 8 + (j & 1);
                    int row = r0 + (j >> 1) * 8;
                    if (col > row) s[nf][j] = -1e5f;
                }
            }
        }
        float mx0 = -1e30f, mx1 = -1e30f;
#pragma unroll
        for (int nf = 0; nf < 8; nf++) {
            mx0 = fmaxf(mx0, fmaxf(s[nf][0], s[nf][1]));
            mx1 = fmaxf(mx1, fmaxf(s[nf][2], s[nf][3]));
        }
        mx0 = fmaxf(mx0, __shfl_xor_sync(0xffffffffu, mx0, 1));
        mx0 = fmaxf(mx0, __shfl_xor_sync(0xffffffffu, mx0, 2));
        mx1 = fmaxf(mx1, __shfl_xor_sync(0xffffffffu, mx1, 1));
        mx1 = fmaxf(mx1, __shfl_xor_sync(0xffffffffu, mx1, 2));
        const float mn0 = fmaxf(m0, mx0), mn1 = fmaxf(m1, mx1);
        const float cr0 = exp2p(m0 - mn0), cr1 = exp2p(m1 - mn1);
        m0 = mn0; m1 = mn1;
        float rs0 = 0.f, rs1 = 0.f;
#pragma unroll
        for (int nf = 0; nf < 8; nf++) {
            float p0 = exp2p(s[nf][0] - mn0), p1 = exp2p(s[nf][1] - mn0);
            float p2 = exp2p(s[nf][2] - mn1), p3 = exp2p(s[nf][3] - mn1);
            s[nf][0] = p0; s[nf][1] = p1; s[nf][2] = p2; s[nf][3] = p3;
            rs0 += p0 + p1; rs1 += p2 + p3;
        }
        rs0 += __shfl_xor_sync(0xffffffffu, rs0, 1);
        rs0 += __shfl_xor_sync(0xffffffffu, rs0, 2);
        rs1 += __shfl_xor_sync(0xffffffffu, rs1, 1);
        rs1 += __shfl_xor_sync(0xffffffffu, rs1, 2);
        l0 = l0 * cr0 + rs0;
        l1 = l1 * cr1 + rs1;
#pragma unroll
        for (int nf = 0; nf < 16; nf++) {
            o[nf][0] *= cr0; o[nf][1] *= cr0; o[nf][2] *= cr1; o[nf][3] *= cr1;
        }
        // ---- P @ V (P hi/lo pair x v single)
#pragma unroll
        for (int kb = 0; kb < 4; kb++) {
            uint32_t ph[4], pl[4];
#pragma unroll
            for (int q2 = 0; q2 < 2; q2++) {
                const int nf = 2 * kb + q2;
                uint32_t h01 = pack_f16x2(s[nf][1], s[nf][0]);
                float2 f01 = unpack_f16x2(h01);
                uint32_t l01 = pack_f16x2(s[nf][1] - f01.y, s[nf][0] - f01.x);
                uint32_t h23 = pack_f16x2(s[nf][3], s[nf][2]);
                float2 f23 = unpack_f16x2(h23);
                uint32_t l23 = pack_f16x2(s[nf][3] - f23.y, s[nf][2] - f23.x);
                ph[2 * q2] = h01; ph[2 * q2 + 1] = h23;
                pl[2 * q2] = l01; pl[2 * q2 + 1] = l23;
            }
#pragma unroll
            for (int ng = 0; ng < 8; ng++) {
                uint32_t vv[4];
                LDSM4T(vv, sVh + voff + kb * (16 * FSTR) + ng * 32);
                MMA16816(o[2 * ng], ph, vv[0], vv[1]);
                MMA16816(o[2 * ng + 1], ph, vv[2], vv[3]);
                MMA16816(o[2 * ng], pl, vv[0], vv[1]);
                MMA16816(o[2 * ng + 1], pl, vv[2], vv[3]);
            }
        }
        st = (st == 2) ? 0 : st + 1;
        st2 = (st2 == 2) ? 0 : st2 + 1;
    }
#undef LOADKV

    const float inv0 = 1.f / l0, inv1 = 1.f / l1;
    const size_t row0_ = (size_t)(b * SEQ + gr + w * 16 + (lane >> 2));
    const int colb = h * 128 + 2 * (lane & 3);
#pragma unroll
    for (int nf = 0; nf < 16; nf++) {
        const int col = colb + nf * 8;
        float v0 = o[nf][0] * inv0, v1 = o[nf][1] * inv0;
        float v2 = o[nf][2] * inv1, v3 = o[nf][3] * inv1;
        uint32_t h01 = pack_f16x2(v1, v0);
        float2 f01 = unpack_f16x2(h01);
        uint32_t l01 = pack_f16x2(v1 - f01.y, v0 - f01.x);
        uint32_t h23 = pack_f16x2(v3, v2);
        float2 f23 = unpack_f16x2(h23);
        uint32_t l23 = pack_f16x2(v3 - f23.y, v2 - f23.x);
        *(uint32_t*)&oh_g[row0_ * HID + col] = h01;
        *(uint32_t*)&ol_g[row0_ * HID + col] = l01;
        *(uint32_t*)&oh_g[(row0_ + 8) * HID + col] = h23;
        *(uint32_t*)&ol_g[(row0_ + 8) * HID + col] = l23;
    }
}

// ---------------- launch ----------------
extern "C" void kernel_launch(void* const* d_in, const int* in_sizes, int n_in,
                              void* d_out, int out_size)
{
    const float* x  = (const float*)d_in[0];
    const float* Wq = (const float*)d_in[2];
    const float* Aq = (const float*)d_in[3];
    const float* Bq = (const float*)d_in[4];
    const float* mq = (const float*)d_in[5];
    const float* Wk = (const float*)d_in[6];
    const float* Ak = (const float*)d_in[7];
    const float* Bk = (const float*)d_in[8];
    const float* mk = (const float*)d_in[9];
    const float* Wv = (const float*)d_in[10];
    const float* Av = (const float*)d_in[11];
    const float* Bv = (const float*)d_in[12];
    const float* mv = (const float*)d_in[13];
    const float* Wo = (const float*)d_in[14];
    const float* Ao = (const float*)d_in[15];
    const float* Bo = (const float*)d_in[16];
    const float* mo = (const float*)d_in[17];

    __half *xh, *xl, *Wqh, *Wkh, *Wvh, *Woh;
    __half *qh, *kh, *vh, *ath, *atl;
    cudaGetSymbolAddress((void**)&xh, g_xh);   cudaGetSymbolAddress((void**)&xl, g_xl);
    cudaGetSymbolAddress((void**)&Wqh, g_Wqh); cudaGetSymbolAddress((void**)&Wkh, g_Wkh);
    cudaGetSymbolAddress((void**)&Wvh, g_Wvh); cudaGetSymbolAddress((void**)&Woh, g_Woh);
    cudaGetSymbolAddress((void**)&qh, g_qh);   cudaGetSymbolAddress((void**)&kh, g_kh);
    cudaGetSymbolAddress((void**)&vh, g_vh);
    cudaGetSymbolAddress((void**)&ath, g_ath); cudaGetSymbolAddress((void**)&atl, g_atl);

    cudaFuncSetAttribute(gemm_qkv, cudaFuncAttributeMaxDynamicSharedMemorySize, GEMM_SMEM);
    cudaFuncSetAttribute(gemm_o, cudaFuncAttributeMaxDynamicSharedMemorySize, GEMM_SMEM);
    cudaFuncSetAttribute(flash_hmma, cudaFuncAttributeMaxDynamicSharedMemorySize, FLASH_SMEM);

    // 1) DoRA effective weights (one launch, single fp16 out)
    dora_all<<<10240, 256>>>(Wq, Aq, Bq, mq, Wk, Ak, Bk, mk,
                             Wv, Av, Bv, mv, Wo, Ao, Bo, mo,
                             Wqh, Wkh, Wvh, Woh);

    // 2) split x
    split_f16<<<(TOK * HID / 4 + 255) / 256, 256>>>(x, xh, xl, TOK * HID / 4);

    // 3) merged q/k/v projections (all 2-term, single fp16 out)
    gemm_qkv<<<dim3(48, TOK / 128), 256, GEMM_SMEM>>>(
        xh, xl, Wqh, Wkh, Wvh, qh, kh, vh);

    // 4) causal attention (HMMA) -> fp16 hi/lo attention output
    flash_hmma<<<dim3(SEQ / 128, 32, 2), 256, FLASH_SMEM>>>(qh, kh, vh, ath, atl);

    // 5) output projection (2-term) -> d_out (fp32)
    gemm_o<<<dim3(HID / 128, TOK / 128), 256, GEMM_SMEM>>>(ath, atl, Woh, (float*)d_out);
}

// round 11
// speedup vs baseline: 1.9749x; 1.1560x over previous
#include <cuda_runtime.h>
#include <cuda_fp16.h>
#include <cstdint>
#include <math.h>

#define HID 4096
#define KVD 1024
#define TOK 4096   /* B*S */
#define SEQ 2048

// ---------------- device scratch ----------------
__device__ __half g_xh[TOK * HID];
__device__ __half g_xl[TOK * HID];
__device__ __half g_Wqh[HID * HID];
__device__ __half g_Wkh[KVD * HID];
__device__ __half g_Wvh[KVD * HID];
__device__ __half g_Woh[HID * HID];
__device__ __half g_qh[TOK * HID];
__device__ __half g_kh[TOK * KVD];
__device__ __half g_vh[TOK * KVD];
__device__ __half g_ath[TOK * HID];

// ---------------- helpers ----------------
__device__ __forceinline__ uint32_t smem_u32(const void* p) {
    uint32_t a;
    asm("{ .reg .u64 t; cvta.to.shared.u64 t, %1; cvt.u32.u64 %0, t; }" : "=r"(a) : "l"(p));
    return a;
}
__device__ __forceinline__ void cp16(uint32_t dst, const void* src) {
    asm volatile("cp.async.cg.shared.global [%0], [%1], 16;\n" :: "r"(dst), "l"(src) : "memory");
}
#define CP_COMMIT() asm volatile("cp.async.commit_group;\n" ::: "memory")

#define LDSM4(r, a) \
    asm volatile("ldmatrix.sync.aligned.m8n8.x4.shared.b16 {%0,%1,%2,%3}, [%4];" \
                 : "=r"((r)[0]), "=r"((r)[1]), "=r"((r)[2]), "=r"((r)[3]) : "r"(a))
#define LDSM4T(r, a) \
    asm volatile("ldmatrix.sync.aligned.m8n8.x4.trans.shared.b16 {%0,%1,%2,%3}, [%4];" \
                 : "=r"((r)[0]), "=r"((r)[1]), "=r"((r)[2]), "=r"((r)[3]) : "r"(a))

#define MMA16816(d, a, b0, b1) \
    asm volatile("mma.sync.aligned.m16n8k16.row.col.f32.f16.f16.f32 " \
                 "{%0,%1,%2,%3}, {%4,%5,%6,%7}, {%8,%9}, {%0,%1,%2,%3};" \
                 : "+f"((d)[0]), "+f"((d)[1]), "+f"((d)[2]), "+f"((d)[3]) \
                 : "r"((a)[0]), "r"((a)[1]), "r"((a)[2]), "r"((a)[3]), "r"(b0), "r"(b1))

__device__ __forceinline__ uint32_t pack_f16x2(float hi_, float lo_) {
    __half2 h = __floats2half2_rn(lo_, hi_);
    return *(uint32_t*)&h;
}
__device__ __forceinline__ float2 unpack_f16x2(uint32_t u) {
    __half2 h = *(__half2*)&u;
    float2 r;
    r.x = __low2float(h);
    r.y = __high2float(h);
    return r;
}
// fast exp2 on FMA pipe (no MUFU). x <= 0 expected; rel err ~2.4e-6.
__device__ __forceinline__ float exp2p(float x) {
    x = fmaxf(x, -120.f);
    int e = __float2int_rn(x);
    float f = x - (float)e;
    float p = 1.3333558e-3f;
    p = fmaf(p, f, 9.6181291e-3f);
    p = fmaf(p, f, 5.5504109e-2f);
    p = fmaf(p, f, 2.4022651e-1f);
    p = fmaf(p, f, 6.9314718e-1f);
    p = fmaf(p, f, 1.0f);
    return p * __int_as_float((uint32_t)(e + 127) << 23);
}

// ---------------- DoRA weight materialization (all 4 weights, one launch) ----
__global__ __launch_bounds__(256) void dora_all(
    const float* __restrict__ Wq, const float* __restrict__ Aq,
    const float* __restrict__ Bq, const float* __restrict__ mq,
    const float* __restrict__ Wk, const float* __restrict__ Ak,
    const float* __restrict__ Bk, const float* __restrict__ mk,
    const float* __restrict__ Wv, const float* __restrict__ Av,
    const float* __restrict__ Bv, const float* __restrict__ mv,
    const float* __restrict__ Wo, const float* __restrict__ Ao,
    const float* __restrict__ Bo, const float* __restrict__ mo,
    __half* __restrict__ Wqh, __half* __restrict__ Wkh,
    __half* __restrict__ Wvh, __half* __restrict__ Woh)
{
    const int bx = blockIdx.x;
    const float *W, *A, *Bm, *mvec;
    __half *Whi;
    int row;
    if (bx < 4096)      { W = Wq; A = Aq; Bm = Bq; mvec = mq; Whi = Wqh; row = bx; }
    else if (bx < 5120) { W = Wk; A = Ak; Bm = Bk; mvec = mk; Whi = Wkh; row = bx - 4096; }
    else if (bx < 6144) { W = Wv; A = Av; Bm = Bv; mvec = mv; Whi = Wvh; row = bx - 5120; }
    else                { W = Wo; A = Ao; Bm = Bo; mvec = mo; Whi = Woh; row = bx - 6144; }

    const int tid = threadIdx.x;
    float b[8];
#pragma unroll
    for (int r = 0; r < 8; r++) b[r] = 2.0f * Bm[row * 8 + r];

    const float4* Wrow = (const float4*)(W + (size_t)row * HID);
    float4 w[4];
    float ss = 0.f;
#pragma unroll
    for (int c = 0; c < 4; c++) {
        int col4 = tid + 256 * c;
        float4 wv = Wrow[col4];
#pragma unroll
        for (int r = 0; r < 8; r++) {
            float4 av = ((const float4*)(A + (size_t)r * HID))[col4];
            wv.x += b[r] * av.x; wv.y += b[r] * av.y;
            wv.z += b[r] * av.z; wv.w += b[r] * av.w;
        }
        ss += wv.x * wv.x + wv.y * wv.y + wv.z * wv.z + wv.w * wv.w;
        w[c] = wv;
    }
#pragma unroll
    for (int off = 16; off; off >>= 1)
        ss += __shfl_xor_sync(0xffffffffu, ss, off);

    __shared__ float red[8];
    __shared__ float s_scale;
    if ((tid & 31) == 0) red[tid >> 5] = ss;
    __syncthreads();
    if (tid == 0) {
        float t = 0.f;
#pragma unroll
        for (int i = 0; i < 8; i++) t += red[i];
        s_scale = mvec[row] / (sqrtf(t) + 1e-8f);
    }
    __syncthreads();
    const float sc = s_scale;
#pragma unroll
    for (int c = 0; c < 4; c++) {
        float vv[4] = {w[c].x * sc, w[c].y * sc, w[c].z * sc, w[c].w * sc};
        size_t base = (size_t)row * HID + (tid + 256 * c) * 4;
        __half2 p0 = __floats2half2_rn(vv[0], vv[1]);
        __half2 p1 = __floats2half2_rn(vv[2], vv[3]);
        *(__half2*)&Whi[base] = p0;
        *(__half2*)&Whi[base + 2] = p1;
    }
}

// ---------------- fp32 -> fp16 hi/lo split (x only) ----------------
__global__ __launch_bounds__(256) void split_f16(
    const float* __restrict__ in, __half* __restrict__ hi,
    __half* __restrict__ lo, int n4)
{
    int i = blockIdx.x * 256 + threadIdx.x;
    if (i >= n4) return;
    float4 v = ((const float4*)in)[i];
    float vv[4] = {v.x, v.y, v.z, v.w};
    size_t base = (size_t)i * 4;
#pragma unroll
    for (int e = 0; e < 4; e++) {
        __half h = __float2half_rn(vv[e]);
        hi[base + e] = h;
        lo[base + e] = __float2half_rn(vv[e] - __half2float(h));
    }
}

// ---------------- HMMA mainloop (2-term): acc += ah*bh + al*bh --------------
// 128x128 tile, K=4096, 3-stage cp.async ring, ONE barrier per chunk.
#define STRIDE_B 80
#define TILE_B   (128 * STRIDE_B)
#define KSTAGE_B (3 * TILE_B)            /* {Ah, Al, Bh} = 30720 */
#define GEMM_SMEM (3 * KSTAGE_B)         /* 92160/CTA -> 2 CTAs/SM */

__device__ __forceinline__ void hmma_mainloop2(
    uint32_t sb, const __half* g0, const __half* g1,
    const __half* g2, int tid, float acc[2][8][4])
{
    const int lane = tid & 31, wid = tid >> 5;
    const int wm = wid & 3, wn = wid >> 2;
    const int K = 4096;
    const int ldr = tid >> 2;
    const int ldc = (tid & 3) * 16;

    const uint32_t a_off = (uint32_t)(wm * 32 + (lane & 15)) * STRIDE_B + ((lane >> 4) * 16);
    const uint32_t b_off = (uint32_t)(wn * 64 + (((lane >> 4) << 3) + (lane & 7))) * STRIDE_B
                           + (((lane >> 3) & 1) * 16);

#define LOAD_STAGE(buf, k0) do { \
    uint32_t s0_ = sb + (buf) * KSTAGE_B; \
    const __half* gg_[3] = {g0 + (k0), g1 + (k0), g2 + (k0)}; \
    _Pragma("unroll") \
    for (int t_ = 0; t_ < 3; t_++) { \
        uint32_t st_ = s0_ + t_ * TILE_B; \
        _Pragma("unroll") \
        for (int p_ = 0; p_ < 2; p_++) { \
            int r_ = ldr + p_ * 64; \
            cp16(st_ + (uint32_t)r_ * STRIDE_B + ldc, \
                 (const char*)(gg_[t_] + (size_t)r_ * K) + ldc); \
        } \
    } \
    CP_COMMIT(); \
} while (0)

    LOAD_STAGE(0, 0);
    LOAD_STAGE(1, 32);

    int cst = 0;
    for (int ch = 0; ch < 128; ch++) {
        if (ch + 1 < 128) {
            asm volatile("cp.async.wait_group 1;\n" ::: "memory");
        } else {
            asm volatile("cp.async.wait_group 0;\n" ::: "memory");
        }
        __syncthreads();
        if (ch + 2 < 128) {
            int lst = cst - 1; if (lst < 0) lst += 3;
            LOAD_STAGE(lst, (ch + 2) * 32);
        }
        const uint32_t s0 = sb + cst * KSTAGE_B;
        const uint32_t sAh = s0, sAl = s0 + TILE_B, sBh = s0 + 2 * TILE_B;
#pragma unroll
        for (int k16 = 0; k16 < 2; k16++) {
            const uint32_t kadd = k16 * 32;
            uint32_t ah[2][4], al[2][4], bb[4][4];
            LDSM4(ah[0], sAh + a_off + kadd);
            LDSM4(ah[1], sAh + a_off + 16 * STRIDE_B + kadd);
            LDSM4(al[0], sAl + a_off + kadd);
            LDSM4(al[1], sAl + a_off + 16 * STRIDE_B + kadd);
#pragma unroll
            for (int j = 0; j < 4; j++) LDSM4(bb[j], sBh + b_off + j * 16 * STRIDE_B + kadd);
#pragma unroll
            for (int i = 0; i < 2; i++)
#pragma unroll
                for (int f = 0; f < 8; f++)
                    MMA16816(acc[i][f], ah[i], bb[f >> 1][(f & 1) * 2], bb[f >> 1][(f & 1) * 2 + 1]);
#pragma unroll
            for (int i = 0; i < 2; i++)
#pragma unroll
                for (int f = 0; f < 8; f++)
                    MMA16816(acc[i][f], al[i], bb[f >> 1][(f & 1) * 2], bb[f >> 1][(f & 1) * 2 + 1]);
        }
        cst = (cst == 2) ? 0 : cst + 1;
    }
#undef LOAD_STAGE
}

// ---------------- HMMA mainloop (1-term): acc += a*b ------------------------
#define KSTAGE1_B (2 * TILE_B)           /* {A, B} = 20480 */
#define GEMM1_SMEM (3 * KSTAGE1_B)       /* 61440/CTA -> 2+ CTAs/SM */

__device__ __forceinline__ void hmma_mainloop1(
    uint32_t sb, const __half* g0, const __half* g2, int tid, float acc[2][8][4])
{
    const int lane = tid & 31, wid = tid >> 5;
    const int wm = wid & 3, wn = wid >> 2;
    const int K = 4096;
    const int ldr = tid >> 2;
    const int ldc = (tid & 3) * 16;

    const uint32_t a_off = (uint32_t)(wm * 32 + (lane & 15)) * STRIDE_B + ((lane >> 4) * 16);
    const uint32_t b_off = (uint32_t)(wn * 64 + (((lane >> 4) << 3) + (lane & 7))) * STRIDE_B
                           + (((lane >> 3) & 1) * 16);

#define LOAD_STAGE1(buf, k0) do { \
    uint32_t s0_ = sb + (buf) * KSTAGE1_B; \
    const __half* gg_[2] = {g0 + (k0), g2 + (k0)}; \
    _Pragma("unroll") \
    for (int t_ = 0; t_ < 2; t_++) { \
        uint32_t st_ = s0_ + t_ * TILE_B; \
        _Pragma("unroll") \
        for (int p_ = 0; p_ < 2; p_++) { \
            int r_ = ldr + p_ * 64; \
            cp16(st_ + (uint32_t)r_ * STRIDE_B + ldc, \
                 (const char*)(gg_[t_] + (size_t)r_ * K) + ldc); \
        } \
    } \
    CP_COMMIT(); \
} while (0)

    LOAD_STAGE1(0, 0);
    LOAD_STAGE1(1, 32);

    int cst = 0;
    for (int ch = 0; ch < 128; ch++) {
        if (ch + 1 < 128) {
            asm volatile("cp.async.wait_group 1;\n" ::: "memory");
        } else {
            asm volatile("cp.async.wait_group 0;\n" ::: "memory");
        }
        __syncthreads();
        if (ch + 2 < 128) {
            int lst = cst - 1; if (lst < 0) lst += 3;
            LOAD_STAGE1(lst, (ch + 2) * 32);
        }
        const uint32_t s0 = sb + cst * KSTAGE1_B;
        const uint32_t sA = s0, sB = s0 + TILE_B;
#pragma unroll
        for (int k16 = 0; k16 < 2; k16++) {
            const uint32_t kadd = k16 * 32;
            uint32_t aa[2][4], bb[4][4];
            LDSM4(aa[0], sA + a_off + kadd);
            LDSM4(aa[1], sA + a_off + 16 * STRIDE_B + kadd);
#pragma unroll
            for (int j = 0; j < 4; j++) LDSM4(bb[j], sB + b_off + j * 16 * STRIDE_B + kadd);
#pragma unroll
            for (int i = 0; i < 2; i++)
#pragma unroll
                for (int f = 0; f < 8; f++)
                    MMA16816(acc[i][f], aa[i], bb[f >> 1][(f & 1) * 2], bb[f >> 1][(f & 1) * 2 + 1]);
        }
        cst = (cst == 2) ? 0 : cst + 1;
    }
#undef LOAD_STAGE1
}

// ---------------- merged QKV projection (all 2-term, single fp16 out) -------
__global__ __launch_bounds__(256, 2) void gemm_qkv(
    const __half* __restrict__ xh, const __half* __restrict__ xl,
    const __half* __restrict__ Wqh, const __half* __restrict__ Wkh,
    const __half* __restrict__ Wvh,
    __half* __restrict__ qh, __half* __restrict__ kh, __half* __restrict__ vh)
{
    extern __shared__ char dsm[];
    const uint32_t sb = smem_u32(dsm);
    const int tid = threadIdx.x, lane = tid & 31, wid = tid >> 5;
    const int wm = wid & 3, wn = wid >> 2;
    const int bx = blockIdx.x;
    const int row0 = blockIdx.y << 7;
    const int K = 4096;

    const __half* Bh_;
    __half* Oh;
    int N, col0;
    if (bx < 32)      { Bh_ = Wqh; Oh = qh; N = HID; col0 = bx << 7; }
    else if (bx < 40) { Bh_ = Wkh; Oh = kh; N = KVD; col0 = (bx - 32) << 7; }
    else              { Bh_ = Wvh; Oh = vh; N = KVD; col0 = (bx - 40) << 7; }

    float acc[2][8][4] = {};
    hmma_mainloop2(sb, xh + (size_t)row0 * K, xl + (size_t)row0 * K,
                   Bh_ + (size_t)col0 * K, tid, acc);

#pragma unroll
    for (int i = 0; i < 2; i++) {
        const int mrow = row0 + wm * 32 + i * 16 + (lane >> 2);
#pragma unroll
        for (int f = 0; f < 8; f++) {
            const int col = col0 + wn * 64 + f * 8 + (lane & 3) * 2;
            uint32_t h01 = pack_f16x2(acc[i][f][1], acc[i][f][0]);
            uint32_t h23 = pack_f16x2(acc[i][f][3], acc[i][f][2]);
            *(uint32_t*)&Oh[(size_t)mrow * N + col] = h01;
            *(uint32_t*)&Oh[(size_t)(mrow + 8) * N + col] = h23;
        }
    }
}

// ---------------- output projection (1-term, fp32 out) ----------------
__global__ __launch_bounds__(256, 2) void gemm_o(
    const __half* __restrict__ Ah, const __half* __restrict__ Bh,
    float* __restrict__ C)
{
    extern __shared__ char dsm[];
    const uint32_t sb = smem_u32(dsm);
    const int tid = threadIdx.x, lane = tid & 31, wid = tid >> 5;
    const int wm = wid & 3, wn = wid >> 2;
    const int row0 = blockIdx.y << 7, col0 = blockIdx.x << 7;
    const int K = 4096, N = HID;

    float acc[2][8][4] = {};
    hmma_mainloop1(sb, Ah + (size_t)row0 * K, Bh + (size_t)col0 * K, tid, acc);

#pragma unroll
    for (int i = 0; i < 2; i++) {
        const int mrow = row0 + wm * 32 + i * 16 + (lane >> 2);
#pragma unroll
        for (int f = 0; f < 8; f++) {
            const int col = col0 + wn * 64 + f * 8 + (lane & 3) * 2;
            float2 lo2 = {acc[i][f][0], acc[i][f][1]};
            float2 hi2 = {acc[i][f][2], acc[i][f][3]};
            *(float2*)&C[(size_t)mrow * N + col] = lo2;
            *(float2*)&C[(size_t)(mrow + 8) * N + col] = hi2;
        }
    }
}

// ---------------- HMMA causal flash attention ----------------
// CTA: 128 q-rows (8 warps x 16 rows), key tiles of 64, D=128.
// QK 1-term; PV 2-term (P hi/lo x v single). Single fp16 output.
#define FSTR 272
#define KV_T 17408
#define KV_STAGE (2 * KV_T)
#define FLASH_SMEM (3 * KV_STAGE)

__global__ __launch_bounds__(256, 1) void flash_hmma(
    const __half* __restrict__ qh_g, const __half* __restrict__ kh_g,
    const __half* __restrict__ vh_g,
    __half* __restrict__ oh_g)
{
    extern __shared__ char dsm[];
    const uint32_t sq = smem_u32(dsm);
    const uint32_t sb = sq;
    const int tid = threadIdx.x, lane = tid & 31, w = tid >> 5;
    const int qt = (int)gridDim.x - 1 - (int)blockIdx.x;
    const int h = blockIdx.y, b = blockIdx.z;
    const int kvh = h >> 2;
    const int gr = qt * 128;
    const int nkt = 2 * qt + 2;

    {
        const __half* src = qh_g + ((size_t)(b * SEQ + gr)) * HID + h * 128;
#pragma unroll
        for (int i = 0; i < 8; i++) {
            int idx = tid + i * 256;
            int r = idx >> 4, c = idx & 15;
            cp16(sq + (uint32_t)r * FSTR + c * 16,
                 (const char*)(src + (size_t)r * HID) + c * 16);
        }
        CP_COMMIT();
        asm volatile("cp.async.wait_group 0;\n" ::: "memory");
        __syncthreads();
    }
    uint32_t qhf[8][4];
    {
        const uint32_t qoff = (uint32_t)(w * 16 + (lane & 15)) * FSTR + ((lane >> 4) * 16);
#pragma unroll
        for (int kf = 0; kf < 8; kf++)
            LDSM4(qhf[kf], sq + qoff + kf * 32);
    }
    __syncthreads();

    float o[16][4];
#pragma unroll
    for (int i = 0; i < 16; i++) { o[i][0] = 0.f; o[i][1] = 0.f; o[i][2] = 0.f; o[i][3] = 0.f; }
    float m0 = -1e5f, m1 = -1e5f, l0 = 0.f, l1 = 0.f;

    const uint32_t koff = (uint32_t)(((lane >> 4) << 3) + (lane & 7)) * FSTR + (((lane >> 3) & 1) * 16);
    const uint32_t voff = (uint32_t)((((lane >> 3) & 1) << 3) + (lane & 7)) * FSTR + ((lane >> 4) * 16);

    const __half* kh_p = kh_g + ((size_t)(b * SEQ)) * KVD + kvh * 128;
    const __half* vh_p = vh_g + ((size_t)(b * SEQ)) * KVD + kvh * 128;

#define LOADKV(kt_, buf_) do { \
    uint32_t s0_ = sb + (buf_) * KV_STAGE; \
    const __half* gs_[2] = { \
        kh_p + (size_t)(kt_) * 64 * KVD, vh_p + (size_t)(kt_) * 64 * KVD}; \
    _Pragma("unroll") \
    for (int t_ = 0; t_ < 2; t_++) { \
        _Pragma("unroll") \
        for (int i_ = 0; i_ < 4; i_++) { \
            int idx_ = tid + i_ * 256; \
            int r_ = idx_ >> 4, c_ = idx_ & 15; \
            cp16(s0_ + t_ * KV_T + (uint32_t)r_ * FSTR + c_ * 16, \
                 (const char*)(gs_[t_] + (size_t)r_ * KVD) + c_ * 16); \
        } \
    } \
    CP_COMMIT(); \
} while (0)

    LOADKV(0, 0);
    LOADKV(1, 1);
    const float Cs = 0.08838834764831845f * 1.4426950408889634f;

    int st = 0;
    int st2 = 2;
    for (int kt = 0; kt < nkt; kt++) {
        if (kt + 2 < nkt) {
            asm volatile("cp.async.wait_group 1;\n" ::: "memory");
        } else {
            asm volatile("cp.async.wait_group 0;\n" ::: "memory");
        }
        __syncthreads();
        if (kt + 2 < nkt) LOADKV(kt + 2, st2);

        const uint32_t sKh = sb + st * KV_STAGE;
        const uint32_t sVh = sKh + KV_T;

        float s[8][4];
#pragma unroll
        for (int i = 0; i < 8; i++) { s[i][0] = 0.f; s[i][1] = 0.f; s[i][2] = 0.f; s[i][3] = 0.f; }
#pragma unroll
        for (int kf = 0; kf < 8; kf++) {
#pragma unroll
            for (int nb = 0; nb < 4; nb++) {
                uint32_t bh[4];
                LDSM4(bh, sKh + koff + nb * (16 * FSTR) + kf * 32);
                MMA16816(s[2 * nb], qhf[kf], bh[0], bh[1]);
                MMA16816(s[2 * nb + 1], qhf[kf], bh[2], bh[3]);
            }
        }
#pragma unroll
        for (int nf = 0; nf < 8; nf++) {
            s[nf][0] *= Cs; s[nf][1] *= Cs; s[nf][2] *= Cs; s[nf][3] *= Cs;
        }
        if (kt >= nkt - 2) {
            const int r0 = gr + w * 16 + (lane >> 2);
            const int c0 = kt * 64 + 2 * (lane & 3);
#pragma unroll
            for (int nf = 0; nf < 8; nf++) {
#pragma unroll
                for (int j = 0; j < 4; j++) {
                    int col = c0 + nf * 8 + (j & 1);
                    int row = r0 + (j >> 1) * 8;
                    if (col > row) s[nf][j] = -1e5f;
                }
            }
        }
        float mx0 = -1e30f, mx1 = -1e30f;
#pragma unroll
        for (int nf = 0; nf < 8; nf++) {
            mx0 = fmaxf(mx0, fmaxf(s[nf][0], s[nf][1]));
            mx1 = fmaxf(mx1, fmaxf(s[nf][2], s[nf][3]));
        }
        mx0 = fmaxf(mx0, __shfl_xor_sync(0xffffffffu, mx0, 1));
        mx0 = fmaxf(mx0, __shfl_xor_sync(0xffffffffu, mx0, 2));
        mx1 = fmaxf(mx1, __shfl_xor_sync(0xffffffffu, mx1, 1));
        mx1 = fmaxf(mx1, __shfl_xor_sync(0xffffffffu, mx1, 2));
        const float mn0 = fmaxf(m0, mx0), mn1 = fmaxf(m1, mx1);
        const float cr0 = exp2p(m0 - mn0), cr1 = exp2p(m1 - mn1);
        m0 = mn0; m1 = mn1;
        float rs0 = 0.f, rs1 = 0.f;
#pragma unroll
        for (int nf = 0; nf < 8; nf++) {
            float p0 = exp2p(s[nf][0] - mn0), p1 = exp2p(s[nf][1] - mn0);
            float p2 = exp2p(s[nf][2] - mn1), p3 = exp2p(s[nf][3] - mn1);
            s[nf][0] = p0; s[nf][1] = p1; s[nf][2] = p2; s[nf][3] = p3;
            rs0 += p0 + p1; rs1 += p2 + p3;
        }
        rs0 += __shfl_xor_sync(0xffffffffu, rs0, 1);
        rs0 += __shfl_xor_sync(0xffffffffu, rs0, 2);
        rs1 += __shfl_xor_sync(0xffffffffu, rs1, 1);
        rs1 += __shfl_xor_sync(0xffffffffu, rs1, 2);
        l0 = l0 * cr0 + rs0;
        l1 = l1 * cr1 + rs1;
#pragma unroll
        for (int nf = 0; nf < 16; nf++) {
            o[nf][0] *= cr0; o[nf][1] *= cr0; o[nf][2] *= cr1; o[nf][3] *= cr1;
        }
#pragma unroll
        for (int kb = 0; kb < 4; kb++) {
            uint32_t ph[4], pl[4];
#pragma unroll
            for (int q2 = 0; q2 < 2; q2++) {
                const int nf = 2 * kb + q2;
                uint32_t h01 = pack_f16x2(s[nf][1], s[nf][0]);
                float2 f01 = unpack_f16x2(h01);
                uint32_t l01 = pack_f16x2(s[nf][1] - f01.y, s[nf][0] - f01.x);
                uint32_t h23 = pack_f16x2(s[nf][3], s[nf][2]);
                float2 f23 = unpack_f16x2(h23);
                uint32_t l23 = pack_f16x2(s[nf][3] - f23.y, s[nf][2] - f23.x);
                ph[2 * q2] = h01; ph[2 * q2 + 1] = h23;
                pl[2 * q2] = l01; pl[2 * q2 + 1] = l23;
            }
#pragma unroll
            for (int ng = 0; ng < 8; ng++) {
                uint32_t vv[4];
                LDSM4T(vv, sVh + voff + kb * (16 * FSTR) + ng * 32);
                MMA16816(o[2 * ng], ph, vv[0], vv[1]);
                MMA16816(o[2 * ng + 1], ph, vv[2], vv[3]);
                MMA16816(o[2 * ng], pl, vv[0], vv[1]);
                MMA16816(o[2 * ng + 1], pl, vv[2], vv[3]);
            }
        }
        st = (st == 2) ? 0 : st + 1;
        st2 = (st2 == 2) ? 0 : st2 + 1;
    }
#undef LOADKV

    const float inv0 = 1.f / l0, inv1 = 1.f / l1;
    const size_t row0_ = (size_t)(b * SEQ + gr + w * 16 + (lane >> 2));
    const int colb = h * 128 + 2 * (lane & 3);
#pragma unroll
    for (int nf = 0; nf < 16; nf++) {
        const int col = colb + nf * 8;
        uint32_t h01 = pack_f16x2(o[nf][1] * inv0, o[nf][0] * inv0);
        uint32_t h23 = pack_f16x2(o[nf][3] * inv1, o[nf][2] * inv1);
        *(uint32_t*)&oh_g[row0_ * HID + col] = h01;
        *(uint32_t*)&oh_g[(row0_ + 8) * HID + col] = h23;
    }
}

// ---------------- launch ----------------
extern "C" void kernel_launch(void* const* d_in, const int* in_sizes, int n_in,
                              void* d_out, int out_size)
{
    const float* x  = (const float*)d_in[0];
    const float* Wq = (const float*)d_in[2];
    const float* Aq = (const float*)d_in[3];
    const float* Bq = (const float*)d_in[4];
    const float* mq = (const float*)d_in[5];
    const float* Wk = (const float*)d_in[6];
    const float* Ak = (const float*)d_in[7];
    const float* Bk = (const float*)d_in[8];
    const float* mk = (const float*)d_in[9];
    const float* Wv = (const float*)d_in[10];
    const float* Av = (const float*)d_in[11];
    const float* Bv = (const float*)d_in[12];
    const float* mv = (const float*)d_in[13];
    const float* Wo = (const float*)d_in[14];
    const float* Ao = (const float*)d_in[15];
    const float* Bo = (const float*)d_in[16];
    const float* mo = (const float*)d_in[17];

    __half *xh, *xl, *Wqh, *Wkh, *Wvh, *Woh;
    __half *qh, *kh, *vh, *ath;
    cudaGetSymbolAddress((void**)&xh, g_xh);   cudaGetSymbolAddress((void**)&xl, g_xl);
    cudaGetSymbolAddress((void**)&Wqh, g_Wqh); cudaGetSymbolAddress((void**)&Wkh, g_Wkh);
    cudaGetSymbolAddress((void**)&Wvh, g_Wvh); cudaGetSymbolAddress((void**)&Woh, g_Woh);
    cudaGetSymbolAddress((void**)&qh, g_qh);   cudaGetSymbolAddress((void**)&kh, g_kh);
    cudaGetSymbolAddress((void**)&vh, g_vh);
    cudaGetSymbolAddress((void**)&ath, g_ath);

    cudaFuncSetAttribute(gemm_qkv, cudaFuncAttributeMaxDynamicSharedMemorySize, GEMM_SMEM);
    cudaFuncSetAttribute(gemm_o, cudaFuncAttributeMaxDynamicSharedMemorySize, GEMM1_SMEM);
    cudaFuncSetAttribute(flash_hmma, cudaFuncAttributeMaxDynamicSharedMemorySize, FLASH_SMEM);

    // 1) DoRA effective weights (one launch, single fp16 out)
    dora_all<<<10240, 256>>>(Wq, Aq, Bq, mq, Wk, Ak, Bk, mk,
                             Wv, Av, Bv, mv, Wo, Ao, Bo, mo,
                             Wqh, Wkh, Wvh, Woh);

    // 2) split x
    split_f16<<<(TOK * HID / 4 + 255) / 256, 256>>>(x, xh, xl, TOK * HID / 4);

    // 3) merged q/k/v projections (2-term, single fp16 out)
    gemm_qkv<<<dim3(48, TOK / 128), 256, GEMM_SMEM>>>(
        xh, xl, Wqh, Wkh, Wvh, qh, kh, vh);

    // 4) causal attention (HMMA) -> single fp16 attention output
    flash_hmma<<<dim3(SEQ / 128, 32, 2), 256, FLASH_SMEM>>>(qh, kh, vh, ath);

    // 5) output projection (1-term) -> d_out (fp32)
    gemm_o<<<dim3(HID / 128, TOK / 128), 256, GEMM1_SMEM>>>(ath, Woh, (float*)d_out);
}

// round 12
// speedup vs baseline: 2.1362x; 1.0817x over previous
#include <cuda_runtime.h>
#include <cuda_fp16.h>
#include <cstdint>
#include <math.h>

#define HID 4096
#define KVD 1024
#define TOK 4096   /* B*S */
#define SEQ 2048

// ---------------- device scratch ----------------
__device__ __half g_xh[TOK * HID];
__device__ __half g_xl[TOK * HID];
__device__ __half g_Wqh[HID * HID];
__device__ __half g_Wkh[KVD * HID];
__device__ __half g_Wvh[KVD * HID];
__device__ __half g_Woh[HID * HID];
__device__ __half g_qh[TOK * HID];
__device__ __half g_kh[TOK * KVD];
__device__ __half g_vh[TOK * KVD];
__device__ __half g_ath[TOK * HID];

// ---------------- helpers ----------------
__device__ __forceinline__ uint32_t smem_u32(const void* p) {
    uint32_t a;
    asm("{ .reg .u64 t; cvta.to.shared.u64 t, %1; cvt.u32.u64 %0, t; }" : "=r"(a) : "l"(p));
    return a;
}
__device__ __forceinline__ void cp16(uint32_t dst, const void* src) {
    asm volatile("cp.async.cg.shared.global [%0], [%1], 16;\n" :: "r"(dst), "l"(src) : "memory");
}
#define CP_COMMIT() asm volatile("cp.async.commit_group;\n" ::: "memory")

#define LDSM4(r, a) \
    asm volatile("ldmatrix.sync.aligned.m8n8.x4.shared.b16 {%0,%1,%2,%3}, [%4];" \
                 : "=r"((r)[0]), "=r"((r)[1]), "=r"((r)[2]), "=r"((r)[3]) : "r"(a))
#define LDSM4T(r, a) \
    asm volatile("ldmatrix.sync.aligned.m8n8.x4.trans.shared.b16 {%0,%1,%2,%3}, [%4];" \
                 : "=r"((r)[0]), "=r"((r)[1]), "=r"((r)[2]), "=r"((r)[3]) : "r"(a))

#define MMA16816(d, a, b0, b1) \
    asm volatile("mma.sync.aligned.m16n8k16.row.col.f32.f16.f16.f32 " \
                 "{%0,%1,%2,%3}, {%4,%5,%6,%7}, {%8,%9}, {%0,%1,%2,%3};" \
                 : "+f"((d)[0]), "+f"((d)[1]), "+f"((d)[2]), "+f"((d)[3]) \
                 : "r"((a)[0]), "r"((a)[1]), "r"((a)[2]), "r"((a)[3]), "r"(b0), "r"(b1))

__device__ __forceinline__ uint32_t pack_f16x2(float hi_, float lo_) {
    __half2 h = __floats2half2_rn(lo_, hi_);
    return *(uint32_t*)&h;
}
__device__ __forceinline__ float2 unpack_f16x2(uint32_t u) {
    __half2 h = *(__half2*)&u;
    float2 r;
    r.x = __low2float(h);
    r.y = __high2float(h);
    return r;
}
// fast exp2 on FMA pipe (no MUFU). x <= 0 expected; rel err ~2.4e-6.
__device__ __forceinline__ float exp2p(float x) {
    x = fmaxf(x, -120.f);
    int e = __float2int_rn(x);
    float f = x - (float)e;
    float p = 1.3333558e-3f;
    p = fmaf(p, f, 9.6181291e-3f);
    p = fmaf(p, f, 5.5504109e-2f);
    p = fmaf(p, f, 2.4022651e-1f);
    p = fmaf(p, f, 6.9314718e-1f);
    p = fmaf(p, f, 1.0f);
    return p * __int_as_float((uint32_t)(e + 127) << 23);
}

// ---------------- DoRA weight materialization (all 4 weights, one launch) ----
__global__ __launch_bounds__(256) void dora_all(
    const float* __restrict__ Wq, const float* __restrict__ Aq,
    const float* __restrict__ Bq, const float* __restrict__ mq,
    const float* __restrict__ Wk, const float* __restrict__ Ak,
    const float* __restrict__ Bk, const float* __restrict__ mk,
    const float* __restrict__ Wv, const float* __restrict__ Av,
    const float* __restrict__ Bv, const float* __restrict__ mv,
    const float* __restrict__ Wo, const float* __restrict__ Ao,
    const float* __restrict__ Bo, const float* __restrict__ mo,
    __half* __restrict__ Wqh, __half* __restrict__ Wkh,
    __half* __restrict__ Wvh, __half* __restrict__ Woh)
{
    const int bx = blockIdx.x;
    const float *W, *A, *Bm, *mvec;
    __half *Whi;
    int row;
    if (bx < 4096)      { W = Wq; A = Aq; Bm = Bq; mvec = mq; Whi = Wqh; row = bx; }
    else if (bx < 5120) { W = Wk; A = Ak; Bm = Bk; mvec = mk; Whi = Wkh; row = bx - 4096; }
    else if (bx < 6144) { W = Wv; A = Av; Bm = Bv; mvec = mv; Whi = Wvh; row = bx - 5120; }
    else                { W = Wo; A = Ao; Bm = Bo; mvec = mo; Whi = Woh; row = bx - 6144; }

    const int tid = threadIdx.x;
    float b[8];
#pragma unroll
    for (int r = 0; r < 8; r++) b[r] = 2.0f * Bm[row * 8 + r];

    const float4* Wrow = (const float4*)(W + (size_t)row * HID);
    float4 w[4];
    float ss = 0.f;
#pragma unroll
    for (int c = 0; c < 4; c++) {
        int col4 = tid + 256 * c;
        float4 wv = Wrow[col4];
#pragma unroll
        for (int r = 0; r < 8; r++) {
            float4 av = ((const float4*)(A + (size_t)r * HID))[col4];
            wv.x += b[r] * av.x; wv.y += b[r] * av.y;
            wv.z += b[r] * av.z; wv.w += b[r] * av.w;
        }
        ss += wv.x * wv.x + wv.y * wv.y + wv.z * wv.z + wv.w * wv.w;
        w[c] = wv;
    }
#pragma unroll
    for (int off = 16; off; off >>= 1)
        ss += __shfl_xor_sync(0xffffffffu, ss, off);

    __shared__ float red[8];
    __shared__ float s_scale;
    if ((tid & 31) == 0) red[tid >> 5] = ss;
    __syncthreads();
    if (tid == 0) {
        float t = 0.f;
#pragma unroll
        for (int i = 0; i < 8; i++) t += red[i];
        s_scale = mvec[row] / (sqrtf(t) + 1e-8f);
    }
    __syncthreads();
    const float sc = s_scale;
#pragma unroll
    for (int c = 0; c < 4; c++) {
        float vv[4] = {w[c].x * sc, w[c].y * sc, w[c].z * sc, w[c].w * sc};
        size_t base = (size_t)row * HID + (tid + 256 * c) * 4;
        __half2 p0 = __floats2half2_rn(vv[0], vv[1]);
        __half2 p1 = __floats2half2_rn(vv[2], vv[3]);
        *(__half2*)&Whi[base] = p0;
        *(__half2*)&Whi[base + 2] = p1;
    }
}

// ---------------- fp32 -> fp16 hi/lo split (x only) ----------------
__global__ __launch_bounds__(256) void split_f16(
    const float* __restrict__ in, __half* __restrict__ hi,
    __half* __restrict__ lo, int n4)
{
    int i = blockIdx.x * 256 + threadIdx.x;
    if (i >= n4) return;
    float4 v = ((const float4*)in)[i];
    float vv[4] = {v.x, v.y, v.z, v.w};
    size_t base = (size_t)i * 4;
#pragma unroll
    for (int e = 0; e < 4; e++) {
        __half h = __float2half_rn(vv[e]);
        hi[base + e] = h;
        lo[base + e] = __float2half_rn(vv[e] - __half2float(h));
    }
}

// ============ GEMM mainloops: 128x128 tile, K=4096, K-chunk 64 ==============
// Row stride 144B (128B data + 16B pad): cp.async 16B-aligned, ldmatrix
// conflict-free (row step = 4 banks). 2-stage double buffer, ONE barrier
// per chunk, 1-chunk lookahead.
#define GSTR 144
#define GTILE_B (128 * GSTR)             /* 18432 */
#define KST2_B (3 * GTILE_B)             /* {Ah, Al, Bh} = 55296 */
#define GEMM_SMEM (2 * KST2_B)           /* 110592/CTA -> 2 CTAs/SM */
#define KST1_B (2 * GTILE_B)             /* {A, B} = 36864 */
#define GEMM1_SMEM (2 * KST1_B)          /* 73728/CTA */

// ---- 2-term: acc += ah*bh + al*bh
__device__ __forceinline__ void hmma_mainloop2(
    uint32_t sb, const __half* g0, const __half* g1,
    const __half* g2, int tid, float acc[2][8][4])
{
    const int lane = tid & 31, wid = tid >> 5;
    const int wm = wid & 3, wn = wid >> 2;
    const int K = 4096;
    const int ldr = tid >> 3;            /* 0..31 */
    const int ldc = (tid & 7) * 16;      /* byte col in 128B row */

    const uint32_t a_off = (uint32_t)(wm * 32 + (lane & 15)) * GSTR + ((lane >> 4) * 16);
    const uint32_t b_off = (uint32_t)(wn * 64 + (((lane >> 4) << 3) + (lane & 7))) * GSTR
                           + (((lane >> 3) & 1) * 16);

#define LOAD_STAGE(buf, k0) do { \
    uint32_t s0_ = sb + (buf) * KST2_B; \
    const __half* gg_[3] = {g0 + (k0), g1 + (k0), g2 + (k0)}; \
    _Pragma("unroll") \
    for (int t_ = 0; t_ < 3; t_++) { \
        uint32_t st_ = s0_ + t_ * GTILE_B; \
        _Pragma("unroll") \
        for (int p_ = 0; p_ < 4; p_++) { \
            int r_ = ldr + p_ * 32; \
            cp16(st_ + (uint32_t)r_ * GSTR + ldc, \
                 (const char*)(gg_[t_] + (size_t)r_ * K) + ldc); \
        } \
    } \
    CP_COMMIT(); \
} while (0)

    LOAD_STAGE(0, 0);
    for (int ch = 0; ch < 64; ch++) {
        asm volatile("cp.async.wait_group 0;\n" ::: "memory");
        __syncthreads();
        if (ch + 1 < 64) LOAD_STAGE((ch + 1) & 1, (ch + 1) * 64);

        const uint32_t s0 = sb + (ch & 1) * KST2_B;
        const uint32_t sAh = s0, sAl = s0 + GTILE_B, sBh = s0 + 2 * GTILE_B;
#pragma unroll
        for (int k16 = 0; k16 < 4; k16++) {
            const uint32_t kadd = k16 * 32;
            uint32_t ah[2][4], al[2][4], bb[4][4];
            LDSM4(ah[0], sAh + a_off + kadd);
            LDSM4(ah[1], sAh + a_off + 16 * GSTR + kadd);
            LDSM4(al[0], sAl + a_off + kadd);
            LDSM4(al[1], sAl + a_off + 16 * GSTR + kadd);
#pragma unroll
            for (int j = 0; j < 4; j++) LDSM4(bb[j], sBh + b_off + j * 16 * GSTR + kadd);
#pragma unroll
            for (int i = 0; i < 2; i++)
#pragma unroll
                for (int f = 0; f < 8; f++)
                    MMA16816(acc[i][f], ah[i], bb[f >> 1][(f & 1) * 2], bb[f >> 1][(f & 1) * 2 + 1]);
#pragma unroll
            for (int i = 0; i < 2; i++)
#pragma unroll
                for (int f = 0; f < 8; f++)
                    MMA16816(acc[i][f], al[i], bb[f >> 1][(f & 1) * 2], bb[f >> 1][(f & 1) * 2 + 1]);
        }
    }
#undef LOAD_STAGE
}

// ---- 1-term: acc += a*b
__device__ __forceinline__ void hmma_mainloop1(
    uint32_t sb, const __half* g0, const __half* g2, int tid, float acc[2][8][4])
{
    const int lane = tid & 31, wid = tid >> 5;
    const int wm = wid & 3, wn = wid >> 2;
    const int K = 4096;
    const int ldr = tid >> 3;
    const int ldc = (tid & 7) * 16;

    const uint32_t a_off = (uint32_t)(wm * 32 + (lane & 15)) * GSTR + ((lane >> 4) * 16);
    const uint32_t b_off = (uint32_t)(wn * 64 + (((lane >> 4) << 3) + (lane & 7))) * GSTR
                           + (((lane >> 3) & 1) * 16);

#define LOAD_STAGE1(buf, k0) do { \
    uint32_t s0_ = sb + (buf) * KST1_B; \
    const __half* gg_[2] = {g0 + (k0), g2 + (k0)}; \
    _Pragma("unroll") \
    for (int t_ = 0; t_ < 2; t_++) { \
        uint32_t st_ = s0_ + t_ * GTILE_B; \
        _Pragma("unroll") \
        for (int p_ = 0; p_ < 4; p_++) { \
            int r_ = ldr + p_ * 32; \
            cp16(st_ + (uint32_t)r_ * GSTR + ldc, \
                 (const char*)(gg_[t_] + (size_t)r_ * K) + ldc); \
        } \
    } \
    CP_COMMIT(); \
} while (0)

    LOAD_STAGE1(0, 0);
    for (int ch = 0; ch < 64; ch++) {
        asm volatile("cp.async.wait_group 0;\n" ::: "memory");
        __syncthreads();
        if (ch + 1 < 64) LOAD_STAGE1((ch + 1) & 1, (ch + 1) * 64);

        const uint32_t s0 = sb + (ch & 1) * KST1_B;
        const uint32_t sA = s0, sB = s0 + GTILE_B;
#pragma unroll
        for (int k16 = 0; k16 < 4; k16++) {
            const uint32_t kadd = k16 * 32;
            uint32_t aa[2][4], bb[4][4];
            LDSM4(aa[0], sA + a_off + kadd);
            LDSM4(aa[1], sA + a_off + 16 * GSTR + kadd);
#pragma unroll
            for (int j = 0; j < 4; j++) LDSM4(bb[j], sB + b_off + j * 16 * GSTR + kadd);
#pragma unroll
            for (int i = 0; i < 2; i++)
#pragma unroll
                for (int f = 0; f < 8; f++)
                    MMA16816(acc[i][f], aa[i], bb[f >> 1][(f & 1) * 2], bb[f >> 1][(f & 1) * 2 + 1]);
        }
    }
#undef LOAD_STAGE1
}

// ---------------- merged QKV projection (all 2-term, single fp16 out) -------
__global__ __launch_bounds__(256, 2) void gemm_qkv(
    const __half* __restrict__ xh, const __half* __restrict__ xl,
    const __half* __restrict__ Wqh, const __half* __restrict__ Wkh,
    const __half* __restrict__ Wvh,
    __half* __restrict__ qh, __half* __restrict__ kh, __half* __restrict__ vh)
{
    extern __shared__ char dsm[];
    const uint32_t sb = smem_u32(dsm);
    const int tid = threadIdx.x, lane = tid & 31, wid = tid >> 5;
    const int wm = wid & 3, wn = wid >> 2;
    const int bx = blockIdx.x;
    const int row0 = blockIdx.y << 7;
    const int K = 4096;

    const __half* Bh_;
    __half* Oh;
    int N, col0;
    if (bx < 32)      { Bh_ = Wqh; Oh = qh; N = HID; col0 = bx << 7; }
    else if (bx < 40) { Bh_ = Wkh; Oh = kh; N = KVD; col0 = (bx - 32) << 7; }
    else              { Bh_ = Wvh; Oh = vh; N = KVD; col0 = (bx - 40) << 7; }

    float acc[2][8][4] = {};
    hmma_mainloop2(sb, xh + (size_t)row0 * K, xl + (size_t)row0 * K,
                   Bh_ + (size_t)col0 * K, tid, acc);

#pragma unroll
    for (int i = 0; i < 2; i++) {
        const int mrow = row0 + wm * 32 + i * 16 + (lane >> 2);
#pragma unroll
        for (int f = 0; f < 8; f++) {
            const int col = col0 + wn * 64 + f * 8 + (lane & 3) * 2;
            uint32_t h01 = pack_f16x2(acc[i][f][1], acc[i][f][0]);
            uint32_t h23 = pack_f16x2(acc[i][f][3], acc[i][f][2]);
            *(uint32_t*)&Oh[(size_t)mrow * N + col] = h01;
            *(uint32_t*)&Oh[(size_t)(mrow + 8) * N + col] = h23;
        }
    }
}

// ---------------- output projection (1-term, fp32 out) ----------------
__global__ __launch_bounds__(256, 2) void gemm_o(
    const __half* __restrict__ Ah, const __half* __restrict__ Bh,
    float* __restrict__ C)
{
    extern __shared__ char dsm[];
    const uint32_t sb = smem_u32(dsm);
    const int tid = threadIdx.x, lane = tid & 31, wid = tid >> 5;
    const int wm = wid & 3, wn = wid >> 2;
    const int row0 = blockIdx.y << 7, col0 = blockIdx.x << 7;
    const int K = 4096, N = HID;

    float acc[2][8][4] = {};
    hmma_mainloop1(sb, Ah + (size_t)row0 * K, Bh + (size_t)col0 * K, tid, acc);

#pragma unroll
    for (int i = 0; i < 2; i++) {
        const int mrow = row0 + wm * 32 + i * 16 + (lane >> 2);
#pragma unroll
        for (int f = 0; f < 8; f++) {
            const int col = col0 + wn * 64 + f * 8 + (lane & 3) * 2;
            float2 lo2 = {acc[i][f][0], acc[i][f][1]};
            float2 hi2 = {acc[i][f][2], acc[i][f][3]};
            *(float2*)&C[(size_t)mrow * N + col] = lo2;
            *(float2*)&C[(size_t)(mrow + 8) * N + col] = hi2;
        }
    }
}

// ---------------- HMMA causal flash attention ----------------
// CTA: 128 q-rows (8 warps x 16 rows), key tiles of 64, D=128.
// QK 1-term; PV 2-term (P hi/lo x v single). Single fp16 output.
#define FSTR 272
#define KV_T 17408
#define KV_STAGE (2 * KV_T)
#define FLASH_SMEM (3 * KV_STAGE)

__global__ __launch_bounds__(256, 1) void flash_hmma(
    const __half* __restrict__ qh_g, const __half* __restrict__ kh_g,
    const __half* __restrict__ vh_g,
    __half* __restrict__ oh_g)
{
    extern __shared__ char dsm[];
    const uint32_t sq = smem_u32(dsm);
    const uint32_t sb = sq;
    const int tid = threadIdx.x, lane = tid & 31, w = tid >> 5;
    const int qt = (int)gridDim.x - 1 - (int)blockIdx.x;
    const int h = blockIdx.y, b = blockIdx.z;
    const int kvh = h >> 2;
    const int gr = qt * 128;
    const int nkt = 2 * qt + 2;

    {
        const __half* src = qh_g + ((size_t)(b * SEQ + gr)) * HID + h * 128;
#pragma unroll
        for (int i = 0; i < 8; i++) {
            int idx = tid + i * 256;
            int r = idx >> 4, c = idx & 15;
            cp16(sq + (uint32_t)r * FSTR + c * 16,
                 (const char*)(src + (size_t)r * HID) + c * 16);
        }
        CP_COMMIT();
        asm volatile("cp.async.wait_group 0;\n" ::: "memory");
        __syncthreads();
    }
    uint32_t qhf[8][4];
    {
        const uint32_t qoff = (uint32_t)(w * 16 + (lane & 15)) * FSTR + ((lane >> 4) * 16);
#pragma unroll
        for (int kf = 0; kf < 8; kf++)
            LDSM4(qhf[kf], sq + qoff + kf * 32);
    }
    __syncthreads();

    float o[16][4];
#pragma unroll
    for (int i = 0; i < 16; i++) { o[i][0] = 0.f; o[i][1] = 0.f; o[i][2] = 0.f; o[i][3] = 0.f; }
    float m0 = -1e5f, m1 = -1e5f, l0 = 0.f, l1 = 0.f;

    const uint32_t koff = (uint32_t)(((lane >> 4) << 3) + (lane & 7)) * FSTR + (((lane >> 3) & 1) * 16);
    const uint32_t voff = (uint32_t)((((lane >> 3) & 1) << 3) + (lane & 7)) * FSTR + ((lane >> 4) * 16);

    const __half* kh_p = kh_g + ((size_t)(b * SEQ)) * KVD + kvh * 128;
    const __half* vh_p = vh_g + ((size_t)(b * SEQ)) * KVD + kvh * 128;

#define LOADKV(kt_, buf_) do { \
    uint32_t s0_ = sb + (buf_) * KV_STAGE; \
    const __half* gs_[2] = { \
        kh_p + (size_t)(kt_) * 64 * KVD, vh_p + (size_t)(kt_) * 64 * KVD}; \
    _Pragma("unroll") \
    for (int t_ = 0; t_ < 2; t_++) { \
        _Pragma("unroll") \
        for (int i_ = 0; i_ < 4; i_++) { \
            int idx_ = tid + i_ * 256; \
            int r_ = idx_ >> 4, c_ = idx_ & 15; \
            cp16(s0_ + t_ * KV_T + (uint32_t)r_ * FSTR + c_ * 16, \
                 (const char*)(gs_[t_] + (size_t)r_ * KVD) + c_ * 16); \
        } \
    } \
    CP_COMMIT(); \
} while (0)

    LOADKV(0, 0);
    LOADKV(1, 1);
    const float Cs = 0.08838834764831845f * 1.4426950408889634f;

    int st = 0;
    int st2 = 2;
    for (int kt = 0; kt < nkt; kt++) {
        if (kt + 2 < nkt) {
            asm volatile("cp.async.wait_group 1;\n" ::: "memory");
        } else {
            asm volatile("cp.async.wait_group 0;\n" ::: "memory");
        }
        __syncthreads();
        if (kt + 2 < nkt) LOADKV(kt + 2, st2);

        const uint32_t sKh = sb + st * KV_STAGE;
        const uint32_t sVh = sKh + KV_T;

        float s[8][4];
#pragma unroll
        for (int i = 0; i < 8; i++) { s[i][0] = 0.f; s[i][1] = 0.f; s[i][2] = 0.f; s[i][3] = 0.f; }
#pragma unroll
        for (int kf = 0; kf < 8; kf++) {
#pragma unroll
            for (int nb = 0; nb < 4; nb++) {
                uint32_t bh[4];
                LDSM4(bh, sKh + koff + nb * (16 * FSTR) + kf * 32);
                MMA16816(s[2 * nb], qhf[kf], bh[0], bh[1]);
                MMA16816(s[2 * nb + 1], qhf[kf], bh[2], bh[3]);
            }
        }
#pragma unroll
        for (int nf = 0; nf < 8; nf++) {
            s[nf][0] *= Cs; s[nf][1] *= Cs; s[nf][2] *= Cs; s[nf][3] *= Cs;
        }
        if (kt >= nkt - 2) {
            const int r0 = gr + w * 16 + (lane >> 2);
            const int c0 = kt * 64 + 2 * (lane & 3);
#pragma unroll
            for (int nf = 0; nf < 8; nf++) {
#pragma unroll
                for (int j = 0; j < 4; j++) {
                    int col = c0 + nf * 8 + (j & 1);
                    int row = r0 + (j >> 1) * 8;
                    if (col > row) s[nf][j] = -1e5f;
                }
            }
        }
        float mx0 = -1e30f, mx1 = -1e30f;
#pragma unroll
        for (int nf = 0; nf < 8; nf++) {
            mx0 = fmaxf(mx0, fmaxf(s[nf][0], s[nf][1]));
            mx1 = fmaxf(mx1, fmaxf(s[nf][2], s[nf][3]));
        }
        mx0 = fmaxf(mx0, __shfl_xor_sync(0xffffffffu, mx0, 1));
        mx0 = fmaxf(mx0, __shfl_xor_sync(0xffffffffu, mx0, 2));
        mx1 = fmaxf(mx1, __shfl_xor_sync(0xffffffffu, mx1, 1));
        mx1 = fmaxf(mx1, __shfl_xor_sync(0xffffffffu, mx1, 2));
        const float mn0 = fmaxf(m0, mx0), mn1 = fmaxf(m1, mx1);
        const float cr0 = exp2p(m0 - mn0), cr1 = exp2p(m1 - mn1);
        m0 = mn0; m1 = mn1;
        float rs0 = 0.f, rs1 = 0.f;
#pragma unroll
        for (int nf = 0; nf < 8; nf++) {
            float p0 = exp2p(s[nf][0] - mn0), p1 = exp2p(s[nf][1] - mn0);
            float p2 = exp2p(s[nf][2] - mn1), p3 = exp2p(s[nf][3] - mn1);
            s[nf][0] = p0; s[nf][1] = p1; s[nf][2] = p2; s[nf][3] = p3;
            rs0 += p0 + p1; rs1 += p2 + p3;
        }
        rs0 += __shfl_xor_sync(0xffffffffu, rs0, 1);
        rs0 += __shfl_xor_sync(0xffffffffu, rs0, 2);
        rs1 += __shfl_xor_sync(0xffffffffu, rs1, 1);
        rs1 += __shfl_xor_sync(0xffffffffu, rs1, 2);
        l0 = l0 * cr0 + rs0;
        l1 = l1 * cr1 + rs1;
#pragma unroll
        for (int nf = 0; nf < 16; nf++) {
            o[nf][0] *= cr0; o[nf][1] *= cr0; o[nf][2] *= cr1; o[nf][3] *= cr1;
        }
#pragma unroll
        for (int kb = 0; kb < 4; kb++) {
            uint32_t ph[4], pl[4];
#pragma unroll
            for (int q2 = 0; q2 < 2; q2++) {
                const int nf = 2 * kb + q2;
                uint32_t h01 = pack_f16x2(s[nf][1], s[nf][0]);
                float2 f01 = unpack_f16x2(h01);
                uint32_t l01 = pack_f16x2(s[nf][1] - f01.y, s[nf][0] - f01.x);
                uint32_t h23 = pack_f16x2(s[nf][3], s[nf][2]);
                float2 f23 = unpack_f16x2(h23);
                uint32_t l23 = pack_f16x2(s[nf][3] - f23.y, s[nf][2] - f23.x);
                ph[2 * q2] = h01; ph[2 * q2 + 1] = h23;
                pl[2 * q2] = l01; pl[2 * q2 + 1] = l23;
            }
#pragma unroll
            for (int ng = 0; ng < 8; ng++) {
                uint32_t vv[4];
                LDSM4T(vv, sVh + voff + kb * (16 * FSTR) + ng * 32);
                MMA16816(o[2 * ng], ph, vv[0], vv[1]);
                MMA16816(o[2 * ng + 1], ph, vv[2], vv[3]);
                MMA16816(o[2 * ng], pl, vv[0], vv[1]);
                MMA16816(o[2 * ng + 1], pl, vv[2], vv[3]);
            }
        }
        st = (st == 2) ? 0 : st + 1;
        st2 = (st2 == 2) ? 0 : st2 + 1;
    }
#undef LOADKV

    const float inv0 = 1.f / l0, inv1 = 1.f / l1;
    const size_t row0_ = (size_t)(b * SEQ + gr + w * 16 + (lane >> 2));
    const int colb = h * 128 + 2 * (lane & 3);
#pragma unroll
    for (int nf = 0; nf < 16; nf++) {
        const int col = colb + nf * 8;
        uint32_t h01 = pack_f16x2(o[nf][1] * inv0, o[nf][0] * inv0);
        uint32_t h23 = pack_f16x2(o[nf][3] * inv1, o[nf][2] * inv1);
        *(uint32_t*)&oh_g[row0_ * HID + col] = h01;
        *(uint32_t*)&oh_g[(row0_ + 8) * HID + col] = h23;
    }
}

// ---------------- launch ----------------
extern "C" void kernel_launch(void* const* d_in, const int* in_sizes, int n_in,
                              void* d_out, int out_size)
{
    const float* x  = (const float*)d_in[0];
    const float* Wq = (const float*)d_in[2];
    const float* Aq = (const float*)d_in[3];
    const float* Bq = (const float*)d_in[4];
    const float* mq = (const float*)d_in[5];
    const float* Wk = (const float*)d_in[6];
    const float* Ak = (const float*)d_in[7];
    const float* Bk = (const float*)d_in[8];
    const float* mk = (const float*)d_in[9];
    const float* Wv = (const float*)d_in[10];
    const float* Av = (const float*)d_in[11];
    const float* Bv = (const float*)d_in[12];
    const float* mv = (const float*)d_in[13];
    const float* Wo = (const float*)d_in[14];
    const float* Ao = (const float*)d_in[15];
    const float* Bo = (const float*)d_in[16];
    const float* mo = (const float*)d_in[17];

    __half *xh, *xl, *Wqh, *Wkh, *Wvh, *Woh;
    __half *qh, *kh, *vh, *ath;
    cudaGetSymbolAddress((void**)&xh, g_xh);   cudaGetSymbolAddress((void**)&xl, g_xl);
    cudaGetSymbolAddress((void**)&Wqh, g_Wqh); cudaGetSymbolAddress((void**)&Wkh, g_Wkh);
    cudaGetSymbolAddress((void**)&Wvh, g_Wvh); cudaGetSymbolAddress((void**)&Woh, g_Woh);
    cudaGetSymbolAddress((void**)&qh, g_qh);   cudaGetSymbolAddress((void**)&kh, g_kh);
    cudaGetSymbolAddress((void**)&vh, g_vh);
    cudaGetSymbolAddress((void**)&ath, g_ath);

    cudaFuncSetAttribute(gemm_qkv, cudaFuncAttributeMaxDynamicSharedMemorySize, GEMM_SMEM);
    cudaFuncSetAttribute(gemm_o, cudaFuncAttributeMaxDynamicSharedMemorySize, GEMM1_SMEM);
    cudaFuncSetAttribute(flash_hmma, cudaFuncAttributeMaxDynamicSharedMemorySize, FLASH_SMEM);

    // 1) DoRA effective weights (one launch, single fp16 out)
    dora_all<<<10240, 256>>>(Wq, Aq, Bq, mq, Wk, Ak, Bk, mk,
                             Wv, Av, Bv, mv, Wo, Ao, Bo, mo,
                             Wqh, Wkh, Wvh, Woh);

    // 2) split x
    split_f16<<<(TOK * HID / 4 + 255) / 256, 256>>>(x, xh, xl, TOK * HID / 4);

    // 3) merged q/k/v projections (2-term, single fp16 out)
    gemm_qkv<<<dim3(48, TOK / 128), 256, GEMM_SMEM>>>(
        xh, xl, Wqh, Wkh, Wvh, qh, kh, vh);

    // 4) causal attention (HMMA) -> single fp16 attention output
    flash_hmma<<<dim3(SEQ / 128, 32, 2), 256, FLASH_SMEM>>>(qh, kh, vh, ath);

    // 5) output projection (1-term) -> d_out (fp32)
    gemm_o<<<dim3(HID / 128, TOK / 128), 256, GEMM1_SMEM>>>(ath, Woh, (float*)d_out);
}

// round 13
// speedup vs baseline: 2.2071x; 1.0332x over previous
#include <cuda_runtime.h>
#include <cuda_fp16.h>
#include <cstdint>
#include <math.h>

#define HID 4096
#define KVD 1024
#define TOK 4096   /* B*S */
#define SEQ 2048

// ---------------- device scratch ----------------
__device__ __half g_xh[TOK * HID];
__device__ __half g_xl[TOK * HID];
__device__ __half g_Wqh[HID * HID];
__device__ __half g_Wkh[KVD * HID];
__device__ __half g_Wvh[KVD * HID];
__device__ __half g_Woh[HID * HID];
__device__ __half g_qh[TOK * HID];
__device__ __half g_kh[TOK * KVD];
__device__ __half g_vh[TOK * KVD];
__device__ __half g_ath[TOK * HID];

// ---------------- helpers ----------------
__device__ __forceinline__ uint32_t smem_u32(const void* p) {
    uint32_t a;
    asm("{ .reg .u64 t; cvta.to.shared.u64 t, %1; cvt.u32.u64 %0, t; }" : "=r"(a) : "l"(p));
    return a;
}
__device__ __forceinline__ void cp16(uint32_t dst, const void* src) {
    asm volatile("cp.async.cg.shared.global [%0], [%1], 16;\n" :: "r"(dst), "l"(src) : "memory");
}
#define CP_COMMIT() asm volatile("cp.async.commit_group;\n" ::: "memory")

#define LDSM4(r, a) \
    asm volatile("ldmatrix.sync.aligned.m8n8.x4.shared.b16 {%0,%1,%2,%3}, [%4];" \
                 : "=r"((r)[0]), "=r"((r)[1]), "=r"((r)[2]), "=r"((r)[3]) : "r"(a))
#define LDSM4T(r, a) \
    asm volatile("ldmatrix.sync.aligned.m8n8.x4.trans.shared.b16 {%0,%1,%2,%3}, [%4];" \
                 : "=r"((r)[0]), "=r"((r)[1]), "=r"((r)[2]), "=r"((r)[3]) : "r"(a))

#define MMA16816(d, a, b0, b1) \
    asm volatile("mma.sync.aligned.m16n8k16.row.col.f32.f16.f16.f32 " \
                 "{%0,%1,%2,%3}, {%4,%5,%6,%7}, {%8,%9}, {%0,%1,%2,%3};" \
                 : "+f"((d)[0]), "+f"((d)[1]), "+f"((d)[2]), "+f"((d)[3]) \
                 : "r"((a)[0]), "r"((a)[1]), "r"((a)[2]), "r"((a)[3]), "r"(b0), "r"(b1))

__device__ __forceinline__ uint32_t pack_f16x2(float hi_, float lo_) {
    __half2 h = __floats2half2_rn(lo_, hi_);
    return *(uint32_t*)&h;
}
__device__ __forceinline__ float2 unpack_f16x2(uint32_t u) {
    __half2 h = *(__half2*)&u;
    float2 r;
    r.x = __low2float(h);
    r.y = __high2float(h);
    return r;
}
// fast exp2 on FMA pipe (no MUFU). x <= 0 expected; rel err ~2.4e-6.
__device__ __forceinline__ float exp2p(float x) {
    x = fmaxf(x, -120.f);
    int e = __float2int_rn(x);
    float f = x - (float)e;
    float p = 1.3333558e-3f;
    p = fmaf(p, f, 9.6181291e-3f);
    p = fmaf(p, f, 5.5504109e-2f);
    p = fmaf(p, f, 2.4022651e-1f);
    p = fmaf(p, f, 6.9314718e-1f);
    p = fmaf(p, f, 1.0f);
    return p * __int_as_float((uint32_t)(e + 127) << 23);
}

// ---------------- DoRA weight materialization (all 4 weights, one launch) ----
__global__ __launch_bounds__(256) void dora_all(
    const float* __restrict__ Wq, const float* __restrict__ Aq,
    const float* __restrict__ Bq, const float* __restrict__ mq,
    const float* __restrict__ Wk, const float* __restrict__ Ak,
    const float* __restrict__ Bk, const float* __restrict__ mk,
    const float* __restrict__ Wv, const float* __restrict__ Av,
    const float* __restrict__ Bv, const float* __restrict__ mv,
    const float* __restrict__ Wo, const float* __restrict__ Ao,
    const float* __restrict__ Bo, const float* __restrict__ mo,
    __half* __restrict__ Wqh, __half* __restrict__ Wkh,
    __half* __restrict__ Wvh, __half* __restrict__ Woh)
{
    const int bx = blockIdx.x;
    const float *W, *A, *Bm, *mvec;
    __half *Whi;
    int row;
    if (bx < 4096)      { W = Wq; A = Aq; Bm = Bq; mvec = mq; Whi = Wqh; row = bx; }
    else if (bx < 5120) { W = Wk; A = Ak; Bm = Bk; mvec = mk; Whi = Wkh; row = bx - 4096; }
    else if (bx < 6144) { W = Wv; A = Av; Bm = Bv; mvec = mv; Whi = Wvh; row = bx - 5120; }
    else                { W = Wo; A = Ao; Bm = Bo; mvec = mo; Whi = Woh; row = bx - 6144; }

    const int tid = threadIdx.x;
    float b[8];
#pragma unroll
    for (int r = 0; r < 8; r++) b[r] = 2.0f * Bm[row * 8 + r];

    const float4* Wrow = (const float4*)(W + (size_t)row * HID);
    float4 w[4];
    float ss = 0.f;
#pragma unroll
    for (int c = 0; c < 4; c++) {
        int col4 = tid + 256 * c;
        float4 wv = Wrow[col4];
#pragma unroll
        for (int r = 0; r < 8; r++) {
            float4 av = ((const float4*)(A + (size_t)r * HID))[col4];
            wv.x += b[r] * av.x; wv.y += b[r] * av.y;
            wv.z += b[r] * av.z; wv.w += b[r] * av.w;
        }
        ss += wv.x * wv.x + wv.y * wv.y + wv.z * wv.z + wv.w * wv.w;
        w[c] = wv;
    }
#pragma unroll
    for (int off = 16; off; off >>= 1)
        ss += __shfl_xor_sync(0xffffffffu, ss, off);

    __shared__ float red[8];
    __shared__ float s_scale;
    if ((tid & 31) == 0) red[tid >> 5] = ss;
    __syncthreads();
    if (tid == 0) {
        float t = 0.f;
#pragma unroll
        for (int i = 0; i < 8; i++) t += red[i];
        s_scale = mvec[row] / (sqrtf(t) + 1e-8f);
    }
    __syncthreads();
    const float sc = s_scale;
#pragma unroll
    for (int c = 0; c < 4; c++) {
        float vv[4] = {w[c].x * sc, w[c].y * sc, w[c].z * sc, w[c].w * sc};
        size_t base = (size_t)row * HID + (tid + 256 * c) * 4;
        __half2 p0 = __floats2half2_rn(vv[0], vv[1]);
        __half2 p1 = __floats2half2_rn(vv[2], vv[3]);
        *(__half2*)&Whi[base] = p0;
        *(__half2*)&Whi[base + 2] = p1;
    }
}

// ---------------- fp32 -> fp16 hi/lo split (x only) ----------------
__global__ __launch_bounds__(256) void split_f16(
    const float* __restrict__ in, __half* __restrict__ hi,
    __half* __restrict__ lo, int n4)
{
    int i = blockIdx.x * 256 + threadIdx.x;
    if (i >= n4) return;
    float4 v = ((const float4*)in)[i];
    float vv[4] = {v.x, v.y, v.z, v.w};
    size_t base = (size_t)i * 4;
#pragma unroll
    for (int e = 0; e < 4; e++) {
        __half h = __float2half_rn(vv[e]);
        hi[base + e] = h;
        lo[base + e] = __float2half_rn(vv[e] - __half2float(h));
    }
}

// ============ GEMM mainloops: 128x128 tile, K=4096, K-chunk 64 ==============
#define GSTR 144
#define GTILE_B (128 * GSTR)             /* 18432 */
#define KST2_B (3 * GTILE_B)             /* {Ah, Al, Bh} = 55296 */
#define GEMM_SMEM (2 * KST2_B)           /* 110592/CTA -> 2 CTAs/SM */
#define KST1_B (2 * GTILE_B)             /* {A, B} = 36864 */
#define GEMM1_SMEM (3 * KST1_B)          /* 110592/CTA -> 2 CTAs/SM */

// ---- 2-term: acc += ah*bh + al*bh (2-stage double buffer)
__device__ __forceinline__ void hmma_mainloop2(
    uint32_t sb, const __half* g0, const __half* g1,
    const __half* g2, int tid, float acc[2][8][4])
{
    const int lane = tid & 31, wid = tid >> 5;
    const int wm = wid & 3, wn = wid >> 2;
    const int K = 4096;
    const int ldr = tid >> 3;
    const int ldc = (tid & 7) * 16;

    const uint32_t a_off = (uint32_t)(wm * 32 + (lane & 15)) * GSTR + ((lane >> 4) * 16);
    const uint32_t b_off = (uint32_t)(wn * 64 + (((lane >> 4) << 3) + (lane & 7))) * GSTR
                           + (((lane >> 3) & 1) * 16);

#define LOAD_STAGE(buf, k0) do { \
    uint32_t s0_ = sb + (buf) * KST2_B; \
    const __half* gg_[3] = {g0 + (k0), g1 + (k0), g2 + (k0)}; \
    _Pragma("unroll") \
    for (int t_ = 0; t_ < 3; t_++) { \
        uint32_t st_ = s0_ + t_ * GTILE_B; \
        _Pragma("unroll") \
        for (int p_ = 0; p_ < 4; p_++) { \
            int r_ = ldr + p_ * 32; \
            cp16(st_ + (uint32_t)r_ * GSTR + ldc, \
                 (const char*)(gg_[t_] + (size_t)r_ * K) + ldc); \
        } \
    } \
    CP_COMMIT(); \
} while (0)

    LOAD_STAGE(0, 0);
    for (int ch = 0; ch < 64; ch++) {
        asm volatile("cp.async.wait_group 0;\n" ::: "memory");
        __syncthreads();
        if (ch + 1 < 64) LOAD_STAGE((ch + 1) & 1, (ch + 1) * 64);

        const uint32_t s0 = sb + (ch & 1) * KST2_B;
        const uint32_t sAh = s0, sAl = s0 + GTILE_B, sBh = s0 + 2 * GTILE_B;
#pragma unroll
        for (int k16 = 0; k16 < 4; k16++) {
            const uint32_t kadd = k16 * 32;
            uint32_t ah[2][4], al[2][4], bb[4][4];
            LDSM4(ah[0], sAh + a_off + kadd);
            LDSM4(ah[1], sAh + a_off + 16 * GSTR + kadd);
            LDSM4(al[0], sAl + a_off + kadd);
            LDSM4(al[1], sAl + a_off + 16 * GSTR + kadd);
#pragma unroll
            for (int j = 0; j < 4; j++) LDSM4(bb[j], sBh + b_off + j * 16 * GSTR + kadd);
#pragma unroll
            for (int i = 0; i < 2; i++)
#pragma unroll
                for (int f = 0; f < 8; f++)
                    MMA16816(acc[i][f], ah[i], bb[f >> 1][(f & 1) * 2], bb[f >> 1][(f & 1) * 2 + 1]);
#pragma unroll
            for (int i = 0; i < 2; i++)
#pragma unroll
                for (int f = 0; f < 8; f++)
                    MMA16816(acc[i][f], al[i], bb[f >> 1][(f & 1) * 2], bb[f >> 1][(f & 1) * 2 + 1]);
        }
    }
#undef LOAD_STAGE
}

// ---- 1-term: acc += a*b (3-stage ring, 2-chunk lookahead)
__device__ __forceinline__ void hmma_mainloop1(
    uint32_t sb, const __half* g0, const __half* g2, int tid, float acc[2][8][4])
{
    const int lane = tid & 31, wid = tid >> 5;
    const int wm = wid & 3, wn = wid >> 2;
    const int K = 4096;
    const int ldr = tid >> 3;
    const int ldc = (tid & 7) * 16;

    const uint32_t a_off = (uint32_t)(wm * 32 + (lane & 15)) * GSTR + ((lane >> 4) * 16);
    const uint32_t b_off = (uint32_t)(wn * 64 + (((lane >> 4) << 3) + (lane & 7))) * GSTR
                           + (((lane >> 3) & 1) * 16);

#define LOAD_STAGE1(buf, k0) do { \
    uint32_t s0_ = sb + (buf) * KST1_B; \
    const __half* gg_[2] = {g0 + (k0), g2 + (k0)}; \
    _Pragma("unroll") \
    for (int t_ = 0; t_ < 2; t_++) { \
        uint32_t st_ = s0_ + t_ * GTILE_B; \
        _Pragma("unroll") \
        for (int p_ = 0; p_ < 4; p_++) { \
            int r_ = ldr + p_ * 32; \
            cp16(st_ + (uint32_t)r_ * GSTR + ldc, \
                 (const char*)(gg_[t_] + (size_t)r_ * K) + ldc); \
        } \
    } \
    CP_COMMIT(); \
} while (0)

    LOAD_STAGE1(0, 0);
    LOAD_STAGE1(1, 64);

    int cst = 0;
    for (int ch = 0; ch < 64; ch++) {
        if (ch + 1 < 64) {
            asm volatile("cp.async.wait_group 1;\n" ::: "memory");
        } else {
            asm volatile("cp.async.wait_group 0;\n" ::: "memory");
        }
        __syncthreads();
        if (ch + 2 < 64) {
            int lst = cst - 1; if (lst < 0) lst += 3;   /* (cst+2)%3 */
            LOAD_STAGE1(lst, (ch + 2) * 64);
        }
        const uint32_t s0 = sb + cst * KST1_B;
        const uint32_t sA = s0, sB = s0 + GTILE_B;
#pragma unroll
        for (int k16 = 0; k16 < 4; k16++) {
            const uint32_t kadd = k16 * 32;
            uint32_t aa[2][4], bb[4][4];
            LDSM4(aa[0], sA + a_off + kadd);
            LDSM4(aa[1], sA + a_off + 16 * GSTR + kadd);
#pragma unroll
            for (int j = 0; j < 4; j++) LDSM4(bb[j], sB + b_off + j * 16 * GSTR + kadd);
#pragma unroll
            for (int i = 0; i < 2; i++)
#pragma unroll
                for (int f = 0; f < 8; f++)
                    MMA16816(acc[i][f], aa[i], bb[f >> 1][(f & 1) * 2], bb[f >> 1][(f & 1) * 2 + 1]);
        }
        cst = (cst == 2) ? 0 : cst + 1;
    }
#undef LOAD_STAGE1
}

// ---------------- merged QKV projection (all 2-term, single fp16 out) -------
__global__ __launch_bounds__(256, 2) void gemm_qkv(
    const __half* __restrict__ xh, const __half* __restrict__ xl,
    const __half* __restrict__ Wqh, const __half* __restrict__ Wkh,
    const __half* __restrict__ Wvh,
    __half* __restrict__ qh, __half* __restrict__ kh, __half* __restrict__ vh)
{
    extern __shared__ char dsm[];
    const uint32_t sb = smem_u32(dsm);
    const int tid = threadIdx.x, lane = tid & 31, wid = tid >> 5;
    const int wm = wid & 3, wn = wid >> 2;
    const int bx = blockIdx.x;
    const int row0 = blockIdx.y << 7;
    const int K = 4096;

    const __half* Bh_;
    __half* Oh;
    int N, col0;
    if (bx < 32)      { Bh_ = Wqh; Oh = qh; N = HID; col0 = bx << 7; }
    else if (bx < 40) { Bh_ = Wkh; Oh = kh; N = KVD; col0 = (bx - 32) << 7; }
    else              { Bh_ = Wvh; Oh = vh; N = KVD; col0 = (bx - 40) << 7; }

    float acc[2][8][4] = {};
    hmma_mainloop2(sb, xh + (size_t)row0 * K, xl + (size_t)row0 * K,
                   Bh_ + (size_t)col0 * K, tid, acc);

#pragma unroll
    for (int i = 0; i < 2; i++) {
        const int mrow = row0 + wm * 32 + i * 16 + (lane >> 2);
#pragma unroll
        for (int f = 0; f < 8; f++) {
            const int col = col0 + wn * 64 + f * 8 + (lane & 3) * 2;
            uint32_t h01 = pack_f16x2(acc[i][f][1], acc[i][f][0]);
            uint32_t h23 = pack_f16x2(acc[i][f][3], acc[i][f][2]);
            *(uint32_t*)&Oh[(size_t)mrow * N + col] = h01;
            *(uint32_t*)&Oh[(size_t)(mrow + 8) * N + col] = h23;
        }
    }
}

// ---------------- output projection (1-term, fp32 out) ----------------
__global__ __launch_bounds__(256, 2) void gemm_o(
    const __half* __restrict__ Ah, const __half* __restrict__ Bh,
    float* __restrict__ C)
{
    extern __shared__ char dsm[];
    const uint32_t sb = smem_u32(dsm);
    const int tid = threadIdx.x, lane = tid & 31, wid = tid >> 5;
    const int wm = wid & 3, wn = wid >> 2;
    const int row0 = blockIdx.y << 7, col0 = blockIdx.x << 7;
    const int K = 4096, N = HID;

    float acc[2][8][4] = {};
    hmma_mainloop1(sb, Ah + (size_t)row0 * K, Bh + (size_t)col0 * K, tid, acc);

#pragma unroll
    for (int i = 0; i < 2; i++) {
        const int mrow = row0 + wm * 32 + i * 16 + (lane >> 2);
#pragma unroll
        for (int f = 0; f < 8; f++) {
            const int col = col0 + wn * 64 + f * 8 + (lane & 3) * 2;
            float2 lo2 = {acc[i][f][0], acc[i][f][1]};
            float2 hi2 = {acc[i][f][2], acc[i][f][3]};
            *(float2*)&C[(size_t)mrow * N + col] = lo2;
            *(float2*)&C[(size_t)(mrow + 8) * N + col] = hi2;
        }
    }
}

// ---------------- HMMA causal flash attention ----------------
// CTA: 128 q-rows (8 warps x 16 rows), key tiles of 64, D=128.
// QK 1-term; PV 1-term (P single fp16 x v single). Single fp16 output.
// Raw-score softmax: Cs folded into exp2 argument; lazy (warp-voted) rescale.
#define FSTR 272
#define KV_T 17408
#define KV_STAGE (2 * KV_T)
#define FLASH_SMEM (3 * KV_STAGE)

__global__ __launch_bounds__(256, 1) void flash_hmma(
    const __half* __restrict__ qh_g, const __half* __restrict__ kh_g,
    const __half* __restrict__ vh_g,
    __half* __restrict__ oh_g)
{
    extern __shared__ char dsm[];
    const uint32_t sq = smem_u32(dsm);
    const uint32_t sb = sq;
    const int tid = threadIdx.x, lane = tid & 31, w = tid >> 5;
    const int qt = (int)gridDim.x - 1 - (int)blockIdx.x;
    const int h = blockIdx.y, b = blockIdx.z;
    const int kvh = h >> 2;
    const int gr = qt * 128;
    const int nkt = 2 * qt + 2;

    {
        const __half* src = qh_g + ((size_t)(b * SEQ + gr)) * HID + h * 128;
#pragma unroll
        for (int i = 0; i < 8; i++) {
            int idx = tid + i * 256;
            int r = idx >> 4, c = idx & 15;
            cp16(sq + (uint32_t)r * FSTR + c * 16,
                 (const char*)(src + (size_t)r * HID) + c * 16);
        }
        CP_COMMIT();
        asm volatile("cp.async.wait_group 0;\n" ::: "memory");
        __syncthreads();
    }
    uint32_t qhf[8][4];
    {
        const uint32_t qoff = (uint32_t)(w * 16 + (lane & 15)) * FSTR + ((lane >> 4) * 16);
#pragma unroll
        for (int kf = 0; kf < 8; kf++)
            LDSM4(qhf[kf], sq + qoff + kf * 32);
    }
    __syncthreads();

    float o[16][4];
#pragma unroll
    for (int i = 0; i < 16; i++) { o[i][0] = 0.f; o[i][1] = 0.f; o[i][2] = 0.f; o[i][3] = 0.f; }
    float m0 = -1e5f, m1 = -1e5f, l0 = 0.f, l1 = 0.f;

    const uint32_t koff = (uint32_t)(((lane >> 4) << 3) + (lane & 7)) * FSTR + (((lane >> 3) & 1) * 16);
    const uint32_t voff = (uint32_t)((((lane >> 3) & 1) << 3) + (lane & 7)) * FSTR + ((lane >> 4) * 16);

    const __half* kh_p = kh_g + ((size_t)(b * SEQ)) * KVD + kvh * 128;
    const __half* vh_p = vh_g + ((size_t)(b * SEQ)) * KVD + kvh * 128;

#define LOADKV(kt_, buf_) do { \
    uint32_t s0_ = sb + (buf_) * KV_STAGE; \
    const __half* gs_[2] = { \
        kh_p + (size_t)(kt_) * 64 * KVD, vh_p + (size_t)(kt_) * 64 * KVD}; \
    _Pragma("unroll") \
    for (int t_ = 0; t_ < 2; t_++) { \
        _Pragma("unroll") \
        for (int i_ = 0; i_ < 4; i_++) { \
            int idx_ = tid + i_ * 256; \
            int r_ = idx_ >> 4, c_ = idx_ & 15; \
            cp16(s0_ + t_ * KV_T + (uint32_t)r_ * FSTR + c_ * 16, \
                 (const char*)(gs_[t_] + (size_t)r_ * KVD) + c_ * 16); \
        } \
    } \
    CP_COMMIT(); \
} while (0)

    LOADKV(0, 0);
    LOADKV(1, 1);
    const float Cs = 0.08838834764831845f * 1.4426950408889634f;  // scale*log2e

    int st = 0;
    int st2 = 2;
    for (int kt = 0; kt < nkt; kt++) {
        if (kt + 2 < nkt) {
            asm volatile("cp.async.wait_group 1;\n" ::: "memory");
        } else {
            asm volatile("cp.async.wait_group 0;\n" ::: "memory");
        }
        __syncthreads();
        if (kt + 2 < nkt) LOADKV(kt + 2, st2);

        const uint32_t sKh = sb + st * KV_STAGE;
        const uint32_t sVh = sKh + KV_T;

        // ---- QK^T (1-term, raw scores)
        float s[8][4];
#pragma unroll
        for (int i = 0; i < 8; i++) { s[i][0] = 0.f; s[i][1] = 0.f; s[i][2] = 0.f; s[i][3] = 0.f; }
#pragma unroll
        for (int kf = 0; kf < 8; kf++) {
#pragma unroll
            for (int nb = 0; nb < 4; nb++) {
                uint32_t bh[4];
                LDSM4(bh, sKh + koff + nb * (16 * FSTR) + kf * 32);
                MMA16816(s[2 * nb], qhf[kf], bh[0], bh[1]);
                MMA16816(s[2 * nb + 1], qhf[kf], bh[2], bh[3]);
            }
        }
        // ---- causal mask (raw units)
        if (kt >= nkt - 2) {
            const int r0 = gr + w * 16 + (lane >> 2);
            const int c0 = kt * 64 + 2 * (lane & 3);
#pragma unroll
            for (int nf = 0; nf < 8; nf++) {
#pragma unroll
                for (int j = 0; j < 4; j++) {
                    int col = c0 + nf * 8 + (j & 1);
                    int row = r0 + (j >> 1) * 8;
                    if (col > row) s[nf][j] = -1e5f;
                }
            }
        }
        // ---- online softmax: lazy rescale with warp vote
        float mx0 = -1e30f, mx1 = -1e30f;
#pragma unroll
        for (int nf = 0; nf < 8; nf++) {
            mx0 = fmaxf(mx0, fmaxf(s[nf][0], s[nf][1]));
            mx1 = fmaxf(mx1, fmaxf(s[nf][2], s[nf][3]));
        }
        mx0 = fmaxf(mx0, __shfl_xor_sync(0xffffffffu, mx0, 1));
        mx0 = fmaxf(mx0, __shfl_xor_sync(0xffffffffu, mx0, 2));
        mx1 = fmaxf(mx1, __shfl_xor_sync(0xffffffffu, mx1, 1));
        mx1 = fmaxf(mx1, __shfl_xor_sync(0xffffffffu, mx1, 2));
        if (__any_sync(0xffffffffu, (mx0 > m0) || (mx1 > m1))) {
            const float mn0 = fmaxf(m0, mx0), mn1 = fmaxf(m1, mx1);
            const float cr0 = exp2p((m0 - mn0) * Cs), cr1 = exp2p((m1 - mn1) * Cs);
            m0 = mn0; m1 = mn1;
            l0 *= cr0; l1 *= cr1;
#pragma unroll
            for (int nf = 0; nf < 16; nf++) {
                o[nf][0] *= cr0; o[nf][1] *= cr0; o[nf][2] *= cr1; o[nf][3] *= cr1;
            }
        }
        const float c0_ = -m0 * Cs, c1_ = -m1 * Cs;
        float rs0 = 0.f, rs1 = 0.f;
#pragma unroll
        for (int nf = 0; nf < 8; nf++) {
            float p0 = exp2p(fmaf(s[nf][0], Cs, c0_));
            float p1 = exp2p(fmaf(s[nf][1], Cs, c0_));
            float p2 = exp2p(fmaf(s[nf][2], Cs, c1_));
            float p3 = exp2p(fmaf(s[nf][3], Cs, c1_));
            s[nf][0] = p0; s[nf][1] = p1; s[nf][2] = p2; s[nf][3] = p3;
            rs0 += p0 + p1; rs1 += p2 + p3;
        }
        rs0 += __shfl_xor_sync(0xffffffffu, rs0, 1);
        rs0 += __shfl_xor_sync(0xffffffffu, rs0, 2);
        rs1 += __shfl_xor_sync(0xffffffffu, rs1, 1);
        rs1 += __shfl_xor_sync(0xffffffffu, rs1, 2);
        l0 += rs0;
        l1 += rs1;
        // ---- P @ V (1-term: P single fp16 x v single)
#pragma unroll
        for (int kb = 0; kb < 4; kb++) {
            uint32_t ph[4];
#pragma unroll
            for (int q2 = 0; q2 < 2; q2++) {
                const int nf = 2 * kb + q2;
                ph[2 * q2]     = pack_f16x2(s[nf][1], s[nf][0]);
                ph[2 * q2 + 1] = pack_f16x2(s[nf][3], s[nf][2]);
            }
#pragma unroll
            for (int ng = 0; ng < 8; ng++) {
                uint32_t vv[4];
                LDSM4T(vv, sVh + voff + kb * (16 * FSTR) + ng * 32);
                MMA16816(o[2 * ng], ph, vv[0], vv[1]);
                MMA16816(o[2 * ng + 1], ph, vv[2], vv[3]);
            }
        }
        st = (st == 2) ? 0 : st + 1;
        st2 = (st2 == 2) ? 0 : st2 + 1;
    }
#undef LOADKV

    const float inv0 = 1.f / l0, inv1 = 1.f / l1;
    const size_t row0_ = (size_t)(b * SEQ + gr + w * 16 + (lane >> 2));
    const int colb = h * 128 + 2 * (lane & 3);
#pragma unroll
    for (int nf = 0; nf < 16; nf++) {
        const int col = colb + nf * 8;
        uint32_t h01 = pack_f16x2(o[nf][1] * inv0, o[nf][0] * inv0);
        uint32_t h23 = pack_f16x2(o[nf][3] * inv1, o[nf][2] * inv1);
        *(uint32_t*)&oh_g[row0_ * HID + col] = h01;
        *(uint32_t*)&oh_g[(row0_ + 8) * HID + col] = h23;
    }
}

// ---------------- launch ----------------
extern "C" void kernel_launch(void* const* d_in, const int* in_sizes, int n_in,
                              void* d_out, int out_size)
{
    const float* x  = (const float*)d_in[0];
    const float* Wq = (const float*)d_in[2];
    const float* Aq = (const float*)d_in[3];
    const float* Bq = (const float*)d_in[4];
    const float* mq = (const float*)d_in[5];
    const float* Wk = (const float*)d_in[6];
    const float* Ak = (const float*)d_in[7];
    const float* Bk = (const float*)d_in[8];
    const float* mk = (const float*)d_in[9];
    const float* Wv = (const float*)d_in[10];
    const float* Av = (const float*)d_in[11];
    const float* Bv = (const float*)d_in[12];
    const float* mv = (const float*)d_in[13];
    const float* Wo = (const float*)d_in[14];
    const float* Ao = (const float*)d_in[15];
    const float* Bo = (const float*)d_in[16];
    const float* mo = (const float*)d_in[17];

    __half *xh, *xl, *Wqh, *Wkh, *Wvh, *Woh;
    __half *qh, *kh, *vh, *ath;
    cudaGetSymbolAddress((void**)&xh, g_xh);   cudaGetSymbolAddress((void**)&xl, g_xl);
    cudaGetSymbolAddress((void**)&Wqh, g_Wqh); cudaGetSymbolAddress((void**)&Wkh, g_Wkh);
    cudaGetSymbolAddress((void**)&Wvh, g_Wvh); cudaGetSymbolAddress((void**)&Woh, g_Woh);
    cudaGetSymbolAddress((void**)&qh, g_qh);   cudaGetSymbolAddress((void**)&kh, g_kh);
    cudaGetSymbolAddress((void**)&vh, g_vh);
    cudaGetSymbolAddress((void**)&ath, g_ath);

    cudaFuncSetAttribute(gemm_qkv, cudaFuncAttributeMaxDynamicSharedMemorySize, GEMM_SMEM);
    cudaFuncSetAttribute(gemm_o, cudaFuncAttributeMaxDynamicSharedMemorySize, GEMM1_SMEM);
    cudaFuncSetAttribute(flash_hmma, cudaFuncAttributeMaxDynamicSharedMemorySize, FLASH_SMEM);

    // 1) DoRA effective weights (one launch, single fp16 out)
    dora_all<<<10240, 256>>>(Wq, Aq, Bq, mq, Wk, Ak, Bk, mk,
                             Wv, Av, Bv, mv, Wo, Ao, Bo, mo,
                             Wqh, Wkh, Wvh, Woh);

    // 2) split x
    split_f16<<<(TOK * HID / 4 + 255) / 256, 256>>>(x, xh, xl, TOK * HID / 4);

    // 3) merged q/k/v projections (2-term, single fp16 out)
    gemm_qkv<<<dim3(48, TOK / 128), 256, GEMM_SMEM>>>(
        xh, xl, Wqh, Wkh, Wvh, qh, kh, vh);

    // 4) causal attention (HMMA) -> single fp16 attention output
    flash_hmma<<<dim3(SEQ / 128, 32, 2), 256, FLASH_SMEM>>>(qh, kh, vh, ath);

    // 5) output projection (1-term) -> d_out (fp32)
    gemm_o<<<dim3(HID / 128, TOK / 128), 256, GEMM1_SMEM>>>(ath, Woh, (float*)d_out);
}

// round 14
// speedup vs baseline: 2.6545x; 1.2027x over previous
#include <cuda_runtime.h>
#include <cuda_fp16.h>
#include <cstdint>
#include <math.h>

#define HID 4096
#define KVD 1024
#define TOK 4096   /* B*S */
#define SEQ 2048

// ---------------- device scratch ----------------
__device__ __half g_xh[TOK * HID];
__device__ __half g_xl[TOK * HID];
__device__ __half g_Wqh[HID * HID];
__device__ __half g_Wkh[KVD * HID];
__device__ __half g_Wvh[KVD * HID];
__device__ __half g_Woh[HID * HID];
__device__ __half g_qh[TOK * HID];
__device__ __half g_kh[TOK * KVD];
__device__ __half g_vh[TOK * KVD];
__device__ __half g_ath[TOK * HID];

// ---------------- helpers ----------------
__device__ __forceinline__ uint32_t smem_u32(const void* p) {
    uint32_t a;
    asm("{ .reg .u64 t; cvta.to.shared.u64 t, %1; cvt.u32.u64 %0, t; }" : "=r"(a) : "l"(p));
    return a;
}
__device__ __forceinline__ void cp16(uint32_t dst, const void* src) {
    asm volatile("cp.async.cg.shared.global [%0], [%1], 16;\n" :: "r"(dst), "l"(src) : "memory");
}
#define CP_COMMIT() asm volatile("cp.async.commit_group;\n" ::: "memory")

#define LDSM4(r, a) \
    asm volatile("ldmatrix.sync.aligned.m8n8.x4.shared.b16 {%0,%1,%2,%3}, [%4];" \
                 : "=r"((r)[0]), "=r"((r)[1]), "=r"((r)[2]), "=r"((r)[3]) : "r"(a))
#define LDSM4T(r, a) \
    asm volatile("ldmatrix.sync.aligned.m8n8.x4.trans.shared.b16 {%0,%1,%2,%3}, [%4];" \
                 : "=r"((r)[0]), "=r"((r)[1]), "=r"((r)[2]), "=r"((r)[3]) : "r"(a))

#define MMA16816(d, a, b0, b1) \
    asm volatile("mma.sync.aligned.m16n8k16.row.col.f32.f16.f16.f32 " \
                 "{%0,%1,%2,%3}, {%4,%5,%6,%7}, {%8,%9}, {%0,%1,%2,%3};" \
                 : "+f"((d)[0]), "+f"((d)[1]), "+f"((d)[2]), "+f"((d)[3]) \
                 : "r"((a)[0]), "r"((a)[1]), "r"((a)[2]), "r"((a)[3]), "r"(b0), "r"(b1))

__device__ __forceinline__ uint32_t pack_f16x2(float hi_, float lo_) {
    __half2 h = __floats2half2_rn(lo_, hi_);
    return *(uint32_t*)&h;
}
// fast exp2 on FMA pipe (no MUFU). x <= 0 expected; rel err ~2.4e-6.
__device__ __forceinline__ float exp2p(float x) {
    x = fmaxf(x, -120.f);
    int e = __float2int_rn(x);
    float f = x - (float)e;
    float p = 1.3333558e-3f;
    p = fmaf(p, f, 9.6181291e-3f);
    p = fmaf(p, f, 5.5504109e-2f);
    p = fmaf(p, f, 2.4022651e-1f);
    p = fmaf(p, f, 6.9314718e-1f);
    p = fmaf(p, f, 1.0f);
    return p * __int_as_float((uint32_t)(e + 127) << 23);
}

// -------- fused: DoRA weights (blocks 0..10239) + x split (blocks 10240..) --
__global__ __launch_bounds__(256) void dora_split(
    const float* __restrict__ Wq, const float* __restrict__ Aq,
    const float* __restrict__ Bq, const float* __restrict__ mq,
    const float* __restrict__ Wk, const float* __restrict__ Ak,
    const float* __restrict__ Bk, const float* __restrict__ mk,
    const float* __restrict__ Wv, const float* __restrict__ Av,
    const float* __restrict__ Bv, const float* __restrict__ mv,
    const float* __restrict__ Wo, const float* __restrict__ Ao,
    const float* __restrict__ Bo, const float* __restrict__ mo,
    __half* __restrict__ Wqh, __half* __restrict__ Wkh,
    __half* __restrict__ Wvh, __half* __restrict__ Woh,
    const float* __restrict__ x, __half* __restrict__ xh,
    __half* __restrict__ xl)
{
    const int bx = blockIdx.x;
    const int tid = threadIdx.x;

    if (bx >= 10240) {
        // ---- x split: one block = 256 float4
        int i = (bx - 10240) * 256 + tid;
        if (i < TOK * HID / 4) {
            float4 v = ((const float4*)x)[i];
            float vv[4] = {v.x, v.y, v.z, v.w};
            size_t base = (size_t)i * 4;
#pragma unroll
            for (int e = 0; e < 4; e++) {
                __half h = __float2half_rn(vv[e]);
                xh[base + e] = h;
                xl[base + e] = __float2half_rn(vv[e] - __half2float(h));
            }
        }
        return;
    }

    const float *W, *A, *Bm, *mvec;
    __half *Whi;
    int row;
    if (bx < 4096)      { W = Wq; A = Aq; Bm = Bq; mvec = mq; Whi = Wqh; row = bx; }
    else if (bx < 5120) { W = Wk; A = Ak; Bm = Bk; mvec = mk; Whi = Wkh; row = bx - 4096; }
    else if (bx < 6144) { W = Wv; A = Av; Bm = Bv; mvec = mv; Whi = Wvh; row = bx - 5120; }
    else                { W = Wo; A = Ao; Bm = Bo; mvec = mo; Whi = Woh; row = bx - 6144; }

    float b[8];
#pragma unroll
    for (int r = 0; r < 8; r++) b[r] = 2.0f * Bm[row * 8 + r];

    const float4* Wrow = (const float4*)(W + (size_t)row * HID);
    float4 w[4];
    float ss = 0.f;
#pragma unroll
    for (int c = 0; c < 4; c++) {
        int col4 = tid + 256 * c;
        float4 wv = Wrow[col4];
#pragma unroll
        for (int r = 0; r < 8; r++) {
            float4 av = ((const float4*)(A + (size_t)r * HID))[col4];
            wv.x += b[r] * av.x; wv.y += b[r] * av.y;
            wv.z += b[r] * av.z; wv.w += b[r] * av.w;
        }
        ss += wv.x * wv.x + wv.y * wv.y + wv.z * wv.z + wv.w * wv.w;
        w[c] = wv;
    }
#pragma unroll
    for (int off = 16; off; off >>= 1)
        ss += __shfl_xor_sync(0xffffffffu, ss, off);

    __shared__ float red[8];
    __shared__ float s_scale;
    if ((tid & 31) == 0) red[tid >> 5] = ss;
    __syncthreads();
    if (tid == 0) {
        float t = 0.f;
#pragma unroll
        for (int i = 0; i < 8; i++) t += red[i];
        s_scale = mvec[row] / (sqrtf(t) + 1e-8f);
    }
    __syncthreads();
    const float sc = s_scale;
#pragma unroll
    for (int c = 0; c < 4; c++) {
        float vv[4] = {w[c].x * sc, w[c].y * sc, w[c].z * sc, w[c].w * sc};
        size_t base = (size_t)row * HID + (tid + 256 * c) * 4;
        __half2 p0 = __floats2half2_rn(vv[0], vv[1]);
        __half2 p1 = __floats2half2_rn(vv[2], vv[3]);
        *(__half2*)&Whi[base] = p0;
        *(__half2*)&Whi[base + 2] = p1;
    }
}

// ============ GEMM mainloops: 128x128 tile, K=4096, K-chunk 64 ==============
#define GSTR 144
#define GTILE_B (128 * GSTR)             /* 18432 */
#define KST2_B (3 * GTILE_B)             /* {Ah, Al, Bh} = 55296 */
#define GEMM_SMEM (2 * KST2_B)           /* 110592/CTA -> 2 CTAs/SM */
#define KST1_B (2 * GTILE_B)             /* {A, B} = 36864 */
#define GEMM1_SMEM (3 * KST1_B)          /* 110592/CTA -> 2 CTAs/SM */

// ---- 2-term: acc += ah*bh + al*bh (2-stage double buffer)
__device__ __forceinline__ void hmma_mainloop2(
    uint32_t sb, const __half* g0, const __half* g1,
    const __half* g2, int tid, float acc[2][8][4])
{
    const int lane = tid & 31, wid = tid >> 5;
    const int wm = wid & 3, wn = wid >> 2;
    const int K = 4096;
    const int ldr = tid >> 3;
    const int ldc = (tid & 7) * 16;

    const uint32_t a_off = (uint32_t)(wm * 32 + (lane & 15)) * GSTR + ((lane >> 4) * 16);
    const uint32_t b_off = (uint32_t)(wn * 64 + (((lane >> 4) << 3) + (lane & 7))) * GSTR
                           + (((lane >> 3) & 1) * 16);

#define LOAD_STAGE(buf, k0) do { \
    uint32_t s0_ = sb + (buf) * KST2_B; \
    const __half* gg_[3] = {g0 + (k0), g1 + (k0), g2 + (k0)}; \
    _Pragma("unroll") \
    for (int t_ = 0; t_ < 3; t_++) { \
        uint32_t st_ = s0_ + t_ * GTILE_B; \
        _Pragma("unroll") \
        for (int p_ = 0; p_ < 4; p_++) { \
            int r_ = ldr + p_ * 32; \
            cp16(st_ + (uint32_t)r_ * GSTR + ldc, \
                 (const char*)(gg_[t_] + (size_t)r_ * K) + ldc); \
        } \
    } \
    CP_COMMIT(); \
} while (0)

    LOAD_STAGE(0, 0);
    for (int ch = 0; ch < 64; ch++) {
        asm volatile("cp.async.wait_group 0;\n" ::: "memory");
        __syncthreads();
        if (ch + 1 < 64) LOAD_STAGE((ch + 1) & 1, (ch + 1) * 64);

        const uint32_t s0 = sb + (ch & 1) * KST2_B;
        const uint32_t sAh = s0, sAl = s0 + GTILE_B, sBh = s0 + 2 * GTILE_B;
#pragma unroll
        for (int k16 = 0; k16 < 4; k16++) {
            const uint32_t kadd = k16 * 32;
            uint32_t ah[2][4], al[2][4], bb[4][4];
            LDSM4(ah[0], sAh + a_off + kadd);
            LDSM4(ah[1], sAh + a_off + 16 * GSTR + kadd);
            LDSM4(al[0], sAl + a_off + kadd);
            LDSM4(al[1], sAl + a_off + 16 * GSTR + kadd);
#pragma unroll
            for (int j = 0; j < 4; j++) LDSM4(bb[j], sBh + b_off + j * 16 * GSTR + kadd);
#pragma unroll
            for (int i = 0; i < 2; i++)
#pragma unroll
                for (int f = 0; f < 8; f++)
                    MMA16816(acc[i][f], ah[i], bb[f >> 1][(f & 1) * 2], bb[f >> 1][(f & 1) * 2 + 1]);
#pragma unroll
            for (int i = 0; i < 2; i++)
#pragma unroll
                for (int f = 0; f < 8; f++)
                    MMA16816(acc[i][f], al[i], bb[f >> 1][(f & 1) * 2], bb[f >> 1][(f & 1) * 2 + 1]);
        }
    }
#undef LOAD_STAGE
}

// ---- 1-term: acc += a*b (3-stage ring, 2-chunk lookahead)
__device__ __forceinline__ void hmma_mainloop1(
    uint32_t sb, const __half* g0, const __half* g2, int tid, float acc[2][8][4])
{
    const int lane = tid & 31, wid = tid >> 5;
    const int wm = wid & 3, wn = wid >> 2;
    const int K = 4096;
    const int ldr = tid >> 3;
    const int ldc = (tid & 7) * 16;

    const uint32_t a_off = (uint32_t)(wm * 32 + (lane & 15)) * GSTR + ((lane >> 4) * 16);
    const uint32_t b_off = (uint32_t)(wn * 64 + (((lane >> 4) << 3) + (lane & 7))) * GSTR
                           + (((lane >> 3) & 1) * 16);

#define LOAD_STAGE1(buf, k0) do { \
    uint32_t s0_ = sb + (buf) * KST1_B; \
    const __half* gg_[2] = {g0 + (k0), g2 + (k0)}; \
    _Pragma("unroll") \
    for (int t_ = 0; t_ < 2; t_++) { \
        uint32_t st_ = s0_ + t_ * GTILE_B; \
        _Pragma("unroll") \
        for (int p_ = 0; p_ < 4; p_++) { \
            int r_ = ldr + p_ * 32; \
            cp16(st_ + (uint32_t)r_ * GSTR + ldc, \
                 (const char*)(gg_[t_] + (size_t)r_ * K) + ldc); \
        } \
    } \
    CP_COMMIT(); \
} while (0)

    LOAD_STAGE1(0, 0);
    LOAD_STAGE1(1, 64);

    int cst = 0;
    for (int ch = 0; ch < 64; ch++) {
        if (ch + 1 < 64) {
            asm volatile("cp.async.wait_group 1;\n" ::: "memory");
        } else {
            asm volatile("cp.async.wait_group 0;\n" ::: "memory");
        }
        __syncthreads();
        if (ch + 2 < 64) {
            int lst = cst - 1; if (lst < 0) lst += 3;   /* (cst+2)%3 */
            LOAD_STAGE1(lst, (ch + 2) * 64);
        }
        const uint32_t s0 = sb + cst * KST1_B;
        const uint32_t sA = s0, sB = s0 + GTILE_B;
#pragma unroll
        for (int k16 = 0; k16 < 4; k16++) {
            const uint32_t kadd = k16 * 32;
            uint32_t aa[2][4], bb[4][4];
            LDSM4(aa[0], sA + a_off + kadd);
            LDSM4(aa[1], sA + a_off + 16 * GSTR + kadd);
#pragma unroll
            for (int j = 0; j < 4; j++) LDSM4(bb[j], sB + b_off + j * 16 * GSTR + kadd);
#pragma unroll
            for (int i = 0; i < 2; i++)
#pragma unroll
                for (int f = 0; f < 8; f++)
                    MMA16816(acc[i][f], aa[i], bb[f >> 1][(f & 1) * 2], bb[f >> 1][(f & 1) * 2 + 1]);
        }
        cst = (cst == 2) ? 0 : cst + 1;
    }
#undef LOAD_STAGE1
}

// ---------------- merged QKV projection ----------------
// Q: 1-term (xh only). K/V: 2-term (xh+xl). All single fp16 out.
__global__ __launch_bounds__(256, 2) void gemm_qkv(
    const __half* __restrict__ xh, const __half* __restrict__ xl,
    const __half* __restrict__ Wqh, const __half* __restrict__ Wkh,
    const __half* __restrict__ Wvh,
    __half* __restrict__ qh, __half* __restrict__ kh, __half* __restrict__ vh)
{
    extern __shared__ char dsm[];
    const uint32_t sb = smem_u32(dsm);
    const int tid = threadIdx.x, lane = tid & 31, wid = tid >> 5;
    const int wm = wid & 3, wn = wid >> 2;
    const int bx = blockIdx.x;
    const int row0 = blockIdx.y << 7;
    const int K = 4096;

    float acc[2][8][4] = {};
    const __half* Bh_;
    __half* Oh;
    int N, col0;
    if (bx < 32) {
        Bh_ = Wqh; Oh = qh; N = HID; col0 = bx << 7;
        hmma_mainloop1(sb, xh + (size_t)row0 * K, Bh_ + (size_t)col0 * K, tid, acc);
    } else {
        if (bx < 40) { Bh_ = Wkh; Oh = kh; N = KVD; col0 = (bx - 32) << 7; }
        else         { Bh_ = Wvh; Oh = vh; N = KVD; col0 = (bx - 40) << 7; }
        hmma_mainloop2(sb, xh + (size_t)row0 * K, xl + (size_t)row0 * K,
                       Bh_ + (size_t)col0 * K, tid, acc);
    }

#pragma unroll
    for (int i = 0; i < 2; i++) {
        const int mrow = row0 + wm * 32 + i * 16 + (lane >> 2);
#pragma unroll
        for (int f = 0; f < 8; f++) {
            const int col = col0 + wn * 64 + f * 8 + (lane & 3) * 2;
            uint32_t h01 = pack_f16x2(acc[i][f][1], acc[i][f][0]);
            uint32_t h23 = pack_f16x2(acc[i][f][3], acc[i][f][2]);
            *(uint32_t*)&Oh[(size_t)mrow * N + col] = h01;
            *(uint32_t*)&Oh[(size_t)(mrow + 8) * N + col] = h23;
        }
    }
}

// ---------------- output projection (1-term, fp32 out) ----------------
__global__ __launch_bounds__(256, 2) void gemm_o(
    const __half* __restrict__ Ah, const __half* __restrict__ Bh,
    float* __restrict__ C)
{
    extern __shared__ char dsm[];
    const uint32_t sb = smem_u32(dsm);
    const int tid = threadIdx.x, lane = tid & 31, wid = tid >> 5;
    const int wm = wid & 3, wn = wid >> 2;
    const int row0 = blockIdx.y << 7, col0 = blockIdx.x << 7;
    const int K = 4096, N = HID;

    float acc[2][8][4] = {};
    hmma_mainloop1(sb, Ah + (size_t)row0 * K, Bh + (size_t)col0 * K, tid, acc);

#pragma unroll
    for (int i = 0; i < 2; i++) {
        const int mrow = row0 + wm * 32 + i * 16 + (lane >> 2);
#pragma unroll
        for (int f = 0; f < 8; f++) {
            const int col = col0 + wn * 64 + f * 8 + (lane & 3) * 2;
            float2 lo2 = {acc[i][f][0], acc[i][f][1]};
            float2 hi2 = {acc[i][f][2], acc[i][f][3]};
            *(float2*)&C[(size_t)mrow * N + col] = lo2;
            *(float2*)&C[(size_t)(mrow + 8) * N + col] = hi2;
        }
    }
}

// ---------------- HMMA causal flash attention ----------------
// QK 1-term; PV 1-term. Raw-score softmax, lazy (warp-voted) rescale.
#define FSTR 272
#define KV_T 17408
#define KV_STAGE (2 * KV_T)
#define FLASH_SMEM (3 * KV_STAGE)

__global__ __launch_bounds__(256, 1) void flash_hmma(
    const __half* __restrict__ qh_g, const __half* __restrict__ kh_g,
    const __half* __restrict__ vh_g,
    __half* __restrict__ oh_g)
{
    extern __shared__ char dsm[];
    const uint32_t sq = smem_u32(dsm);
    const uint32_t sb = sq;
    const int tid = threadIdx.x, lane = tid & 31, w = tid >> 5;
    const int qt = (int)gridDim.x - 1 - (int)blockIdx.x;
    const int h = blockIdx.y, b = blockIdx.z;
    const int kvh = h >> 2;
    const int gr = qt * 128;
    const int nkt = 2 * qt + 2;

    {
        const __half* src = qh_g + ((size_t)(b * SEQ + gr)) * HID + h * 128;
#pragma unroll
        for (int i = 0; i < 8; i++) {
            int idx = tid + i * 256;
            int r = idx >> 4, c = idx & 15;
            cp16(sq + (uint32_t)r * FSTR + c * 16,
                 (const char*)(src + (size_t)r * HID) + c * 16);
        }
        CP_COMMIT();
        asm volatile("cp.async.wait_group 0;\n" ::: "memory");
        __syncthreads();
    }
    uint32_t qhf[8][4];
    {
        const uint32_t qoff = (uint32_t)(w * 16 + (lane & 15)) * FSTR + ((lane >> 4) * 16);
#pragma unroll
        for (int kf = 0; kf < 8; kf++)
            LDSM4(qhf[kf], sq + qoff + kf * 32);
    }
    __syncthreads();

    float o[16][4];
#pragma unroll
    for (int i = 0; i < 16; i++) { o[i][0] = 0.f; o[i][1] = 0.f; o[i][2] = 0.f; o[i][3] = 0.f; }
    float m0 = -1e5f, m1 = -1e5f, l0 = 0.f, l1 = 0.f;

    const uint32_t koff = (uint32_t)(((lane >> 4) << 3) + (lane & 7)) * FSTR + (((lane >> 3) & 1) * 16);
    const uint32_t voff = (uint32_t)((((lane >> 3) & 1) << 3) + (lane & 7)) * FSTR + ((lane >> 4) * 16);

    const __half* kh_p = kh_g + ((size_t)(b * SEQ)) * KVD + kvh * 128;
    const __half* vh_p = vh_g + ((size_t)(b * SEQ)) * KVD + kvh * 128;

#define LOADKV(kt_, buf_) do { \
    uint32_t s0_ = sb + (buf_) * KV_STAGE; \
    const __half* gs_[2] = { \
        kh_p + (size_t)(kt_) * 64 * KVD, vh_p + (size_t)(kt_) * 64 * KVD}; \
    _Pragma("unroll") \
    for (int t_ = 0; t_ < 2; t_++) { \
        _Pragma("unroll") \
        for (int i_ = 0; i_ < 4; i_++) { \
            int idx_ = tid + i_ * 256; \
            int r_ = idx_ >> 4, c_ = idx_ & 15; \
            cp16(s0_ + t_ * KV_T + (uint32_t)r_ * FSTR + c_ * 16, \
                 (const char*)(gs_[t_] + (size_t)r_ * KVD) + c_ * 16); \
        } \
    } \
    CP_COMMIT(); \
} while (0)

    LOADKV(0, 0);
    LOADKV(1, 1);
    const float Cs = 0.08838834764831845f * 1.4426950408889634f;

    int st = 0;
    int st2 = 2;
    for (int kt = 0; kt < nkt; kt++) {
        if (kt + 2 < nkt) {
            asm volatile("cp.async.wait_group 1;\n" ::: "memory");
        } else {
            asm volatile("cp.async.wait_group 0;\n" ::: "memory");
        }
        __syncthreads();
        if (kt + 2 < nkt) LOADKV(kt + 2, st2);

        const uint32_t sKh = sb + st * KV_STAGE;
        const uint32_t sVh = sKh + KV_T;

        float s[8][4];
#pragma unroll
        for (int i = 0; i < 8; i++) { s[i][0] = 0.f; s[i][1] = 0.f; s[i][2] = 0.f; s[i][3] = 0.f; }
#pragma unroll
        for (int kf = 0; kf < 8; kf++) {
#pragma unroll
            for (int nb = 0; nb < 4; nb++) {
                uint32_t bh[4];
                LDSM4(bh, sKh + koff + nb * (16 * FSTR) + kf * 32);
                MMA16816(s[2 * nb], qhf[kf], bh[0], bh[1]);
                MMA16816(s[2 * nb + 1], qhf[kf], bh[2], bh[3]);
            }
        }
        if (kt >= nkt - 2) {
            const int r0 = gr + w * 16 + (lane >> 2);
            const int c0 = kt * 64 + 2 * (lane & 3);
#pragma unroll
            for (int nf = 0; nf < 8; nf++) {
#pragma unroll
                for (int j = 0; j < 4; j++) {
                    int col = c0 + nf * 8 + (j & 1);
                    int row = r0 + (j >> 1) * 8;
                    if (col > row) s[nf][j] = -1e5f;
                }
            }
        }
        float mx0 = -1e30f, mx1 = -1e30f;
#pragma unroll
        for (int nf = 0; nf < 8; nf++) {
            mx0 = fmaxf(mx0, fmaxf(s[nf][0], s[nf][1]));
            mx1 = fmaxf(mx1, fmaxf(s[nf][2], s[nf][3]));
        }
        mx0 = fmaxf(mx0, __shfl_xor_sync(0xffffffffu, mx0, 1));
        mx0 = fmaxf(mx0, __shfl_xor_sync(0xffffffffu, mx0, 2));
        mx1 = fmaxf(mx1, __shfl_xor_sync(0xffffffffu, mx1, 1));
        mx1 = fmaxf(mx1, __shfl_xor_sync(0xffffffffu, mx1, 2));
        if (__any_sync(0xffffffffu, (mx0 > m0) || (mx1 > m1))) {
            const float mn0 = fmaxf(m0, mx0), mn1 = fmaxf(m1, mx1);
            const float cr0 = exp2p((m0 - mn0) * Cs), cr1 = exp2p((m1 - mn1) * Cs);
            m0 = mn0; m1 = mn1;
            l0 *= cr0; l1 *= cr1;
#pragma unroll
            for (int nf = 0; nf < 16; nf++) {
                o[nf][0] *= cr0; o[nf][1] *= cr0; o[nf][2] *= cr1; o[nf][3] *= cr1;
            }
        }
        const float c0_ = -m0 * Cs, c1_ = -m1 * Cs;
        float rs0 = 0.f, rs1 = 0.f;
#pragma unroll
        for (int nf = 0; nf < 8; nf++) {
            float p0 = exp2p(fmaf(s[nf][0], Cs, c0_));
            float p1 = exp2p(fmaf(s[nf][1], Cs, c0_));
            float p2 = exp2p(fmaf(s[nf][2], Cs, c1_));
            float p3 = exp2p(fmaf(s[nf][3], Cs, c1_));
            s[nf][0] = p0; s[nf][1] = p1; s[nf][2] = p2; s[nf][3] = p3;
            rs0 += p0 + p1; rs1 += p2 + p3;
        }
        rs0 += __shfl_xor_sync(0xffffffffu, rs0, 1);
        rs0 += __shfl_xor_sync(0xffffffffu, rs0, 2);
        rs1 += __shfl_xor_sync(0xffffffffu, rs1, 1);
        rs1 += __shfl_xor_sync(0xffffffffu, rs1, 2);
        l0 += rs0;
        l1 += rs1;
#pragma unroll
        for (int kb = 0; kb < 4; kb++) {
            uint32_t ph[4];
#pragma unroll
            for (int q2 = 0; q2 < 2; q2++) {
                const int nf = 2 * kb + q2;
                ph[2 * q2]     = pack_f16x2(s[nf][1], s[nf][0]);
                ph[2 * q2 + 1] = pack_f16x2(s[nf][3], s[nf][2]);
            }
#pragma unroll
            for (int ng = 0; ng < 8; ng++) {
                uint32_t vv[4];
                LDSM4T(vv, sVh + voff + kb * (16 * FSTR) + ng * 32);
                MMA16816(o[2 * ng], ph, vv[0], vv[1]);
                MMA16816(o[2 * ng + 1], ph, vv[2], vv[3]);
            }
        }
        st = (st == 2) ? 0 : st + 1;
        st2 = (st2 == 2) ? 0 : st2 + 1;
    }
#undef LOADKV

    const float inv0 = 1.f / l0, inv1 = 1.f / l1;
    const size_t row0_ = (size_t)(b * SEQ + gr + w * 16 + (lane >> 2));
    const int colb = h * 128 + 2 * (lane & 3);
#pragma unroll
    for (int nf = 0; nf < 16; nf++) {
        const int col = colb + nf * 8;
        uint32_t h01 = pack_f16x2(o[nf][1] * inv0, o[nf][0] * inv0);
        uint32_t h23 = pack_f16x2(o[nf][3] * inv1, o[nf][2] * inv1);
        *(uint32_t*)&oh_g[row0_ * HID + col] = h01;
        *(uint32_t*)&oh_g[(row0_ + 8) * HID + col] = h23;
    }
}

// ---------------- launch ----------------
extern "C" void kernel_launch(void* const* d_in, const int* in_sizes, int n_in,
                              void* d_out, int out_size)
{
    const float* x  = (const float*)d_in[0];
    const float* Wq = (const float*)d_in[2];
    const float* Aq = (const float*)d_in[3];
    const float* Bq = (const float*)d_in[4];
    const float* mq = (const float*)d_in[5];
    const float* Wk = (const float*)d_in[6];
    const float* Ak = (const float*)d_in[7];
    const float* Bk = (const float*)d_in[8];
    const float* mk = (const float*)d_in[9];
    const float* Wv = (const float*)d_in[10];
    const float* Av = (const float*)d_in[11];
    const float* Bv = (const float*)d_in[12];
    const float* mv = (const float*)d_in[13];
    const float* Wo = (const float*)d_in[14];
    const float* Ao = (const float*)d_in[15];
    const float* Bo = (const float*)d_in[16];
    const float* mo = (const float*)d_in[17];

    __half *xh, *xl, *Wqh, *Wkh, *Wvh, *Woh;
    __half *qh, *kh, *vh, *ath;
    cudaGetSymbolAddress((void**)&xh, g_xh);   cudaGetSymbolAddress((void**)&xl, g_xl);
    cudaGetSymbolAddress((void**)&Wqh, g_Wqh); cudaGetSymbolAddress((void**)&Wkh, g_Wkh);
    cudaGetSymbolAddress((void**)&Wvh, g_Wvh); cudaGetSymbolAddress((void**)&Woh, g_Woh);
    cudaGetSymbolAddress((void**)&qh, g_qh);   cudaGetSymbolAddress((void**)&kh, g_kh);
    cudaGetSymbolAddress((void**)&vh, g_vh);
    cudaGetSymbolAddress((void**)&ath, g_ath);

    cudaFuncSetAttribute(gemm_qkv, cudaFuncAttributeMaxDynamicSharedMemorySize, GEMM_SMEM);
    cudaFuncSetAttribute(gemm_o, cudaFuncAttributeMaxDynamicSharedMemorySize, GEMM1_SMEM);
    cudaFuncSetAttribute(flash_hmma, cudaFuncAttributeMaxDynamicSharedMemorySize, FLASH_SMEM);

    // 1) DoRA effective weights + x split (one fused launch)
    const int split_blocks = (TOK * HID / 4 + 255) / 256;
    dora_split<<<10240 + split_blocks, 256>>>(
        Wq, Aq, Bq, mq, Wk, Ak, Bk, mk, Wv, Av, Bv, mv, Wo, Ao, Bo, mo,
        Wqh, Wkh, Wvh, Woh, x, xh, xl);

    // 2) merged q/k/v projections (Q 1-term, K/V 2-term)
    gemm_qkv<<<dim3(48, TOK / 128), 256, GEMM_SMEM>>>(
        xh, xl, Wqh, Wkh, Wvh, qh, kh, vh);

    // 3) causal attention (HMMA) -> single fp16 attention output
    flash_hmma<<<dim3(SEQ / 128, 32, 2), 256, FLASH_SMEM>>>(qh, kh, vh, ath);

    // 4) output projection (1-term) -> d_out (fp32)
    gemm_o<<<dim3(HID / 128, TOK / 128), 256, GEMM1_SMEM>>>(ath, Woh, (float*)d_out);
}

// round 15
// speedup vs baseline: 2.6582x; 1.0014x over previous
#include <cuda_runtime.h>
#include <cuda_fp16.h>
#include <cstdint>
#include <math.h>

#define HID 4096
#define KVD 1024
#define TOK 4096   /* B*S */
#define SEQ 2048

// ---------------- device scratch ----------------
__device__ __half g_xh[TOK * HID];
__device__ __half g_xl[TOK * HID];
__device__ __half g_Wqh[HID * HID];
__device__ __half g_Wkh[KVD * HID];
__device__ __half g_Wvh[KVD * HID];
__device__ __half g_Woh[HID * HID];
__device__ __half g_qh[TOK * HID];
__device__ __half g_kh[TOK * KVD];
__device__ __half g_vh[TOK * KVD];
__device__ __half g_ath[TOK * HID];

// ---------------- helpers ----------------
__device__ __forceinline__ uint32_t smem_u32(const void* p) {
    uint32_t a;
    asm("{ .reg .u64 t; cvta.to.shared.u64 t, %1; cvt.u32.u64 %0, t; }" : "=r"(a) : "l"(p));
    return a;
}
__device__ __forceinline__ void cp16(uint32_t dst, const void* src) {
    asm volatile("cp.async.cg.shared.global [%0], [%1], 16;\n" :: "r"(dst), "l"(src) : "memory");
}
#define CP_COMMIT() asm volatile("cp.async.commit_group;\n" ::: "memory")

#define LDSM4(r, a) \
    asm volatile("ldmatrix.sync.aligned.m8n8.x4.shared.b16 {%0,%1,%2,%3}, [%4];" \
                 : "=r"((r)[0]), "=r"((r)[1]), "=r"((r)[2]), "=r"((r)[3]) : "r"(a))
#define LDSM4T(r, a) \
    asm volatile("ldmatrix.sync.aligned.m8n8.x4.trans.shared.b16 {%0,%1,%2,%3}, [%4];" \
                 : "=r"((r)[0]), "=r"((r)[1]), "=r"((r)[2]), "=r"((r)[3]) : "r"(a))

#define MMA16816(d, a, b0, b1) \
    asm volatile("mma.sync.aligned.m16n8k16.row.col.f32.f16.f16.f32 " \
                 "{%0,%1,%2,%3}, {%4,%5,%6,%7}, {%8,%9}, {%0,%1,%2,%3};" \
                 : "+f"((d)[0]), "+f"((d)[1]), "+f"((d)[2]), "+f"((d)[3]) \
                 : "r"((a)[0]), "r"((a)[1]), "r"((a)[2]), "r"((a)[3]), "r"(b0), "r"(b1))

__device__ __forceinline__ uint32_t pack_f16x2(float hi_, float lo_) {
    __half2 h = __floats2half2_rn(lo_, hi_);
    return *(uint32_t*)&h;
}
// fast exp2 on FMA pipe (no MUFU). rel err ~2.4e-6.
__device__ __forceinline__ float exp2p(float x) {
    x = fmaxf(x, -120.f);
    int e = __float2int_rn(x);
    float f = x - (float)e;
    float p = 1.3333558e-3f;
    p = fmaf(p, f, 9.6181291e-3f);
    p = fmaf(p, f, 5.5504109e-2f);
    p = fmaf(p, f, 2.4022651e-1f);
    p = fmaf(p, f, 6.9314718e-1f);
    p = fmaf(p, f, 1.0f);
    return p * __int_as_float((uint32_t)(e + 127) << 23);
}

// -------- fused: DoRA weights (blocks 0..10239) + x split (blocks 10240..) --
__global__ __launch_bounds__(256) void dora_split(
    const float* __restrict__ Wq, const float* __restrict__ Aq,
    const float* __restrict__ Bq, const float* __restrict__ mq,
    const float* __restrict__ Wk, const float* __restrict__ Ak,
    const float* __restrict__ Bk, const float* __restrict__ mk,
    const float* __restrict__ Wv, const float* __restrict__ Av,
    const float* __restrict__ Bv, const float* __restrict__ mv,
    const float* __restrict__ Wo, const float* __restrict__ Ao,
    const float* __restrict__ Bo, const float* __restrict__ mo,
    __half* __restrict__ Wqh, __half* __restrict__ Wkh,
    __half* __restrict__ Wvh, __half* __restrict__ Woh,
    const float* __restrict__ x, __half* __restrict__ xh,
    __half* __restrict__ xl)
{
    const int bx = blockIdx.x;
    const int tid = threadIdx.x;

    if (bx >= 10240) {
        int i = (bx - 10240) * 256 + tid;
        if (i < TOK * HID / 4) {
            float4 v = ((const float4*)x)[i];
            float vv[4] = {v.x, v.y, v.z, v.w};
            size_t base = (size_t)i * 4;
#pragma unroll
            for (int e = 0; e < 4; e++) {
                __half h = __float2half_rn(vv[e]);
                xh[base + e] = h;
                xl[base + e] = __float2half_rn(vv[e] - __half2float(h));
            }
        }
        return;
    }

    const float *W, *A, *Bm, *mvec;
    __half *Whi;
    int row;
    if (bx < 4096)      { W = Wq; A = Aq; Bm = Bq; mvec = mq; Whi = Wqh; row = bx; }
    else if (bx < 5120) { W = Wk; A = Ak; Bm = Bk; mvec = mk; Whi = Wkh; row = bx - 4096; }
    else if (bx < 6144) { W = Wv; A = Av; Bm = Bv; mvec = mv; Whi = Wvh; row = bx - 5120; }
    else                { W = Wo; A = Ao; Bm = Bo; mvec = mo; Whi = Woh; row = bx - 6144; }

    float b[8];
#pragma unroll
    for (int r = 0; r < 8; r++) b[r] = 2.0f * Bm[row * 8 + r];

    const float4* Wrow = (const float4*)(W + (size_t)row * HID);
    float4 w[4];
    float ss = 0.f;
#pragma unroll
    for (int c = 0; c < 4; c++) {
        int col4 = tid + 256 * c;
        float4 wv = Wrow[col4];
#pragma unroll
        for (int r = 0; r < 8; r++) {
            float4 av = ((const float4*)(A + (size_t)r * HID))[col4];
            wv.x += b[r] * av.x; wv.y += b[r] * av.y;
            wv.z += b[r] * av.z; wv.w += b[r] * av.w;
        }
        ss += wv.x * wv.x + wv.y * wv.y + wv.z * wv.z + wv.w * wv.w;
        w[c] = wv;
    }
#pragma unroll
    for (int off = 16; off; off >>= 1)
        ss += __shfl_xor_sync(0xffffffffu, ss, off);

    __shared__ float red[8];
    __shared__ float s_scale;
    if ((tid & 31) == 0) red[tid >> 5] = ss;
    __syncthreads();
    if (tid == 0) {
        float t = 0.f;
#pragma unroll
        for (int i = 0; i < 8; i++) t += red[i];
        s_scale = mvec[row] / (sqrtf(t) + 1e-8f);
    }
    __syncthreads();
    const float sc = s_scale;
#pragma unroll
    for (int c = 0; c < 4; c++) {
        float vv[4] = {w[c].x * sc, w[c].y * sc, w[c].z * sc, w[c].w * sc};
        size_t base = (size_t)row * HID + (tid + 256 * c) * 4;
        __half2 p0 = __floats2half2_rn(vv[0], vv[1]);
        __half2 p1 = __floats2half2_rn(vv[2], vv[3]);
        *(__half2*)&Whi[base] = p0;
        *(__half2*)&Whi[base + 2] = p1;
    }
}

// ======= unified 1-term GEMM mainloop: 128x128 CTA tile, 128 threads ========
// Warp grid 2x2, warp tile 64x64 (acc 128 regs). K-chunk 64, 2-stage double
// buffer, ONE barrier per chunk. 2-term emulated as K=8192 (A: xh then xl,
// B re-loops). 73.7KB smem -> 3 CTAs/SM.
#define GSTR 144
#define GTILE_B (128 * GSTR)             /* 18432 */
#define QKV_STAGE (2 * GTILE_B)          /* {A, B} = 36864 */
#define QKV_SMEM (2 * QKV_STAGE)         /* 73728 */

__device__ __forceinline__ void hmma_loop64(
    uint32_t sb, const __half* A0, const __half* A1, const __half* Bp,
    int nch, int tid, float acc[4][8][4])
{
    const int lane = tid & 31, wid = tid >> 5;
    const int wm = wid & 1, wn = wid >> 1;
    const int K = 4096;
    const int ldr = tid >> 3;        /* 0..15 */
    const int ldc = (tid & 7) * 16;

    const uint32_t a_off = (uint32_t)(wm * 64 + (lane & 15)) * GSTR + ((lane >> 4) * 16);
    const uint32_t b_off = (uint32_t)(wn * 64 + (((lane >> 4) << 3) + (lane & 7))) * GSTR
                           + (((lane >> 3) & 1) * 16);

#define LD64(buf, ch_) do { \
    uint32_t s0_ = sb + (buf) * QKV_STAGE; \
    const __half* a_ = ((ch_) < 64 ? A0 : A1) + ((ch_) & 63) * 64; \
    const __half* b_ = Bp + ((ch_) & 63) * 64; \
    const __half* gg_[2] = {a_, b_}; \
    _Pragma("unroll") \
    for (int t_ = 0; t_ < 2; t_++) { \
        uint32_t st_ = s0_ + t_ * GTILE_B; \
        _Pragma("unroll") \
        for (int p_ = 0; p_ < 8; p_++) { \
            int r_ = ldr + p_ * 16; \
            cp16(st_ + (uint32_t)r_ * GSTR + ldc, \
                 (const char*)(gg_[t_] + (size_t)r_ * K) + ldc); \
        } \
    } \
    CP_COMMIT(); \
} while (0)

    LD64(0, 0);
    for (int ch = 0; ch < nch; ch++) {
        asm volatile("cp.async.wait_group 0;\n" ::: "memory");
        __syncthreads();
        if (ch + 1 < nch) LD64((ch + 1) & 1, ch + 1);
        const uint32_t s0 = sb + (ch & 1) * QKV_STAGE;
        const uint32_t sA = s0, sB = s0 + GTILE_B;
#pragma unroll
        for (int k16 = 0; k16 < 4; k16++) {
            const uint32_t kadd = k16 * 32;
            uint32_t aa[4][4];
#pragma unroll
            for (int mb = 0; mb < 4; mb++)
                LDSM4(aa[mb], sA + a_off + mb * (16 * GSTR) + kadd);
#pragma unroll
            for (int jb = 0; jb < 4; jb++) {
                uint32_t bb[4];
                LDSM4(bb, sB + b_off + jb * (16 * GSTR) + kadd);
#pragma unroll
                for (int mb = 0; mb < 4; mb++) {
                    MMA16816(acc[mb][2 * jb], aa[mb], bb[0], bb[1]);
                    MMA16816(acc[mb][2 * jb + 1], aa[mb], bb[2], bb[3]);
                }
            }
        }
    }
#undef LD64
}

// ---------------- merged QKV projection ----------------
// bx 0..7: K (K=8192 via xh,xl), bx 8..15: V (K=8192), bx 16..47: Q (K=4096).
__global__ __launch_bounds__(128, 3) void gemm_qkv(
    const __half* __restrict__ xh, const __half* __restrict__ xl,
    const __half* __restrict__ Wqh, const __half* __restrict__ Wkh,
    const __half* __restrict__ Wvh,
    __half* __restrict__ qh, __half* __restrict__ kh, __half* __restrict__ vh)
{
    extern __shared__ char dsm[];
    const uint32_t sb = smem_u32(dsm);
    const int tid = threadIdx.x, lane = tid & 31, wid = tid >> 5;
    const int wm = wid & 1, wn = wid >> 1;
    const int bx = blockIdx.x;
    const int row0 = blockIdx.y << 7;
    const int K = 4096;

    const __half* Bp;
    __half* Oh;
    int N, col0, nch;
    if (bx < 8)       { Bp = Wkh; Oh = kh; N = KVD; col0 = bx << 7; nch = 128; }
    else if (bx < 16) { Bp = Wvh; Oh = vh; N = KVD; col0 = (bx - 8) << 7; nch = 128; }
    else              { Bp = Wqh; Oh = qh; N = HID; col0 = (bx - 16) << 7; nch = 64; }

    float acc[4][8][4] = {};
    hmma_loop64(sb, xh + (size_t)row0 * K, xl + (size_t)row0 * K,
                Bp + (size_t)col0 * K, nch, tid, acc);

#pragma unroll
    for (int mb = 0; mb < 4; mb++) {
        const int mrow = row0 + wm * 64 + mb * 16 + (lane >> 2);
#pragma unroll
        for (int jf = 0; jf < 8; jf++) {
            const int col = col0 + wn * 64 + jf * 8 + (lane & 3) * 2;
            uint32_t h01 = pack_f16x2(acc[mb][jf][1], acc[mb][jf][0]);
            uint32_t h23 = pack_f16x2(acc[mb][jf][3], acc[mb][jf][2]);
            *(uint32_t*)&Oh[(size_t)mrow * N + col] = h01;
            *(uint32_t*)&Oh[(size_t)(mrow + 8) * N + col] = h23;
        }
    }
}

// ---------------- output projection (1-term, fp32 out) ----------------
__global__ __launch_bounds__(128, 3) void gemm_o(
    const __half* __restrict__ Ah, const __half* __restrict__ Bh,
    float* __restrict__ C)
{
    extern __shared__ char dsm[];
    const uint32_t sb = smem_u32(dsm);
    const int tid = threadIdx.x, lane = tid & 31, wid = tid >> 5;
    const int wm = wid & 1, wn = wid >> 1;
    const int row0 = blockIdx.y << 7, col0 = blockIdx.x << 7;
    const int K = 4096, N = HID;

    float acc[4][8][4] = {};
    hmma_loop64(sb, Ah + (size_t)row0 * K, Ah + (size_t)row0 * K,
                Bh + (size_t)col0 * K, 64, tid, acc);

#pragma unroll
    for (int mb = 0; mb < 4; mb++) {
        const int mrow = row0 + wm * 64 + mb * 16 + (lane >> 2);
#pragma unroll
        for (int jf = 0; jf < 8; jf++) {
            const int col = col0 + wn * 64 + jf * 8 + (lane & 3) * 2;
            float2 lo2 = {acc[mb][jf][0], acc[mb][jf][1]};
            float2 hi2 = {acc[mb][jf][2], acc[mb][jf][3]};
            *(float2*)&C[(size_t)mrow * N + col] = lo2;
            *(float2*)&C[(size_t)(mrow + 8) * N + col] = hi2;
        }
    }
}

// ---------------- HMMA causal flash attention ----------------
// QK 1-term; PV 1-term. Raw-score softmax, lazy (warp-voted) rescale.
#define FSTR 272
#define KV_T 17408
#define KV_STAGE (2 * KV_T)
#define FLASH_SMEM (3 * KV_STAGE)

__global__ __launch_bounds__(256, 1) void flash_hmma(
    const __half* __restrict__ qh_g, const __half* __restrict__ kh_g,
    const __half* __restrict__ vh_g,
    __half* __restrict__ oh_g)
{
    extern __shared__ char dsm[];
    const uint32_t sq = smem_u32(dsm);
    const uint32_t sb = sq;
    const int tid = threadIdx.x, lane = tid & 31, w = tid >> 5;
    const int qt = (int)gridDim.x - 1 - (int)blockIdx.x;
    const int h = blockIdx.y, b = blockIdx.z;
    const int kvh = h >> 2;
    const int gr = qt * 128;
    const int nkt = 2 * qt + 2;

    {
        const __half* src = qh_g + ((size_t)(b * SEQ + gr)) * HID + h * 128;
#pragma unroll
        for (int i = 0; i < 8; i++) {
            int idx = tid + i * 256;
            int r = idx >> 4, c = idx & 15;
            cp16(sq + (uint32_t)r * FSTR + c * 16,
                 (const char*)(src + (size_t)r * HID) + c * 16);
        }
        CP_COMMIT();
        asm volatile("cp.async.wait_group 0;\n" ::: "memory");
        __syncthreads();
    }
    uint32_t qhf[8][4];
    {
        const uint32_t qoff = (uint32_t)(w * 16 + (lane & 15)) * FSTR + ((lane >> 4) * 16);
#pragma unroll
        for (int kf = 0; kf < 8; kf++)
            LDSM4(qhf[kf], sq + qoff + kf * 32);
    }
    __syncthreads();

    float o[16][4];
#pragma unroll
    for (int i = 0; i < 16; i++) { o[i][0] = 0.f; o[i][1] = 0.f; o[i][2] = 0.f; o[i][3] = 0.f; }
    float m0 = -1e5f, m1 = -1e5f, l0 = 0.f, l1 = 0.f;

    const uint32_t koff = (uint32_t)(((lane >> 4) << 3) + (lane & 7)) * FSTR + (((lane >> 3) & 1) * 16);
    const uint32_t voff = (uint32_t)((((lane >> 3) & 1) << 3) + (lane & 7)) * FSTR + ((lane >> 4) * 16);

    const __half* kh_p = kh_g + ((size_t)(b * SEQ)) * KVD + kvh * 128;
    const __half* vh_p = vh_g + ((size_t)(b * SEQ)) * KVD + kvh * 128;

#define LOADKV(kt_, buf_) do { \
    uint32_t s0_ = sb + (buf_) * KV_STAGE; \
    const __half* gs_[2] = { \
        kh_p + (size_t)(kt_) * 64 * KVD, vh_p + (size_t)(kt_) * 64 * KVD}; \
    _Pragma("unroll") \
    for (int t_ = 0; t_ < 2; t_++) { \
        _Pragma("unroll") \
        for (int i_ = 0; i_ < 4; i_++) { \
            int idx_ = tid + i_ * 256; \
            int r_ = idx_ >> 4, c_ = idx_ & 15; \
            cp16(s0_ + t_ * KV_T + (uint32_t)r_ * FSTR + c_ * 16, \
                 (const char*)(gs_[t_] + (size_t)r_ * KVD) + c_ * 16); \
        } \
    } \
    CP_COMMIT(); \
} while (0)

    LOADKV(0, 0);
    LOADKV(1, 1);
    const float Cs = 0.08838834764831845f * 1.4426950408889634f;

    int st = 0;
    int st2 = 2;
    for (int kt = 0; kt < nkt; kt++) {
        if (kt + 2 < nkt) {
            asm volatile("cp.async.wait_group 1;\n" ::: "memory");
        } else {
            asm volatile("cp.async.wait_group 0;\n" ::: "memory");
        }
        __syncthreads();
        if (kt + 2 < nkt) LOADKV(kt + 2, st2);

        const uint32_t sKh = sb + st * KV_STAGE;
        const uint32_t sVh = sKh + KV_T;

        float s[8][4];
#pragma unroll
        for (int i = 0; i < 8; i++) { s[i][0] = 0.f; s[i][1] = 0.f; s[i][2] = 0.f; s[i][3] = 0.f; }
#pragma unroll
        for (int kf = 0; kf < 8; kf++) {
#pragma unroll
            for (int nb = 0; nb < 4; nb++) {
                uint32_t bh[4];
                LDSM4(bh, sKh + koff + nb * (16 * FSTR) + kf * 32);
                MMA16816(s[2 * nb], qhf[kf], bh[0], bh[1]);
                MMA16816(s[2 * nb + 1], qhf[kf], bh[2], bh[3]);
            }
        }
        if (kt >= nkt - 2) {
            const int r0 = gr + w * 16 + (lane >> 2);
            const int c0 = kt * 64 + 2 * (lane & 3);
#pragma unroll
            for (int nf = 0; nf < 8; nf++) {
#pragma unroll
                for (int j = 0; j < 4; j++) {
                    int col = c0 + nf * 8 + (j & 1);
                    int row = r0 + (j >> 1) * 8;
                    if (col > row) s[nf][j] = -1e5f;
                }
            }
        }
        float mx0 = -1e30f, mx1 = -1e30f;
#pragma unroll
        for (int nf = 0; nf < 8; nf++) {
            mx0 = fmaxf(mx0, fmaxf(s[nf][0], s[nf][1]));
            mx1 = fmaxf(mx1, fmaxf(s[nf][2], s[nf][3]));
        }
        mx0 = fmaxf(mx0, __shfl_xor_sync(0xffffffffu, mx0, 1));
        mx0 = fmaxf(mx0, __shfl_xor_sync(0xffffffffu, mx0, 2));
        mx1 = fmaxf(mx1, __shfl_xor_sync(0xffffffffu, mx1, 1));
        mx1 = fmaxf(mx1, __shfl_xor_sync(0xffffffffu, mx1, 2));
        if (__any_sync(0xffffffffu, (mx0 > m0) || (mx1 > m1))) {
            const float mn0 = fmaxf(m0, mx0), mn1 = fmaxf(m1, mx1);
            const float cr0 = exp2p((m0 - mn0) * Cs), cr1 = exp2p((m1 - mn1) * Cs);
            m0 = mn0; m1 = mn1;
            l0 *= cr0; l1 *= cr1;
#pragma unroll
            for (int nf = 0; nf < 16; nf++) {
                o[nf][0] *= cr0; o[nf][1] *= cr0; o[nf][2] *= cr1; o[nf][3] *= cr1;
            }
        }
        const float c0_ = -m0 * Cs, c1_ = -m1 * Cs;
        float rs0 = 0.f, rs1 = 0.f;
#pragma unroll
        for (int nf = 0; nf < 8; nf++) {
            float p0 = exp2p(fmaf(s[nf][0], Cs, c0_));
            float p1 = exp2p(fmaf(s[nf][1], Cs, c0_));
            float p2 = exp2p(fmaf(s[nf][2], Cs, c1_));
            float p3 = exp2p(fmaf(s[nf][3], Cs, c1_));
            s[nf][0] = p0; s[nf][1] = p1; s[nf][2] = p2; s[nf][3] = p3;
            rs0 += p0 + p1; rs1 += p2 + p3;
        }
        rs0 += __shfl_xor_sync(0xffffffffu, rs0, 1);
        rs0 += __shfl_xor_sync(0xffffffffu, rs0, 2);
        rs1 += __shfl_xor_sync(0xffffffffu, rs1, 1);
        rs1 += __shfl_xor_sync(0xffffffffu, rs1, 2);
        l0 += rs0;
        l1 += rs1;
#pragma unroll
        for (int kb = 0; kb < 4; kb++) {
            uint32_t ph[4];
#pragma unroll
            for (int q2 = 0; q2 < 2; q2++) {
                const int nf = 2 * kb + q2;
                ph[2 * q2]     = pack_f16x2(s[nf][1], s[nf][0]);
                ph[2 * q2 + 1] = pack_f16x2(s[nf][3], s[nf][2]);
            }
#pragma unroll
            for (int ng = 0; ng < 8; ng++) {
                uint32_t vv[4];
                LDSM4T(vv, sVh + voff + kb * (16 * FSTR) + ng * 32);
                MMA16816(o[2 * ng], ph, vv[0], vv[1]);
                MMA16816(o[2 * ng + 1], ph, vv[2], vv[3]);
            }
        }
        st = (st == 2) ? 0 : st + 1;
        st2 = (st2 == 2) ? 0 : st2 + 1;
    }
#undef LOADKV

    const float inv0 = 1.f / l0, inv1 = 1.f / l1;
    const size_t row0_ = (size_t)(b * SEQ + gr + w * 16 + (lane >> 2));
    const int colb = h * 128 + 2 * (lane & 3);
#pragma unroll
    for (int nf = 0; nf < 16; nf++) {
        const int col = colb + nf * 8;
        uint32_t h01 = pack_f16x2(o[nf][1] * inv0, o[nf][0] * inv0);
        uint32_t h23 = pack_f16x2(o[nf][3] * inv1, o[nf][2] * inv1);
        *(uint32_t*)&oh_g[row0_ * HID + col] = h01;
        *(uint32_t*)&oh_g[(row0_ + 8) * HID + col] = h23;
    }
}

// ---------------- launch ----------------
extern "C" void kernel_launch(void* const* d_in, const int* in_sizes, int n_in,
                              void* d_out, int out_size)
{
    const float* x  = (const float*)d_in[0];
    const float* Wq = (const float*)d_in[2];
    const float* Aq = (const float*)d_in[3];
    const float* Bq = (const float*)d_in[4];
    const float* mq = (const float*)d_in[5];
    const float* Wk = (const float*)d_in[6];
    const float* Ak = (const float*)d_in[7];
    const float* Bk = (const float*)d_in[8];
    const float* mk = (const float*)d_in[9];
    const float* Wv = (const float*)d_in[10];
    const float* Av = (const float*)d_in[11];
    const float* Bv = (const float*)d_in[12];
    const float* mv = (const float*)d_in[13];
    const float* Wo = (const float*)d_in[14];
    const float* Ao = (const float*)d_in[15];
    const float* Bo = (const float*)d_in[16];
    const float* mo = (const float*)d_in[17];

    __half *xh, *xl, *Wqh, *Wkh, *Wvh, *Woh;
    __half *qh, *kh, *vh, *ath;
    cudaGetSymbolAddress((void**)&xh, g_xh);   cudaGetSymbolAddress((void**)&xl, g_xl);
    cudaGetSymbolAddress((void**)&Wqh, g_Wqh); cudaGetSymbolAddress((void**)&Wkh, g_Wkh);
    cudaGetSymbolAddress((void**)&Wvh, g_Wvh); cudaGetSymbolAddress((void**)&Woh, g_Woh);
    cudaGetSymbolAddress((void**)&qh, g_qh);   cudaGetSymbolAddress((void**)&kh, g_kh);
    cudaGetSymbolAddress((void**)&vh, g_vh);
    cudaGetSymbolAddress((void**)&ath, g_ath);

    cudaFuncSetAttribute(gemm_qkv, cudaFuncAttributeMaxDynamicSharedMemorySize, QKV_SMEM);
    cudaFuncSetAttribute(gemm_o, cudaFuncAttributeMaxDynamicSharedMemorySize, QKV_SMEM);
    cudaFuncSetAttribute(flash_hmma, cudaFuncAttributeMaxDynamicSharedMemorySize, FLASH_SMEM);

    // 1) DoRA effective weights + x split (one fused launch)
    const int split_blocks = (TOK * HID / 4 + 255) / 256;
    dora_split<<<10240 + split_blocks, 256>>>(
        Wq, Aq, Bq, mq, Wk, Ak, Bk, mk, Wv, Av, Bv, mv, Wo, Ao, Bo, mo,
        Wqh, Wkh, Wvh, Woh, x, xh, xl);

    // 2) merged q/k/v projections (K/V as K=8192 1-term, Q as K=4096 1-term)
    gemm_qkv<<<dim3(48, TOK / 128), 128, QKV_SMEM>>>(
        xh, xl, Wqh, Wkh, Wvh, qh, kh, vh);

    // 3) causal attention (HMMA) -> single fp16 attention output
    flash_hmma<<<dim3(SEQ / 128, 32, 2), 256, FLASH_SMEM>>>(qh, kh, vh, ath);

    // 4) output projection (1-term) -> d_out (fp32)
    gemm_o<<<dim3(HID / 128, TOK / 128), 128, QKV_SMEM>>>(ath, Woh, (float*)d_out);
}